// round 1
// baseline (speedup 1.0000x reference)
#include <cuda_runtime.h>
#include <cuda_bf16.h>
#include <math.h>

// Problem constants: B=1, S=2048, HIDDEN=2048, NUM_HEADS=16, MLA_DIM=HEAD_DIM=128
#define S_LEN 2048
#define HID   2048
#define NH    16
#define HD    128

// ---------------- scratch (no allocations allowed) ----------------
__device__ float g_Q[S_LEN * HID];
__device__ float g_K[S_LEN * HID];
__device__ float g_V[S_LEN * HID];
__device__ float g_AO[S_LEN * HID];

// ---------------- SGEMM: C[M,N] = A[M,K] @ B[K,N], M=N=K=2048 ----------------
#define GBM 128
#define GBN 128
#define GBK 8
#define GTM 8
#define GTN 8

__global__ __launch_bounds__(256) void sgemm_kernel(const float* __restrict__ A,
                                                    const float* __restrict__ B,
                                                    float* __restrict__ C) {
    const int N = HID, K = HID;
    __shared__ float As[GBK * GBM];   // transposed: As[k*GBM + m]
    __shared__ float Bs[GBK * GBN];

    const int tid  = threadIdx.x;
    const int row0 = blockIdx.y * GBM;
    const int col0 = blockIdx.x * GBN;

    const int innerRowA = tid >> 1;          // 0..127
    const int innerColA = (tid & 1) * 4;     // 0 or 4
    const int innerRowB = tid >> 5;          // 0..7
    const int innerColB = (tid & 31) * 4;    // 0..124

    const int tr = (tid >> 4) * GTM;         // 0..120
    const int tc = (tid & 15) * GTN;         // 0..120

    float acc[GTM][GTN];
#pragma unroll
    for (int i = 0; i < GTM; i++)
#pragma unroll
        for (int j = 0; j < GTN; j++) acc[i][j] = 0.f;

    for (int kb = 0; kb < K; kb += GBK) {
        float4 a = *(const float4*)&A[(row0 + innerRowA) * K + kb + innerColA];
        As[(innerColA + 0) * GBM + innerRowA] = a.x;
        As[(innerColA + 1) * GBM + innerRowA] = a.y;
        As[(innerColA + 2) * GBM + innerRowA] = a.z;
        As[(innerColA + 3) * GBM + innerRowA] = a.w;
        *(float4*)&Bs[innerRowB * GBN + innerColB] =
            *(const float4*)&B[(kb + innerRowB) * N + col0 + innerColB];
        __syncthreads();

#pragma unroll
        for (int k = 0; k < GBK; k++) {
            float4 m0 = *(const float4*)&As[k * GBM + tr];
            float4 m1 = *(const float4*)&As[k * GBM + tr + 4];
            float4 n0 = *(const float4*)&Bs[k * GBN + tc];
            float4 n1 = *(const float4*)&Bs[k * GBN + tc + 4];
            float regM[GTM] = {m0.x, m0.y, m0.z, m0.w, m1.x, m1.y, m1.z, m1.w};
            float regN[GTN] = {n0.x, n0.y, n0.z, n0.w, n1.x, n1.y, n1.z, n1.w};
#pragma unroll
            for (int i = 0; i < GTM; i++)
#pragma unroll
                for (int j = 0; j < GTN; j++) acc[i][j] += regM[i] * regN[j];
        }
        __syncthreads();
    }

#pragma unroll
    for (int i = 0; i < GTM; i++) {
#pragma unroll
        for (int j = 0; j < GTN; j += 4) {
            float4 v = make_float4(acc[i][j], acc[i][j + 1], acc[i][j + 2], acc[i][j + 3]);
            *(float4*)&C[(row0 + tr + i) * N + col0 + tc + j] = v;
        }
    }
}

// ---------------- RoPE (applied in-place to Q and K) ----------------
// For head-dim 128: pair (j, j+64), j<64.
// q'[j]    = q[j]*cos(t*f_j) - q[j+64]*sin(t*f_j)
// q'[j+64] = q[j+64]*cos(t*f_j) + q[j]*sin(t*f_j)
__global__ void rope_kernel(float* __restrict__ Q, float* __restrict__ K) {
    int idx = blockIdx.x * blockDim.x + threadIdx.x;  // S*NH*64 threads
    int j = idx & 63;
    int h = (idx >> 6) & (NH - 1);
    int t = idx >> 10;

    float expo   = (float)(2 * j) * (1.0f / 128.0f);
    float invfrq = expf(-expo * 9.210340371976184f);  // 10000^(-2j/128)
    float ang    = (float)t * invfrq;
    float sv, cv;
    sincosf(ang, &sv, &cv);

    int base = t * HID + h * HD + j;
    float q1 = Q[base], q2 = Q[base + 64];
    Q[base]      = q1 * cv - q2 * sv;
    Q[base + 64] = q2 * cv + q1 * sv;
    float k1 = K[base], k2 = K[base + 64];
    K[base]      = k1 * cv - k2 * sv;
    K[base + 64] = k2 * cv + k1 * sv;
}

// ---------------- Flash attention (fp32, causal, online softmax) ----------------
#define FBM 64
#define FBN 64
#define FD  128
#define LDK 129   // padded K lead dim (2-way-conflict scalar reads)
#define LDS 68    // padded S-tile lead dim

#define FLASH_SMEM_FLOATS (FBM*FD + FBN*LDK + FBN*FD + FBM*LDS + FBM)
#define FLASH_SMEM_BYTES  (FLASH_SMEM_FLOATS * 4)

__global__ __launch_bounds__(256) void flash_kernel(const float* __restrict__ Q,
                                                    const float* __restrict__ K,
                                                    const float* __restrict__ V,
                                                    float* __restrict__ O) {
    extern __shared__ float sm[];
    float* Qs  = sm;                   // FBM x FD (row-major)
    float* Ks  = Qs + FBM * FD;        // FBN x LDK
    float* Vs  = Ks + FBN * LDK;       // FBN x FD
    float* Ss  = Vs + FBN * FD;        // FBM x LDS
    float* red = Ss + FBM * LDS;       // FBM (alpha / l broadcast)

    const int qb  = blockIdx.x;
    const int h   = blockIdx.y;
    const int tid = threadIdx.x;
    const int tr  = (tid >> 4) * 4;    // rows base (S and O)
    const int tc4 = (tid & 15) * 4;    // S cols base
    const int tc8 = (tid & 15) * 8;    // O cols base
    const int qrow0 = qb * FBM;
    const float scale = 0.08838834764831845f;  // 1/sqrt(128)

    // Load Q tile (pre-scaled)
    for (int i = tid; i < FBM * FD / 4; i += 256) {
        int r = i >> 5;
        int c = (i & 31) * 4;
        float4 v = *(const float4*)&Q[(qrow0 + r) * HID + h * HD + c];
        v.x *= scale; v.y *= scale; v.z *= scale; v.w *= scale;
        *(float4*)&Qs[r * FD + c] = v;
    }

    float o[4][8];
#pragma unroll
    for (int i = 0; i < 4; i++)
#pragma unroll
        for (int j = 0; j < 8; j++) o[i][j] = 0.f;
    float m_i = -1e30f, l_i = 0.f;

    for (int kb = 0; kb <= qb; kb++) {
        __syncthreads();  // previous Ss/Vs consumers done
        int krow0 = kb * FBN;
        for (int i = tid; i < FBN * FD / 4; i += 256) {
            int r = i >> 5;
            int c = (i & 31) * 4;
            float4 kv = *(const float4*)&K[(krow0 + r) * HID + h * HD + c];
            Ks[r * LDK + c + 0] = kv.x;
            Ks[r * LDK + c + 1] = kv.y;
            Ks[r * LDK + c + 2] = kv.z;
            Ks[r * LDK + c + 3] = kv.w;
            *(float4*)&Vs[r * FD + c] = *(const float4*)&V[(krow0 + r) * HID + h * HD + c];
        }
        __syncthreads();

        // S = Qs @ Ks^T  (each thread: 4x4 tile)
        float sacc[4][4];
#pragma unroll
        for (int i = 0; i < 4; i++)
#pragma unroll
            for (int j = 0; j < 4; j++) sacc[i][j] = 0.f;

        for (int d = 0; d < FD; d++) {
            float qv[4], kv[4];
#pragma unroll
            for (int i = 0; i < 4; i++) qv[i] = Qs[(tr + i) * FD + d];
#pragma unroll
            for (int j = 0; j < 4; j++) kv[j] = Ks[(tc4 + j) * LDK + d];
#pragma unroll
            for (int i = 0; i < 4; i++)
#pragma unroll
                for (int j = 0; j < 4; j++) sacc[i][j] += qv[i] * kv[j];
        }

        if (kb == qb) {  // causal mask on diagonal tile
#pragma unroll
            for (int i = 0; i < 4; i++)
#pragma unroll
                for (int j = 0; j < 4; j++)
                    if (tc4 + j > tr + i) sacc[i][j] = -1e30f;
        }

#pragma unroll
        for (int i = 0; i < 4; i++)
#pragma unroll
            for (int j = 0; j < 4; j++)
                Ss[(tr + i) * LDS + tc4 + j] = sacc[i][j];
        __syncthreads();

        // online-softmax row update: thread t owns row t (t < 64)
        if (tid < FBM) {
            float tmax = -1e30f;
            for (int c = 0; c < FBN; c++) tmax = fmaxf(tmax, Ss[tid * LDS + c]);
            float mnew = fmaxf(m_i, tmax);
            float a = __expf(m_i - mnew);
            float rs = 0.f;
            for (int c = 0; c < FBN; c++) {
                float p = __expf(Ss[tid * LDS + c] - mnew);
                Ss[tid * LDS + c] = p;
                rs += p;
            }
            l_i = l_i * a + rs;
            m_i = mnew;
            red[tid] = a;
        }
        __syncthreads();

        // O = O*alpha + P @ V   (each thread: 4 rows x 8 cols)
        float a[4];
#pragma unroll
        for (int i = 0; i < 4; i++) a[i] = red[tr + i];
#pragma unroll
        for (int i = 0; i < 4; i++)
#pragma unroll
            for (int j = 0; j < 8; j++) o[i][j] *= a[i];

        for (int k = 0; k < FBN; k++) {
            float4 v0 = *(const float4*)&Vs[k * FD + tc8];
            float4 v1 = *(const float4*)&Vs[k * FD + tc8 + 4];
            float vv[8] = {v0.x, v0.y, v0.z, v0.w, v1.x, v1.y, v1.z, v1.w};
            float p[4];
#pragma unroll
            for (int i = 0; i < 4; i++) p[i] = Ss[(tr + i) * LDS + k];
#pragma unroll
            for (int i = 0; i < 4; i++)
#pragma unroll
                for (int j = 0; j < 8; j++) o[i][j] += p[i] * vv[j];
        }
    }

    __syncthreads();
    if (tid < FBM) red[tid] = l_i;
    __syncthreads();

#pragma unroll
    for (int i = 0; i < 4; i++) {
        float inv = 1.0f / red[tr + i];
        float4 w0 = make_float4(o[i][0] * inv, o[i][1] * inv, o[i][2] * inv, o[i][3] * inv);
        float4 w1 = make_float4(o[i][4] * inv, o[i][5] * inv, o[i][6] * inv, o[i][7] * inv);
        *(float4*)&g_AO[(qrow0 + tr + i) * HID + h * HD + tc8]     = w0;
        *(float4*)&g_AO[(qrow0 + tr + i) * HID + h * HD + tc8 + 4] = w1;
    }
    (void)O;
}

// ---------------- launch ----------------
extern "C" void kernel_launch(void* const* d_in, const int* in_sizes, int n_in,
                              void* d_out, int out_size) {
    const float* X  = (const float*)d_in[0];
    const float* wq = (const float*)d_in[1];
    const float* wk = (const float*)d_in[2];
    const float* wv = (const float*)d_in[3];
    const float* wo = (const float*)d_in[4];
    // d_in[5] = attention_mask (exact causal; implemented analytically)
    float* out = (float*)d_out;

    float *Q, *K, *V, *AO;
    cudaGetSymbolAddress((void**)&Q,  g_Q);
    cudaGetSymbolAddress((void**)&K,  g_K);
    cudaGetSymbolAddress((void**)&V,  g_V);
    cudaGetSymbolAddress((void**)&AO, g_AO);

    cudaFuncSetAttribute(flash_kernel, cudaFuncAttributeMaxDynamicSharedMemorySize,
                         FLASH_SMEM_BYTES);

    dim3 gg(HID / GBN, S_LEN / GBM), gb(256);
    sgemm_kernel<<<gg, gb>>>(X, wq, Q);
    sgemm_kernel<<<gg, gb>>>(X, wk, K);
    sgemm_kernel<<<gg, gb>>>(X, wv, V);

    rope_kernel<<<(S_LEN * NH * 64) / 256, 256>>>(Q, K);

    flash_kernel<<<dim3(S_LEN / FBM, NH), 256, FLASH_SMEM_BYTES>>>(Q, K, V, AO);

    sgemm_kernel<<<gg, gb>>>(AO, wo, out);

    (void)in_sizes; (void)n_in; (void)out_size;
}

// round 4
// speedup vs baseline: 1.8099x; 1.8099x over previous
#include <cuda_runtime.h>
#include <cuda_bf16.h>
#include <cstdint>
#include <math.h>

typedef unsigned int u32;

// Problem constants: B=1, S=2048, HIDDEN=2048, NUM_HEADS=16, MLA_DIM=HEAD_DIM=128
#define S_LEN 2048
#define HID   2048
#define NH    16
#define HD    128

// ---------------- scratch (no allocations allowed) ----------------
__device__ float g_Q[S_LEN * HID];
__device__ float g_K[S_LEN * HID];
__device__ float g_V[S_LEN * HID];
__device__ float g_AO[S_LEN * HID];
__device__ float g_Xt[S_LEN * HID];     // tf32-rounded hidden states
__device__ float g_Wq[HID * HID];
__device__ float g_Wk[HID * HID];
__device__ float g_Wv[HID * HID];
__device__ float g_Wo[HID * HID];

__device__ __forceinline__ float to_tf32(float x) {
    float r;
    asm("cvt.rna.tf32.f32 %0, %1;" : "=f"(r) : "f"(x));
    return r;
}

__device__ __forceinline__ void cp_async16(u32 dst, const void* src) {
    asm volatile("cp.async.cg.shared.global [%0], [%1], 16;" :: "r"(dst), "l"(src));
}
__device__ __forceinline__ void cp_commit() {
    asm volatile("cp.async.commit_group;");
}
__device__ __forceinline__ void cp_wait1() {
    asm volatile("cp.async.wait_group 1;");
}
__device__ __forceinline__ void cp_wait0() {
    asm volatile("cp.async.wait_group 0;");
}

__device__ __forceinline__ void mma_tf32(float* d, const u32* a, const u32* b) {
    asm volatile(
        "mma.sync.aligned.m16n8k8.row.col.f32.tf32.tf32.f32 "
        "{%0,%1,%2,%3}, {%4,%5,%6,%7}, {%8,%9}, {%0,%1,%2,%3};"
        : "+f"(d[0]), "+f"(d[1]), "+f"(d[2]), "+f"(d[3])
        : "r"(a[0]), "r"(a[1]), "r"(a[2]), "r"(a[3]), "r"(b[0]), "r"(b[1]));
}

// ---------------- tf32 pre-round pass ----------------
__global__ void cvt_tf32_kernel(const float* __restrict__ in, float* __restrict__ out) {
    int i = (blockIdx.x * blockDim.x + threadIdx.x) * 4;
    float4 v = *(const float4*)&in[i];
    v.x = to_tf32(v.x); v.y = to_tf32(v.y); v.z = to_tf32(v.z); v.w = to_tf32(v.w);
    *(float4*)&out[i] = v;
}

// ---------------- TF32 tensor-core GEMM: C[M,N] = A[M,K] @ B[K,N] ----------------
// M=N=K=2048. Block tile 128x128x16, 8 warps (4M x 2N), warp tile 32x64.
#define TBM 128
#define TBN 128
#define TBK 16
#define LDA 20    // As row stride (floats)
#define LDB 136   // Bs row stride (floats)
#define NKIT (HID / TBK)

__global__ __launch_bounds__(256) void tf32_gemm_kernel(const float* __restrict__ A,
                                                        const float* __restrict__ B,
                                                        float* __restrict__ C) {
    const int N = HID, K = HID;
    __shared__ float As[2][TBM * LDA];
    __shared__ float Bs[2][TBK * LDB];

    const int tid  = threadIdx.x;
    const int lane = tid & 31;
    const int warp = tid >> 5;
    const int warpM = warp >> 1;   // 0..3
    const int warpN = warp & 1;    // 0..1
    const int g  = lane >> 2;      // groupID 0..7
    const int tg = lane & 3;       // threadID_in_group 0..3

    const int row0 = blockIdx.y * TBM;
    const int col0 = blockIdx.x * TBN;

    // global->smem load mapping
    const int arow = tid >> 2;          // 0..63 (and +64)
    const int acol = (tid & 3) * 4;     // 0,4,8,12
    const int brow = tid >> 5;          // 0..7 (and +8)
    const int bcol = (tid & 31) * 4;    // 0..124

    const float* gA0 = A + (size_t)(row0 + arow) * K + acol;
    const float* gA1 = A + (size_t)(row0 + arow + 64) * K + acol;
    const float* gB0 = B + (size_t)brow * N + col0 + bcol;
    const float* gB1 = B + (size_t)(brow + 8) * N + col0 + bcol;

    float acc[2][8][4];
#pragma unroll
    for (int mt = 0; mt < 2; mt++)
#pragma unroll
        for (int nt = 0; nt < 8; nt++)
#pragma unroll
            for (int r = 0; r < 4; r++) acc[mt][nt][r] = 0.f;

    u32 aSm0 = (u32)__cvta_generic_to_shared(&As[0][arow * LDA + acol]);
    u32 aSm1 = (u32)__cvta_generic_to_shared(&As[1][arow * LDA + acol]);
    u32 bSm0 = (u32)__cvta_generic_to_shared(&Bs[0][brow * LDB + bcol]);
    u32 bSm1 = (u32)__cvta_generic_to_shared(&Bs[1][brow * LDB + bcol]);

    // prologue: load tile kb=0 into stage 0
    cp_async16(aSm0,                gA0);
    cp_async16(aSm0 + 64 * LDA * 4, gA1);
    cp_async16(bSm0,                gB0);
    cp_async16(bSm0 + 8 * LDB * 4,  gB1);
    cp_commit();

    for (int kb = 0; kb < NKIT; kb++) {
        int st = kb & 1;
        if (kb + 1 < NKIT) {
            int kk = (kb + 1) * TBK;
            u32 ad = st ? aSm0 : aSm1;   // next stage
            u32 bd = st ? bSm0 : bSm1;
            cp_async16(ad,                gA0 + kk);
            cp_async16(ad + 64 * LDA * 4, gA1 + kk);
            cp_async16(bd,                gB0 + (size_t)kk * N);
            cp_async16(bd + 8 * LDB * 4,  gB1 + (size_t)kk * N);
            cp_commit();
            cp_wait1();
        } else {
            cp_wait0();
        }
        __syncthreads();

        const float* as = As[st];
        const float* bs = Bs[st];
#pragma unroll
        for (int s = 0; s < 2; s++) {
            u32 af[2][4];
#pragma unroll
            for (int mt = 0; mt < 2; mt++) {
                int r = warpM * 32 + mt * 16 + g;
                int c = s * 8 + tg;
                af[mt][0] = __float_as_uint(as[r * LDA + c]);
                af[mt][1] = __float_as_uint(as[(r + 8) * LDA + c]);
                af[mt][2] = __float_as_uint(as[r * LDA + c + 4]);
                af[mt][3] = __float_as_uint(as[(r + 8) * LDA + c + 4]);
            }
            u32 bf[8][2];
#pragma unroll
            for (int nt = 0; nt < 8; nt++) {
                int n = warpN * 64 + nt * 8 + g;
                bf[nt][0] = __float_as_uint(bs[(s * 8 + tg) * LDB + n]);
                bf[nt][1] = __float_as_uint(bs[(s * 8 + tg + 4) * LDB + n]);
            }
#pragma unroll
            for (int mt = 0; mt < 2; mt++)
#pragma unroll
                for (int nt = 0; nt < 8; nt++)
                    mma_tf32(acc[mt][nt], af[mt], bf[nt]);
        }
        __syncthreads();
    }

    // epilogue
#pragma unroll
    for (int mt = 0; mt < 2; mt++) {
        int r = row0 + warpM * 32 + mt * 16 + g;
#pragma unroll
        for (int nt = 0; nt < 8; nt++) {
            int c = col0 + warpN * 64 + nt * 8 + 2 * tg;
            *(float2*)&C[(size_t)r * N + c]       = make_float2(acc[mt][nt][0], acc[mt][nt][1]);
            *(float2*)&C[(size_t)(r + 8) * N + c] = make_float2(acc[mt][nt][2], acc[mt][nt][3]);
        }
    }
}

// ---------------- RoPE (applied in-place to Q and K) ----------------
__global__ void rope_kernel(float* __restrict__ Q, float* __restrict__ K) {
    int idx = blockIdx.x * blockDim.x + threadIdx.x;  // S*NH*64 threads
    int j = idx & 63;
    int h = (idx >> 6) & (NH - 1);
    int t = idx >> 10;

    float expo   = (float)(2 * j) * (1.0f / 128.0f);
    float invfrq = expf(-expo * 9.210340371976184f);  // 10000^(-2j/128)
    float ang    = (float)t * invfrq;
    float sv, cv;
    sincosf(ang, &sv, &cv);

    int base = t * HID + h * HD + j;
    float q1 = Q[base], q2 = Q[base + 64];
    Q[base]      = q1 * cv - q2 * sv;
    Q[base + 64] = q2 * cv + q1 * sv;
    float k1 = K[base], k2 = K[base + 64];
    K[base]      = k1 * cv - k2 * sv;
    K[base + 64] = k2 * cv + k1 * sv;
}

// ---------------- Flash attention (fp32, causal, online softmax) ----------------
#define FBM 64
#define FBN 64
#define FD  128
#define LDK 129
#define LDS 68

#define FLASH_SMEM_FLOATS (FBM*FD + FBN*LDK + FBN*FD + FBM*LDS + FBM)
#define FLASH_SMEM_BYTES  (FLASH_SMEM_FLOATS * 4)

__global__ __launch_bounds__(256) void flash_kernel(const float* __restrict__ Q,
                                                    const float* __restrict__ K,
                                                    const float* __restrict__ V) {
    extern __shared__ float sm[];
    float* Qs  = sm;                   // FBM x FD
    float* Ks  = Qs + FBM * FD;        // FBN x LDK
    float* Vs  = Ks + FBN * LDK;       // FBN x FD
    float* Ss  = Vs + FBN * FD;        // FBM x LDS
    float* red = Ss + FBM * LDS;       // FBM

    const int qb  = blockIdx.x;
    const int h   = blockIdx.y;
    const int tid = threadIdx.x;
    const int tr  = (tid >> 4) * 4;
    const int tc4 = (tid & 15) * 4;
    const int tc8 = (tid & 15) * 8;
    const int qrow0 = qb * FBM;
    const float scale = 0.08838834764831845f;

    for (int i = tid; i < FBM * FD / 4; i += 256) {
        int r = i >> 5;
        int c = (i & 31) * 4;
        float4 v = *(const float4*)&Q[(qrow0 + r) * HID + h * HD + c];
        v.x *= scale; v.y *= scale; v.z *= scale; v.w *= scale;
        *(float4*)&Qs[r * FD + c] = v;
    }

    float o[4][8];
#pragma unroll
    for (int i = 0; i < 4; i++)
#pragma unroll
        for (int j = 0; j < 8; j++) o[i][j] = 0.f;
    float m_i = -1e30f, l_i = 0.f;

    for (int kb = 0; kb <= qb; kb++) {
        __syncthreads();
        int krow0 = kb * FBN;
        for (int i = tid; i < FBN * FD / 4; i += 256) {
            int r = i >> 5;
            int c = (i & 31) * 4;
            float4 kv = *(const float4*)&K[(krow0 + r) * HID + h * HD + c];
            Ks[r * LDK + c + 0] = kv.x;
            Ks[r * LDK + c + 1] = kv.y;
            Ks[r * LDK + c + 2] = kv.z;
            Ks[r * LDK + c + 3] = kv.w;
            *(float4*)&Vs[r * FD + c] = *(const float4*)&V[(krow0 + r) * HID + h * HD + c];
        }
        __syncthreads();

        float sacc[4][4];
#pragma unroll
        for (int i = 0; i < 4; i++)
#pragma unroll
            for (int j = 0; j < 4; j++) sacc[i][j] = 0.f;

        for (int d = 0; d < FD; d++) {
            float qv[4], kv[4];
#pragma unroll
            for (int i = 0; i < 4; i++) qv[i] = Qs[(tr + i) * FD + d];
#pragma unroll
            for (int j = 0; j < 4; j++) kv[j] = Ks[(tc4 + j) * LDK + d];
#pragma unroll
            for (int i = 0; i < 4; i++)
#pragma unroll
                for (int j = 0; j < 4; j++) sacc[i][j] += qv[i] * kv[j];
        }

        if (kb == qb) {
#pragma unroll
            for (int i = 0; i < 4; i++)
#pragma unroll
                for (int j = 0; j < 4; j++)
                    if (tc4 + j > tr + i) sacc[i][j] = -1e30f;
        }

#pragma unroll
        for (int i = 0; i < 4; i++)
#pragma unroll
            for (int j = 0; j < 4; j++)
                Ss[(tr + i) * LDS + tc4 + j] = sacc[i][j];
        __syncthreads();

        if (tid < FBM) {
            float tmax = -1e30f;
            for (int c = 0; c < FBN; c++) tmax = fmaxf(tmax, Ss[tid * LDS + c]);
            float mnew = fmaxf(m_i, tmax);
            float a = __expf(m_i - mnew);
            float rs = 0.f;
            for (int c = 0; c < FBN; c++) {
                float p = __expf(Ss[tid * LDS + c] - mnew);
                Ss[tid * LDS + c] = p;
                rs += p;
            }
            l_i = l_i * a + rs;
            m_i = mnew;
            red[tid] = a;
        }
        __syncthreads();

        float a[4];
#pragma unroll
        for (int i = 0; i < 4; i++) a[i] = red[tr + i];
#pragma unroll
        for (int i = 0; i < 4; i++)
#pragma unroll
            for (int j = 0; j < 8; j++) o[i][j] *= a[i];

        for (int k = 0; k < FBN; k++) {
            float4 v0 = *(const float4*)&Vs[k * FD + tc8];
            float4 v1 = *(const float4*)&Vs[k * FD + tc8 + 4];
            float vv[8] = {v0.x, v0.y, v0.z, v0.w, v1.x, v1.y, v1.z, v1.w};
            float p[4];
#pragma unroll
            for (int i = 0; i < 4; i++) p[i] = Ss[(tr + i) * LDS + k];
#pragma unroll
            for (int i = 0; i < 4; i++)
#pragma unroll
                for (int j = 0; j < 8; j++) o[i][j] += p[i] * vv[j];
        }
    }

    __syncthreads();
    if (tid < FBM) red[tid] = l_i;
    __syncthreads();

    // epilogue writes tf32-rounded AO (it feeds the tf32 output GEMM)
#pragma unroll
    for (int i = 0; i < 4; i++) {
        float inv = 1.0f / red[tr + i];
        float4 w0, w1;
        w0.x = to_tf32(o[i][0] * inv); w0.y = to_tf32(o[i][1] * inv);
        w0.z = to_tf32(o[i][2] * inv); w0.w = to_tf32(o[i][3] * inv);
        w1.x = to_tf32(o[i][4] * inv); w1.y = to_tf32(o[i][5] * inv);
        w1.z = to_tf32(o[i][6] * inv); w1.w = to_tf32(o[i][7] * inv);
        *(float4*)&g_AO[(qrow0 + tr + i) * HID + h * HD + tc8]     = w0;
        *(float4*)&g_AO[(qrow0 + tr + i) * HID + h * HD + tc8 + 4] = w1;
    }
}

// ---------------- launch ----------------
extern "C" void kernel_launch(void* const* d_in, const int* in_sizes, int n_in,
                              void* d_out, int out_size) {
    const float* X  = (const float*)d_in[0];
    const float* wq = (const float*)d_in[1];
    const float* wk = (const float*)d_in[2];
    const float* wv = (const float*)d_in[3];
    const float* wo = (const float*)d_in[4];
    float* out = (float*)d_out;

    float *Q, *K, *V, *AO, *Xt, *Wq, *Wk, *Wv, *Wo;
    cudaGetSymbolAddress((void**)&Q,  g_Q);
    cudaGetSymbolAddress((void**)&K,  g_K);
    cudaGetSymbolAddress((void**)&V,  g_V);
    cudaGetSymbolAddress((void**)&AO, g_AO);
    cudaGetSymbolAddress((void**)&Xt, g_Xt);
    cudaGetSymbolAddress((void**)&Wq, g_Wq);
    cudaGetSymbolAddress((void**)&Wk, g_Wk);
    cudaGetSymbolAddress((void**)&Wv, g_Wv);
    cudaGetSymbolAddress((void**)&Wo, g_Wo);

    cudaFuncSetAttribute(flash_kernel, cudaFuncAttributeMaxDynamicSharedMemorySize,
                         FLASH_SMEM_BYTES);

    const int CVT_N = HID * HID;  // elements per tensor
    cvt_tf32_kernel<<<CVT_N / (256 * 4), 256>>>(X,  Xt);
    cvt_tf32_kernel<<<CVT_N / (256 * 4), 256>>>(wq, Wq);
    cvt_tf32_kernel<<<CVT_N / (256 * 4), 256>>>(wk, Wk);
    cvt_tf32_kernel<<<CVT_N / (256 * 4), 256>>>(wv, Wv);
    cvt_tf32_kernel<<<CVT_N / (256 * 4), 256>>>(wo, Wo);

    dim3 gg(HID / TBN, S_LEN / TBM), gb(256);
    tf32_gemm_kernel<<<gg, gb>>>(Xt, Wq, Q);
    tf32_gemm_kernel<<<gg, gb>>>(Xt, Wk, K);
    tf32_gemm_kernel<<<gg, gb>>>(Xt, Wv, V);

    rope_kernel<<<(S_LEN * NH * 64) / 256, 256>>>(Q, K);

    flash_kernel<<<dim3(S_LEN / FBM, NH), 256, FLASH_SMEM_BYTES>>>(Q, K, V);

    tf32_gemm_kernel<<<gg, gb>>>(AO, Wo, out);

    (void)in_sizes; (void)n_in; (void)out_size;
}

// round 6
// speedup vs baseline: 3.4881x; 1.9273x over previous
#include <cuda_runtime.h>
#include <cuda_bf16.h>
#include <cstdint>
#include <math.h>

typedef unsigned int u32;

// Problem constants: B=1, S=2048, HIDDEN=2048, NUM_HEADS=16, MLA_DIM=HEAD_DIM=128
#define S_LEN 2048
#define HID   2048
#define NH    16
#define HD    128

// ---------------- scratch (no allocations allowed) ----------------
__device__ float g_Q[S_LEN * HID];
__device__ float g_K[S_LEN * HID];
__device__ float g_V[S_LEN * HID];
__device__ float g_AO[S_LEN * HID];
__device__ float g_Xt[S_LEN * HID];     // tf32-rounded hidden states
__device__ float g_Wq[HID * HID];
__device__ float g_Wk[HID * HID];
__device__ float g_Wv[HID * HID];
__device__ float g_Wo[HID * HID];

__device__ __forceinline__ float to_tf32(float x) {
    float r;
    asm("cvt.rna.tf32.f32 %0, %1;" : "=f"(r) : "f"(x));
    return r;
}

__device__ __forceinline__ void cp_async16(u32 dst, const void* src) {
    asm volatile("cp.async.cg.shared.global [%0], [%1], 16;" :: "r"(dst), "l"(src));
}
__device__ __forceinline__ void cp_commit() {
    asm volatile("cp.async.commit_group;");
}
__device__ __forceinline__ void cp_wait1() {
    asm volatile("cp.async.wait_group 1;");
}
__device__ __forceinline__ void cp_wait0() {
    asm volatile("cp.async.wait_group 0;");
}

__device__ __forceinline__ void mma_tf32(float* d, const u32* a, const u32* b) {
    asm volatile(
        "mma.sync.aligned.m16n8k8.row.col.f32.tf32.tf32.f32 "
        "{%0,%1,%2,%3}, {%4,%5,%6,%7}, {%8,%9}, {%0,%1,%2,%3};"
        : "+f"(d[0]), "+f"(d[1]), "+f"(d[2]), "+f"(d[3])
        : "r"(a[0]), "r"(a[1]), "r"(a[2]), "r"(a[3]), "r"(b[0]), "r"(b[1]));
}

// ---------------- tf32 pre-round pass (supports in-place) ----------------
__global__ void cvt_tf32_kernel(const float* __restrict__ in, float* __restrict__ out) {
    int i = (blockIdx.x * blockDim.x + threadIdx.x) * 4;
    float4 v = *(const float4*)&in[i];
    v.x = to_tf32(v.x); v.y = to_tf32(v.y); v.z = to_tf32(v.z); v.w = to_tf32(v.w);
    *(float4*)&out[i] = v;
}

// ---------------- TF32 tensor-core GEMM: C[M,N] = A[M,K] @ B[K,N] ----------------
#define TBM 128
#define TBN 128
#define TBK 16
#define LDA 20    // As row stride (floats)
#define LDB 136   // Bs row stride (floats)
#define NKIT (HID / TBK)

__global__ __launch_bounds__(256) void tf32_gemm_kernel(const float* __restrict__ A,
                                                        const float* __restrict__ B,
                                                        float* __restrict__ C) {
    const int N = HID, K = HID;
    __shared__ float As[2][TBM * LDA];
    __shared__ float Bs[2][TBK * LDB];

    const int tid  = threadIdx.x;
    const int lane = tid & 31;
    const int warp = tid >> 5;
    const int warpM = warp >> 1;   // 0..3
    const int warpN = warp & 1;    // 0..1
    const int g  = lane >> 2;      // groupID 0..7
    const int tg = lane & 3;       // threadID_in_group 0..3

    const int row0 = blockIdx.y * TBM;
    const int col0 = blockIdx.x * TBN;

    const int arow = tid >> 2;          // 0..63 (and +64)
    const int acol = (tid & 3) * 4;     // 0,4,8,12
    const int brow = tid >> 5;          // 0..7 (and +8)
    const int bcol = (tid & 31) * 4;    // 0..124

    const float* gA0 = A + (size_t)(row0 + arow) * K + acol;
    const float* gA1 = A + (size_t)(row0 + arow + 64) * K + acol;
    const float* gB0 = B + (size_t)brow * N + col0 + bcol;
    const float* gB1 = B + (size_t)(brow + 8) * N + col0 + bcol;

    float acc[2][8][4];
#pragma unroll
    for (int mt = 0; mt < 2; mt++)
#pragma unroll
        for (int nt = 0; nt < 8; nt++)
#pragma unroll
            for (int r = 0; r < 4; r++) acc[mt][nt][r] = 0.f;

    u32 aSm0 = (u32)__cvta_generic_to_shared(&As[0][arow * LDA + acol]);
    u32 aSm1 = (u32)__cvta_generic_to_shared(&As[1][arow * LDA + acol]);
    u32 bSm0 = (u32)__cvta_generic_to_shared(&Bs[0][brow * LDB + bcol]);
    u32 bSm1 = (u32)__cvta_generic_to_shared(&Bs[1][brow * LDB + bcol]);

    cp_async16(aSm0,                gA0);
    cp_async16(aSm0 + 64 * LDA * 4, gA1);
    cp_async16(bSm0,                gB0);
    cp_async16(bSm0 + 8 * LDB * 4,  gB1);
    cp_commit();

    for (int kb = 0; kb < NKIT; kb++) {
        int st = kb & 1;
        if (kb + 1 < NKIT) {
            int kk = (kb + 1) * TBK;
            u32 ad = st ? aSm0 : aSm1;   // next stage
            u32 bd = st ? bSm0 : bSm1;
            cp_async16(ad,                gA0 + kk);
            cp_async16(ad + 64 * LDA * 4, gA1 + kk);
            cp_async16(bd,                gB0 + (size_t)kk * N);
            cp_async16(bd + 8 * LDB * 4,  gB1 + (size_t)kk * N);
            cp_commit();
            cp_wait1();
        } else {
            cp_wait0();
        }
        __syncthreads();

        const float* as = As[st];
        const float* bs = Bs[st];
#pragma unroll
        for (int s = 0; s < 2; s++) {
            u32 af[2][4];
#pragma unroll
            for (int mt = 0; mt < 2; mt++) {
                int r = warpM * 32 + mt * 16 + g;
                int c = s * 8 + tg;
                af[mt][0] = __float_as_uint(as[r * LDA + c]);
                af[mt][1] = __float_as_uint(as[(r + 8) * LDA + c]);
                af[mt][2] = __float_as_uint(as[r * LDA + c + 4]);
                af[mt][3] = __float_as_uint(as[(r + 8) * LDA + c + 4]);
            }
            u32 bf[8][2];
#pragma unroll
            for (int nt = 0; nt < 8; nt++) {
                int n = warpN * 64 + nt * 8 + g;
                bf[nt][0] = __float_as_uint(bs[(s * 8 + tg) * LDB + n]);
                bf[nt][1] = __float_as_uint(bs[(s * 8 + tg + 4) * LDB + n]);
            }
#pragma unroll
            for (int mt = 0; mt < 2; mt++)
#pragma unroll
                for (int nt = 0; nt < 8; nt++)
                    mma_tf32(acc[mt][nt], af[mt], bf[nt]);
        }
        __syncthreads();
    }

#pragma unroll
    for (int mt = 0; mt < 2; mt++) {
        int r = row0 + warpM * 32 + mt * 16 + g;
#pragma unroll
        for (int nt = 0; nt < 8; nt++) {
            int c = col0 + warpN * 64 + nt * 8 + 2 * tg;
            *(float2*)&C[(size_t)r * N + c]       = make_float2(acc[mt][nt][0], acc[mt][nt][1]);
            *(float2*)&C[(size_t)(r + 8) * N + c] = make_float2(acc[mt][nt][2], acc[mt][nt][3]);
        }
    }
}

// ---------------- RoPE (in-place; K output tf32-rounded for cp.async path) ----------------
__global__ void rope_kernel(float* __restrict__ Q, float* __restrict__ K) {
    int idx = blockIdx.x * blockDim.x + threadIdx.x;  // S*NH*64 threads
    int j = idx & 63;
    int h = (idx >> 6) & (NH - 1);
    int t = idx >> 10;

    float expo   = (float)(2 * j) * (1.0f / 128.0f);
    float invfrq = expf(-expo * 9.210340371976184f);  // 10000^(-2j/128)
    float ang    = (float)t * invfrq;
    float sv, cv;
    sincosf(ang, &sv, &cv);

    int base = t * HID + h * HD + j;
    float q1 = Q[base], q2 = Q[base + 64];
    Q[base]      = q1 * cv - q2 * sv;
    Q[base + 64] = q2 * cv + q1 * sv;
    float k1 = K[base], k2 = K[base + 64];
    K[base]      = to_tf32(k1 * cv - k2 * sv);
    K[base + 64] = to_tf32(k2 * cv + k1 * sv);
}

// ---------------- Flash attention on tensor cores (tf32 mma, causal) ----------------
// Per CTA: one (q-block, head). BM=BN=64, D=128. 8 warps as 4M x 2N.
#define FLD 132   // Q/K tile lead (mod 32 == 4 -> conflict-free frags)
#define VLD 136   // V tile lead (mod 32 == 8)
#define SLD 68    // S tile lead (mod 32 == 4)

#define FM_SMEM_FLOATS (64*FLD + 2*64*FLD + 2*64*VLD + 64*SLD + 128)
#define FM_SMEM_BYTES  (FM_SMEM_FLOATS * 4)

__global__ __launch_bounds__(256) void flash_mma_kernel(const float* __restrict__ Q,
                                                        const float* __restrict__ K,
                                                        const float* __restrict__ V) {
    extern __shared__ float sm[];
    float* Qs = sm;                        // 64 x FLD
    float* Ks = Qs + 64 * FLD;             // 2 stages x 64 x FLD
    float* Vs = Ks + 2 * 64 * FLD;         // 2 stages x 64 x VLD
    float* Ss = Vs + 2 * 64 * VLD;         // 64 x SLD
    float* ra = Ss + 64 * SLD;             // 64 (alpha)
    float* rl = ra + 64;                   // 64 (l)

    const int qb = blockIdx.x, h = blockIdx.y;
    const int tid  = threadIdx.x;
    const int lane = tid & 31, warp = tid >> 5;
    const int g = lane >> 2, tg = lane & 3;
    const int wm = warp >> 1, wn = warp & 1;     // 4M x 2N
    const int m0 = wm * 16;
    const int qrow0 = qb * 64;
    const float scale = 0.08838834764831845f;    // 1/sqrt(128)

    const int srow = tid >> 2, part = tid & 3;   // softmax: 4 lanes per row

    u32 ksm = (u32)__cvta_generic_to_shared(Ks);
    u32 vsm = (u32)__cvta_generic_to_shared(Vs);

    // Q tile: scale + tf32-round
    for (int i = tid; i < 64 * 32; i += 256) {
        int r = i >> 5, c = (i & 31) << 2;
        float4 v = *(const float4*)&Q[(size_t)(qrow0 + r) * HID + h * HD + c];
        v.x = to_tf32(v.x * scale); v.y = to_tf32(v.y * scale);
        v.z = to_tf32(v.z * scale); v.w = to_tf32(v.w * scale);
        *(float4*)&Qs[r * FLD + c] = v;
    }

    // prefetch kb=0 into stage 0: 64 rows x 128 floats = 2048 float4 per tile
#pragma unroll
    for (int t = 0; t < 8; t++) {
        int c = tid + t * 256;
        int r = c >> 5, s = (c & 31) << 2;
        cp_async16(ksm + (u32)(r * FLD + s) * 4, &K[(size_t)r * HID + h * HD + s]);
        cp_async16(vsm + (u32)(r * VLD + s) * 4, &V[(size_t)r * HID + h * HD + s]);
    }
    cp_commit();

    float oac[8][4];
#pragma unroll
    for (int nt = 0; nt < 8; nt++)
#pragma unroll
        for (int r = 0; r < 4; r++) oac[nt][r] = 0.f;
    float m_i = -1e30f, l_i = 0.f;

    for (int kb = 0; kb <= qb; kb++) {
        int st = kb & 1;
        __syncthreads();   // prior iter fully consumed (Ss, Vs[st^1])
        if (kb < qb) {
            int krow0 = (kb + 1) * 64;
            u32 ko = ksm + (u32)((st ^ 1) * 64 * FLD) * 4;
            u32 vo = vsm + (u32)((st ^ 1) * 64 * VLD) * 4;
#pragma unroll
            for (int t = 0; t < 8; t++) {
                int c = tid + t * 256;
                int r = c >> 5, s = (c & 31) << 2;
                cp_async16(ko + (u32)(r * FLD + s) * 4, &K[(size_t)(krow0 + r) * HID + h * HD + s]);
                cp_async16(vo + (u32)(r * VLD + s) * 4, &V[(size_t)(krow0 + r) * HID + h * HD + s]);
            }
            cp_commit();
            cp_wait1();
        } else {
            cp_wait0();
        }
        __syncthreads();   // stage st ready (and Qs on kb==0)

        const float* ks = Ks + st * 64 * FLD;
        const float* vs = Vs + st * 64 * VLD;

        // ---- S = Q @ K^T : warp tile 16x32 at (m0, wn*32) ----
        float sac[4][4];
#pragma unroll
        for (int nt = 0; nt < 4; nt++)
#pragma unroll
            for (int r = 0; r < 4; r++) sac[nt][r] = 0.f;

#pragma unroll
        for (int kk = 0; kk < 16; kk++) {
            int k0 = kk * 8;
            u32 af[4];
            af[0] = __float_as_uint(Qs[(m0 + g) * FLD + k0 + tg]);
            af[1] = __float_as_uint(Qs[(m0 + g + 8) * FLD + k0 + tg]);
            af[2] = __float_as_uint(Qs[(m0 + g) * FLD + k0 + tg + 4]);
            af[3] = __float_as_uint(Qs[(m0 + g + 8) * FLD + k0 + tg + 4]);
#pragma unroll
            for (int nt = 0; nt < 4; nt++) {
                int n0 = wn * 32 + nt * 8;
                u32 bf[2];
                bf[0] = __float_as_uint(ks[(n0 + g) * FLD + k0 + tg]);
                bf[1] = __float_as_uint(ks[(n0 + g) * FLD + k0 + tg + 4]);
                mma_tf32(sac[nt], af, bf);
            }
        }

        // ---- causal mask + store S ----
        const bool diag = (kb == qb);
#pragma unroll
        for (int nt = 0; nt < 4; nt++) {
            int col = wn * 32 + nt * 8 + 2 * tg;
            int r0 = m0 + g, r1 = m0 + g + 8;
            float c0 = sac[nt][0], c1 = sac[nt][1], c2 = sac[nt][2], c3 = sac[nt][3];
            if (diag) {
                if (col     > r0) c0 = -1e30f;
                if (col + 1 > r0) c1 = -1e30f;
                if (col     > r1) c2 = -1e30f;
                if (col + 1 > r1) c3 = -1e30f;
            }
            Ss[r0 * SLD + col]     = c0;
            Ss[r0 * SLD + col + 1] = c1;
            Ss[r1 * SLD + col]     = c2;
            Ss[r1 * SLD + col + 1] = c3;
        }
        __syncthreads();

        // ---- online softmax: 4 lanes per row, 16 cols each ----
        {
            float* srow_p = Ss + srow * SLD + part * 16;
            float4 p0 = *(float4*)(srow_p + 0);
            float4 p1 = *(float4*)(srow_p + 4);
            float4 p2 = *(float4*)(srow_p + 8);
            float4 p3 = *(float4*)(srow_p + 12);
            float mx = fmaxf(fmaxf(fmaxf(p0.x, p0.y), fmaxf(p0.z, p0.w)),
                             fmaxf(fmaxf(p1.x, p1.y), fmaxf(p1.z, p1.w)));
            mx = fmaxf(mx, fmaxf(fmaxf(fmaxf(p2.x, p2.y), fmaxf(p2.z, p2.w)),
                                 fmaxf(fmaxf(p3.x, p3.y), fmaxf(p3.z, p3.w))));
            mx = fmaxf(mx, __shfl_xor_sync(0xffffffffu, mx, 1));
            mx = fmaxf(mx, __shfl_xor_sync(0xffffffffu, mx, 2));
            float mnew = fmaxf(m_i, mx);
            float alpha = __expf(m_i - mnew);
            p0.x = __expf(p0.x - mnew); p0.y = __expf(p0.y - mnew);
            p0.z = __expf(p0.z - mnew); p0.w = __expf(p0.w - mnew);
            p1.x = __expf(p1.x - mnew); p1.y = __expf(p1.y - mnew);
            p1.z = __expf(p1.z - mnew); p1.w = __expf(p1.w - mnew);
            p2.x = __expf(p2.x - mnew); p2.y = __expf(p2.y - mnew);
            p2.z = __expf(p2.z - mnew); p2.w = __expf(p2.w - mnew);
            p3.x = __expf(p3.x - mnew); p3.y = __expf(p3.y - mnew);
            p3.z = __expf(p3.z - mnew); p3.w = __expf(p3.w - mnew);
            float s = (((p0.x + p0.y) + (p0.z + p0.w)) + ((p1.x + p1.y) + (p1.z + p1.w)))
                    + (((p2.x + p2.y) + (p2.z + p2.w)) + ((p3.x + p3.y) + (p3.z + p3.w)));
            // tf32-round P for the PV mma
            p0.x = to_tf32(p0.x); p0.y = to_tf32(p0.y); p0.z = to_tf32(p0.z); p0.w = to_tf32(p0.w);
            p1.x = to_tf32(p1.x); p1.y = to_tf32(p1.y); p1.z = to_tf32(p1.z); p1.w = to_tf32(p1.w);
            p2.x = to_tf32(p2.x); p2.y = to_tf32(p2.y); p2.z = to_tf32(p2.z); p2.w = to_tf32(p2.w);
            p3.x = to_tf32(p3.x); p3.y = to_tf32(p3.y); p3.z = to_tf32(p3.z); p3.w = to_tf32(p3.w);
            *(float4*)(srow_p + 0)  = p0;
            *(float4*)(srow_p + 4)  = p1;
            *(float4*)(srow_p + 8)  = p2;
            *(float4*)(srow_p + 12) = p3;
            s += __shfl_xor_sync(0xffffffffu, s, 1);
            s += __shfl_xor_sync(0xffffffffu, s, 2);
            l_i = l_i * alpha + s;
            m_i = mnew;
            if (part == 0) ra[srow] = alpha;
        }
        __syncthreads();

        // ---- O = O*alpha + P @ V : warp tile 16x64 at (m0, wn*64), K=64 ----
        float a0 = ra[m0 + g], a1 = ra[m0 + g + 8];
#pragma unroll
        for (int nt = 0; nt < 8; nt++) {
            oac[nt][0] *= a0; oac[nt][1] *= a0;
            oac[nt][2] *= a1; oac[nt][3] *= a1;
        }
#pragma unroll
        for (int kk = 0; kk < 8; kk++) {
            int k0 = kk * 8;
            u32 af[4];
            af[0] = __float_as_uint(Ss[(m0 + g) * SLD + k0 + tg]);
            af[1] = __float_as_uint(Ss[(m0 + g + 8) * SLD + k0 + tg]);
            af[2] = __float_as_uint(Ss[(m0 + g) * SLD + k0 + tg + 4]);
            af[3] = __float_as_uint(Ss[(m0 + g + 8) * SLD + k0 + tg + 4]);
#pragma unroll
            for (int nt = 0; nt < 8; nt++) {
                int n0 = wn * 64 + nt * 8;
                u32 bf[2];
                bf[0] = __float_as_uint(vs[(k0 + tg) * VLD + n0 + g]);
                bf[1] = __float_as_uint(vs[(k0 + tg + 4) * VLD + n0 + g]);
                mma_tf32(oac[nt], af, bf);
            }
        }
    }

    if (part == 0) rl[srow] = l_i;
    __syncthreads();

    float inv0 = 1.0f / rl[m0 + g];
    float inv1 = 1.0f / rl[m0 + g + 8];
#pragma unroll
    for (int nt = 0; nt < 8; nt++) {
        int col = wn * 64 + nt * 8 + 2 * tg;
        int r0 = qrow0 + m0 + g, r1 = r0 + 8;
        float2 w0 = make_float2(to_tf32(oac[nt][0] * inv0), to_tf32(oac[nt][1] * inv0));
        float2 w1 = make_float2(to_tf32(oac[nt][2] * inv1), to_tf32(oac[nt][3] * inv1));
        *(float2*)&g_AO[(size_t)r0 * HID + h * HD + col] = w0;
        *(float2*)&g_AO[(size_t)r1 * HID + h * HD + col] = w1;
    }
}

// ---------------- launch ----------------
extern "C" void kernel_launch(void* const* d_in, const int* in_sizes, int n_in,
                              void* d_out, int out_size) {
    const float* X  = (const float*)d_in[0];
    const float* wq = (const float*)d_in[1];
    const float* wk = (const float*)d_in[2];
    const float* wv = (const float*)d_in[3];
    const float* wo = (const float*)d_in[4];
    float* out = (float*)d_out;

    float *Q, *K, *V, *AO, *Xt, *Wq, *Wk, *Wv, *Wo;
    cudaGetSymbolAddress((void**)&Q,  g_Q);
    cudaGetSymbolAddress((void**)&K,  g_K);
    cudaGetSymbolAddress((void**)&V,  g_V);
    cudaGetSymbolAddress((void**)&AO, g_AO);
    cudaGetSymbolAddress((void**)&Xt, g_Xt);
    cudaGetSymbolAddress((void**)&Wq, g_Wq);
    cudaGetSymbolAddress((void**)&Wk, g_Wk);
    cudaGetSymbolAddress((void**)&Wv, g_Wv);
    cudaGetSymbolAddress((void**)&Wo, g_Wo);

    cudaFuncSetAttribute(flash_mma_kernel, cudaFuncAttributeMaxDynamicSharedMemorySize,
                         FM_SMEM_BYTES);

    const int CVT_N = HID * HID;  // elements per tensor
    cvt_tf32_kernel<<<CVT_N / (256 * 4), 256>>>(X,  Xt);
    cvt_tf32_kernel<<<CVT_N / (256 * 4), 256>>>(wq, Wq);
    cvt_tf32_kernel<<<CVT_N / (256 * 4), 256>>>(wk, Wk);
    cvt_tf32_kernel<<<CVT_N / (256 * 4), 256>>>(wv, Wv);
    cvt_tf32_kernel<<<CVT_N / (256 * 4), 256>>>(wo, Wo);

    dim3 gg(HID / TBN, S_LEN / TBM), gb(256);
    tf32_gemm_kernel<<<gg, gb>>>(Xt, Wq, Q);
    tf32_gemm_kernel<<<gg, gb>>>(Xt, Wk, K);
    tf32_gemm_kernel<<<gg, gb>>>(Xt, Wv, V);

    rope_kernel<<<(S_LEN * NH * 64) / 256, 256>>>(Q, K);
    cvt_tf32_kernel<<<CVT_N / (256 * 4), 256>>>(V, V);   // in-place round for cp.async path

    flash_mma_kernel<<<dim3(S_LEN / 64, NH), 256, FM_SMEM_BYTES>>>(Q, K, V);

    tf32_gemm_kernel<<<gg, gb>>>(AO, Wo, out);

    (void)in_sizes; (void)n_in; (void)out_size;
}

// round 7
// speedup vs baseline: 3.5116x; 1.0067x over previous
#include <cuda_runtime.h>
#include <cuda_bf16.h>
#include <cstdint>
#include <math.h>

typedef unsigned int u32;

// Problem constants: B=1, S=2048, HIDDEN=2048, NUM_HEADS=16, MLA_DIM=HEAD_DIM=128
#define S_LEN 2048
#define HID   2048
#define NH    16
#define HD    128

// ---------------- scratch (no allocations allowed) ----------------
__device__ float g_Q[S_LEN * HID];
__device__ float g_K[S_LEN * HID];
__device__ float g_V[S_LEN * HID];
__device__ float g_AO[S_LEN * HID];
__device__ float g_Xt[S_LEN * HID];     // tf32-rounded hidden states
__device__ float g_Wq[HID * HID];
__device__ float g_Wk[HID * HID];
__device__ float g_Wv[HID * HID];
__device__ float g_Wo[HID * HID];

__device__ __forceinline__ float to_tf32(float x) {
    float r;
    asm("cvt.rna.tf32.f32 %0, %1;" : "=f"(r) : "f"(x));
    return r;
}

// fast exp2 for t <= 0: FMA/ALU pipes only (no MUFU).
// degree-6 Taylor of 2^f on [0,1): max rel err ~1.5e-5.
__device__ __forceinline__ float fexp2(float t) {
    t = fmaxf(t, -126.0f);
    float n = floorf(t);
    float f = t - n;
    float p = 1.5403530393381608e-4f;
    p = fmaf(p, f, 1.3333558146428443e-3f);
    p = fmaf(p, f, 9.6181291076284770e-3f);
    p = fmaf(p, f, 5.5504108664821580e-2f);
    p = fmaf(p, f, 2.4022650695910071e-1f);
    p = fmaf(p, f, 6.9314718055994531e-1f);
    p = fmaf(p, f, 1.0f);
    int e = (int)n;
    return p * __int_as_float((e + 127) << 23);
}

__device__ __forceinline__ void cp_async16(u32 dst, const void* src) {
    asm volatile("cp.async.cg.shared.global [%0], [%1], 16;" :: "r"(dst), "l"(src));
}
__device__ __forceinline__ void cp_commit() {
    asm volatile("cp.async.commit_group;");
}
__device__ __forceinline__ void cp_wait1() {
    asm volatile("cp.async.wait_group 1;");
}
__device__ __forceinline__ void cp_wait0() {
    asm volatile("cp.async.wait_group 0;");
}

__device__ __forceinline__ void mma_tf32(float* d, const u32* a, const u32* b) {
    asm volatile(
        "mma.sync.aligned.m16n8k8.row.col.f32.tf32.tf32.f32 "
        "{%0,%1,%2,%3}, {%4,%5,%6,%7}, {%8,%9}, {%0,%1,%2,%3};"
        : "+f"(d[0]), "+f"(d[1]), "+f"(d[2]), "+f"(d[3])
        : "r"(a[0]), "r"(a[1]), "r"(a[2]), "r"(a[3]), "r"(b[0]), "r"(b[1]));
}

// ---------------- tf32 pre-round: all 5 tensors in one launch ----------------
__global__ void cvt_tf32_all_kernel(const float* __restrict__ s0, float* __restrict__ d0,
                                    const float* __restrict__ s1, float* __restrict__ d1,
                                    const float* __restrict__ s2, float* __restrict__ d2,
                                    const float* __restrict__ s3, float* __restrict__ d3,
                                    const float* __restrict__ s4, float* __restrict__ d4) {
    const float* in;
    float* out;
    switch (blockIdx.y) {
        case 0: in = s0; out = d0; break;
        case 1: in = s1; out = d1; break;
        case 2: in = s2; out = d2; break;
        case 3: in = s3; out = d3; break;
        default: in = s4; out = d4; break;
    }
    int i = (blockIdx.x * blockDim.x + threadIdx.x) * 4;
    float4 v = *(const float4*)&in[i];
    v.x = to_tf32(v.x); v.y = to_tf32(v.y); v.z = to_tf32(v.z); v.w = to_tf32(v.w);
    *(float4*)&out[i] = v;
}

// ---------------- TF32 tensor-core GEMM: C[M,N] = A[M,K] @ B[K,N] ----------------
// 3-stage cp.async pipeline, one __syncthreads per K-iter.
#define TBM 128
#define TBN 128
#define TBK 16
#define LDA 20    // As row stride (floats)
#define LDB 136   // Bs row stride (floats)
#define NKIT (HID / TBK)

template <bool ROUND_OUT>
__global__ __launch_bounds__(256) void tf32_gemm_kernel(const float* __restrict__ A,
                                                        const float* __restrict__ B,
                                                        float* __restrict__ C) {
    const int N = HID, K = HID;
    __shared__ float As[3][TBM * LDA];
    __shared__ float Bs[3][TBK * LDB];

    const int tid  = threadIdx.x;
    const int lane = tid & 31;
    const int warp = tid >> 5;
    const int warpM = warp >> 1;   // 0..3
    const int warpN = warp & 1;    // 0..1
    const int g  = lane >> 2;      // groupID 0..7
    const int tg = lane & 3;       // threadID_in_group 0..3

    const int row0 = blockIdx.y * TBM;
    const int col0 = blockIdx.x * TBN;

    const int arow = tid >> 2;          // 0..63 (and +64)
    const int acol = (tid & 3) * 4;     // 0,4,8,12
    const int brow = tid >> 5;          // 0..7 (and +8)
    const int bcol = (tid & 31) * 4;    // 0..124

    const float* gA0 = A + (size_t)(row0 + arow) * K + acol;
    const float* gA1 = A + (size_t)(row0 + arow + 64) * K + acol;
    const float* gB0 = B + (size_t)brow * N + col0 + bcol;
    const float* gB1 = B + (size_t)(brow + 8) * N + col0 + bcol;

    float acc[2][8][4];
#pragma unroll
    for (int mt = 0; mt < 2; mt++)
#pragma unroll
        for (int nt = 0; nt < 8; nt++)
#pragma unroll
            for (int r = 0; r < 4; r++) acc[mt][nt][r] = 0.f;

    u32 aS[3], bS[3];
#pragma unroll
    for (int s = 0; s < 3; s++) {
        aS[s] = (u32)__cvta_generic_to_shared(&As[s][arow * LDA + acol]);
        bS[s] = (u32)__cvta_generic_to_shared(&Bs[s][brow * LDB + bcol]);
    }

    // prologue: stages 0,1 as two groups
#pragma unroll
    for (int p = 0; p < 2; p++) {
        int kk = p * TBK;
        cp_async16(aS[p],                gA0 + kk);
        cp_async16(aS[p] + 64 * LDA * 4, gA1 + kk);
        cp_async16(bS[p],                gB0 + (size_t)kk * N);
        cp_async16(bS[p] + 8 * LDB * 4,  gB1 + (size_t)kk * N);
        cp_commit();
    }

    int st = 0, ld = 2;
    for (int kb = 0; kb < NKIT; kb++) {
        if (kb == NKIT - 1) cp_wait0(); else cp_wait1();
        __syncthreads();   // stage st ready; prior compute on stage ld done by all warps

        if (kb + 2 < NKIT) {
            int kk = (kb + 2) * TBK;
            cp_async16(aS[ld],                gA0 + kk);
            cp_async16(aS[ld] + 64 * LDA * 4, gA1 + kk);
            cp_async16(bS[ld],                gB0 + (size_t)kk * N);
            cp_async16(bS[ld] + 8 * LDB * 4,  gB1 + (size_t)kk * N);
            cp_commit();
        }

        const float* as = As[st];
        const float* bs = Bs[st];
#pragma unroll
        for (int s = 0; s < 2; s++) {
            u32 af[2][4];
#pragma unroll
            for (int mt = 0; mt < 2; mt++) {
                int r = warpM * 32 + mt * 16 + g;
                int c = s * 8 + tg;
                af[mt][0] = __float_as_uint(as[r * LDA + c]);
                af[mt][1] = __float_as_uint(as[(r + 8) * LDA + c]);
                af[mt][2] = __float_as_uint(as[r * LDA + c + 4]);
                af[mt][3] = __float_as_uint(as[(r + 8) * LDA + c + 4]);
            }
            u32 bf[8][2];
#pragma unroll
            for (int nt = 0; nt < 8; nt++) {
                int n = warpN * 64 + nt * 8 + g;
                bf[nt][0] = __float_as_uint(bs[(s * 8 + tg) * LDB + n]);
                bf[nt][1] = __float_as_uint(bs[(s * 8 + tg + 4) * LDB + n]);
            }
#pragma unroll
            for (int mt = 0; mt < 2; mt++)
#pragma unroll
                for (int nt = 0; nt < 8; nt++)
                    mma_tf32(acc[mt][nt], af[mt], bf[nt]);
        }
        st = (st == 2) ? 0 : st + 1;
        ld = (ld == 2) ? 0 : ld + 1;
    }

#pragma unroll
    for (int mt = 0; mt < 2; mt++) {
        int r = row0 + warpM * 32 + mt * 16 + g;
#pragma unroll
        for (int nt = 0; nt < 8; nt++) {
            int c = col0 + warpN * 64 + nt * 8 + 2 * tg;
            float2 v0 = make_float2(acc[mt][nt][0], acc[mt][nt][1]);
            float2 v1 = make_float2(acc[mt][nt][2], acc[mt][nt][3]);
            if (ROUND_OUT) {
                v0.x = to_tf32(v0.x); v0.y = to_tf32(v0.y);
                v1.x = to_tf32(v1.x); v1.y = to_tf32(v1.y);
            }
            *(float2*)&C[(size_t)r * N + c]       = v0;
            *(float2*)&C[(size_t)(r + 8) * N + c] = v1;
        }
    }
}

// ---------------- RoPE (in-place; K output tf32-rounded for cp.async path) ----------------
__global__ void rope_kernel(float* __restrict__ Q, float* __restrict__ K) {
    int idx = blockIdx.x * blockDim.x + threadIdx.x;  // S*NH*64 threads
    int j = idx & 63;
    int h = (idx >> 6) & (NH - 1);
    int t = idx >> 10;

    float expo   = (float)(2 * j) * (1.0f / 128.0f);
    float invfrq = expf(-expo * 9.210340371976184f);  // 10000^(-2j/128)
    float ang    = (float)t * invfrq;
    float sv, cv;
    sincosf(ang, &sv, &cv);

    int base = t * HID + h * HD + j;
    float q1 = Q[base], q2 = Q[base + 64];
    Q[base]      = q1 * cv - q2 * sv;
    Q[base + 64] = q2 * cv + q1 * sv;
    float k1 = K[base], k2 = K[base + 64];
    K[base]      = to_tf32(k1 * cv - k2 * sv);
    K[base + 64] = to_tf32(k2 * cv + k1 * sv);
}

// ---------------- Flash attention on tensor cores (tf32 mma, causal) ----------------
// Per CTA: one (q-block, head). BM=BN=64, D=128. 8 warps as 4M x 2N.
// Scores computed in base-2 units (log2e folded into Q scale); softmax uses fexp2.
#define FLD 132   // Q/K tile lead (mod 32 == 4 -> conflict-free frags)
#define VLD 136   // V tile lead (mod 32 == 8)
#define SLD 68    // S tile lead (mod 32 == 4)

#define FM_SMEM_FLOATS (64*FLD + 2*64*FLD + 2*64*VLD + 64*SLD + 128)
#define FM_SMEM_BYTES  (FM_SMEM_FLOATS * 4)

__global__ __launch_bounds__(256) void flash_mma_kernel(const float* __restrict__ Q,
                                                        const float* __restrict__ K,
                                                        const float* __restrict__ V) {
    extern __shared__ float sm[];
    float* Qs = sm;                        // 64 x FLD
    float* Ks = Qs + 64 * FLD;             // 2 stages x 64 x FLD
    float* Vs = Ks + 2 * 64 * FLD;         // 2 stages x 64 x VLD
    float* Ss = Vs + 2 * 64 * VLD;         // 64 x SLD
    float* ra = Ss + 64 * SLD;             // 64 (alpha)
    float* rl = ra + 64;                   // 64 (l)

    const int qb = gridDim.x - 1 - blockIdx.x;   // heaviest CTAs first
    const int h  = blockIdx.y;
    const int tid  = threadIdx.x;
    const int lane = tid & 31, warp = tid >> 5;
    const int g = lane >> 2, tg = lane & 3;
    const int wm = warp >> 1, wn = warp & 1;     // 4M x 2N
    const int m0 = wm * 16;
    const int qrow0 = qb * 64;
    // 1/sqrt(128) * log2(e): scores land in base-2 units
    const float scale = 0.08838834764831845f * 1.4426950408889634f;

    const int srow = tid >> 2, part = tid & 3;   // softmax: 4 lanes per row

    u32 ksm = (u32)__cvta_generic_to_shared(Ks);
    u32 vsm = (u32)__cvta_generic_to_shared(Vs);

    // Q tile: scale + tf32-round
    for (int i = tid; i < 64 * 32; i += 256) {
        int r = i >> 5, c = (i & 31) << 2;
        float4 v = *(const float4*)&Q[(size_t)(qrow0 + r) * HID + h * HD + c];
        v.x = to_tf32(v.x * scale); v.y = to_tf32(v.y * scale);
        v.z = to_tf32(v.z * scale); v.w = to_tf32(v.w * scale);
        *(float4*)&Qs[r * FLD + c] = v;
    }

    // prefetch kb=0 into stage 0: 64 rows x 128 floats per tile
#pragma unroll
    for (int t = 0; t < 8; t++) {
        int c = tid + t * 256;
        int r = c >> 5, s = (c & 31) << 2;
        cp_async16(ksm + (u32)(r * FLD + s) * 4, &K[(size_t)r * HID + h * HD + s]);
        cp_async16(vsm + (u32)(r * VLD + s) * 4, &V[(size_t)r * HID + h * HD + s]);
    }
    cp_commit();

    float oac[8][4];
#pragma unroll
    for (int nt = 0; nt < 8; nt++)
#pragma unroll
        for (int r = 0; r < 4; r++) oac[nt][r] = 0.f;
    float m_i = -1e30f, l_i = 0.f;

    for (int kb = 0; kb <= qb; kb++) {
        int st = kb & 1;
        cp_wait0();
        __syncthreads();   // stage st ready; all warps done with PV(kb-1) and Ss

        const float* ks = Ks + st * 64 * FLD;
        const float* vs = Vs + st * 64 * VLD;

        // ---- S = Q @ K^T : warp tile 16x32 at (m0, wn*32) ----
        float sac[4][4];
#pragma unroll
        for (int nt = 0; nt < 4; nt++)
#pragma unroll
            for (int r = 0; r < 4; r++) sac[nt][r] = 0.f;

#pragma unroll
        for (int kk = 0; kk < 16; kk++) {
            int k0 = kk * 8;
            u32 af[4];
            af[0] = __float_as_uint(Qs[(m0 + g) * FLD + k0 + tg]);
            af[1] = __float_as_uint(Qs[(m0 + g + 8) * FLD + k0 + tg]);
            af[2] = __float_as_uint(Qs[(m0 + g) * FLD + k0 + tg + 4]);
            af[3] = __float_as_uint(Qs[(m0 + g + 8) * FLD + k0 + tg + 4]);
#pragma unroll
            for (int nt = 0; nt < 4; nt++) {
                int n0 = wn * 32 + nt * 8;
                u32 bf[2];
                bf[0] = __float_as_uint(ks[(n0 + g) * FLD + k0 + tg]);
                bf[1] = __float_as_uint(ks[(n0 + g) * FLD + k0 + tg + 4]);
                mma_tf32(sac[nt], af, bf);
            }
        }

        // ---- causal mask + store S ----
        const bool diag = (kb == qb);
#pragma unroll
        for (int nt = 0; nt < 4; nt++) {
            int col = wn * 32 + nt * 8 + 2 * tg;
            int r0 = m0 + g, r1 = m0 + g + 8;
            float c0 = sac[nt][0], c1 = sac[nt][1], c2 = sac[nt][2], c3 = sac[nt][3];
            if (diag) {
                if (col     > r0) c0 = -1e30f;
                if (col + 1 > r0) c1 = -1e30f;
                if (col     > r1) c2 = -1e30f;
                if (col + 1 > r1) c3 = -1e30f;
            }
            Ss[r0 * SLD + col]     = c0;
            Ss[r0 * SLD + col + 1] = c1;
            Ss[r1 * SLD + col]     = c2;
            Ss[r1 * SLD + col + 1] = c3;
        }
        __syncthreads();

        // ---- prefetch next K/V stage; overlaps softmax + PV ----
        if (kb < qb) {
            int krow0 = (kb + 1) * 64;
            u32 ko = ksm + (u32)((st ^ 1) * 64 * FLD) * 4;
            u32 vo = vsm + (u32)((st ^ 1) * 64 * VLD) * 4;
#pragma unroll
            for (int t = 0; t < 8; t++) {
                int c = tid + t * 256;
                int r = c >> 5, s = (c & 31) << 2;
                cp_async16(ko + (u32)(r * FLD + s) * 4, &K[(size_t)(krow0 + r) * HID + h * HD + s]);
                cp_async16(vo + (u32)(r * VLD + s) * 4, &V[(size_t)(krow0 + r) * HID + h * HD + s]);
            }
            cp_commit();
        }

        // ---- online softmax (base-2): 4 lanes per row, 16 cols each ----
        {
            float* srow_p = Ss + srow * SLD + part * 16;
            float4 p0 = *(float4*)(srow_p + 0);
            float4 p1 = *(float4*)(srow_p + 4);
            float4 p2 = *(float4*)(srow_p + 8);
            float4 p3 = *(float4*)(srow_p + 12);
            float mx = fmaxf(fmaxf(fmaxf(p0.x, p0.y), fmaxf(p0.z, p0.w)),
                             fmaxf(fmaxf(p1.x, p1.y), fmaxf(p1.z, p1.w)));
            mx = fmaxf(mx, fmaxf(fmaxf(fmaxf(p2.x, p2.y), fmaxf(p2.z, p2.w)),
                                 fmaxf(fmaxf(p3.x, p3.y), fmaxf(p3.z, p3.w))));
            mx = fmaxf(mx, __shfl_xor_sync(0xffffffffu, mx, 1));
            mx = fmaxf(mx, __shfl_xor_sync(0xffffffffu, mx, 2));
            float mnew = fmaxf(m_i, mx);
            float alpha = fexp2(m_i - mnew);
            p0.x = fexp2(p0.x - mnew); p0.y = fexp2(p0.y - mnew);
            p0.z = fexp2(p0.z - mnew); p0.w = fexp2(p0.w - mnew);
            p1.x = fexp2(p1.x - mnew); p1.y = fexp2(p1.y - mnew);
            p1.z = fexp2(p1.z - mnew); p1.w = fexp2(p1.w - mnew);
            p2.x = fexp2(p2.x - mnew); p2.y = fexp2(p2.y - mnew);
            p2.z = fexp2(p2.z - mnew); p2.w = fexp2(p2.w - mnew);
            p3.x = fexp2(p3.x - mnew); p3.y = fexp2(p3.y - mnew);
            p3.z = fexp2(p3.z - mnew); p3.w = fexp2(p3.w - mnew);
            float s = (((p0.x + p0.y) + (p0.z + p0.w)) + ((p1.x + p1.y) + (p1.z + p1.w)))
                    + (((p2.x + p2.y) + (p2.z + p2.w)) + ((p3.x + p3.y) + (p3.z + p3.w)));
            // tf32-round P for the PV mma
            p0.x = to_tf32(p0.x); p0.y = to_tf32(p0.y); p0.z = to_tf32(p0.z); p0.w = to_tf32(p0.w);
            p1.x = to_tf32(p1.x); p1.y = to_tf32(p1.y); p1.z = to_tf32(p1.z); p1.w = to_tf32(p1.w);
            p2.x = to_tf32(p2.x); p2.y = to_tf32(p2.y); p2.z = to_tf32(p2.z); p2.w = to_tf32(p2.w);
            p3.x = to_tf32(p3.x); p3.y = to_tf32(p3.y); p3.z = to_tf32(p3.z); p3.w = to_tf32(p3.w);
            *(float4*)(srow_p + 0)  = p0;
            *(float4*)(srow_p + 4)  = p1;
            *(float4*)(srow_p + 8)  = p2;
            *(float4*)(srow_p + 12) = p3;
            s += __shfl_xor_sync(0xffffffffu, s, 1);
            s += __shfl_xor_sync(0xffffffffu, s, 2);
            l_i = l_i * alpha + s;
            m_i = mnew;
            if (part == 0) ra[srow] = alpha;
        }
        __syncthreads();

        // ---- O = O*alpha + P @ V : warp tile 16x64 at (m0, wn*64), K=64 ----
        float a0 = ra[m0 + g], a1 = ra[m0 + g + 8];
#pragma unroll
        for (int nt = 0; nt < 8; nt++) {
            oac[nt][0] *= a0; oac[nt][1] *= a0;
            oac[nt][2] *= a1; oac[nt][3] *= a1;
        }
#pragma unroll
        for (int kk = 0; kk < 8; kk++) {
            int k0 = kk * 8;
            u32 af[4];
            af[0] = __float_as_uint(Ss[(m0 + g) * SLD + k0 + tg]);
            af[1] = __float_as_uint(Ss[(m0 + g + 8) * SLD + k0 + tg]);
            af[2] = __float_as_uint(Ss[(m0 + g) * SLD + k0 + tg + 4]);
            af[3] = __float_as_uint(Ss[(m0 + g + 8) * SLD + k0 + tg + 4]);
#pragma unroll
            for (int nt = 0; nt < 8; nt++) {
                int n0 = wn * 64 + nt * 8;
                u32 bf[2];
                bf[0] = __float_as_uint(vs[(k0 + tg) * VLD + n0 + g]);
                bf[1] = __float_as_uint(vs[(k0 + tg + 4) * VLD + n0 + g]);
                mma_tf32(oac[nt], af, bf);
            }
        }
    }

    if (part == 0) rl[srow] = l_i;
    __syncthreads();

    float inv0 = 1.0f / rl[m0 + g];
    float inv1 = 1.0f / rl[m0 + g + 8];
#pragma unroll
    for (int nt = 0; nt < 8; nt++) {
        int col = wn * 64 + nt * 8 + 2 * tg;
        int r0 = qrow0 + m0 + g, r1 = r0 + 8;
        float2 w0 = make_float2(to_tf32(oac[nt][0] * inv0), to_tf32(oac[nt][1] * inv0));
        float2 w1 = make_float2(to_tf32(oac[nt][2] * inv1), to_tf32(oac[nt][3] * inv1));
        *(float2*)&g_AO[(size_t)r0 * HID + h * HD + col] = w0;
        *(float2*)&g_AO[(size_t)r1 * HID + h * HD + col] = w1;
    }
}

// ---------------- launch ----------------
extern "C" void kernel_launch(void* const* d_in, const int* in_sizes, int n_in,
                              void* d_out, int out_size) {
    const float* X  = (const float*)d_in[0];
    const float* wq = (const float*)d_in[1];
    const float* wk = (const float*)d_in[2];
    const float* wv = (const float*)d_in[3];
    const float* wo = (const float*)d_in[4];
    float* out = (float*)d_out;

    float *Q, *K, *V, *AO, *Xt, *Wq, *Wk, *Wv, *Wo;
    cudaGetSymbolAddress((void**)&Q,  g_Q);
    cudaGetSymbolAddress((void**)&K,  g_K);
    cudaGetSymbolAddress((void**)&V,  g_V);
    cudaGetSymbolAddress((void**)&AO, g_AO);
    cudaGetSymbolAddress((void**)&Xt, g_Xt);
    cudaGetSymbolAddress((void**)&Wq, g_Wq);
    cudaGetSymbolAddress((void**)&Wk, g_Wk);
    cudaGetSymbolAddress((void**)&Wv, g_Wv);
    cudaGetSymbolAddress((void**)&Wo, g_Wo);

    cudaFuncSetAttribute(flash_mma_kernel, cudaFuncAttributeMaxDynamicSharedMemorySize,
                         FM_SMEM_BYTES);

    // one launch rounds all 5 input tensors to tf32
    cvt_tf32_all_kernel<<<dim3(HID * HID / (256 * 4), 5), 256>>>(
        X, Xt, wq, Wq, wk, Wk, wv, Wv, wo, Wo);

    dim3 gg(HID / TBN, S_LEN / TBM), gb(256);
    tf32_gemm_kernel<false><<<gg, gb>>>(Xt, Wq, Q);
    tf32_gemm_kernel<false><<<gg, gb>>>(Xt, Wk, K);
    tf32_gemm_kernel<true ><<<gg, gb>>>(Xt, Wv, V);   // V rounded in epilogue

    rope_kernel<<<(S_LEN * NH * 64) / 256, 256>>>(Q, K);

    flash_mma_kernel<<<dim3(S_LEN / 64, NH), 256, FM_SMEM_BYTES>>>(Q, K, V);

    tf32_gemm_kernel<false><<<gg, gb>>>(AO, Wo, out);

    (void)in_sizes; (void)n_in; (void)out_size;
}

// round 8
// speedup vs baseline: 3.7711x; 1.0739x over previous
#include <cuda_runtime.h>
#include <cuda_bf16.h>
#include <cstdint>
#include <math.h>

typedef unsigned int u32;

// Problem constants: B=1, S=2048, HIDDEN=2048, NUM_HEADS=16, MLA_DIM=HEAD_DIM=128
#define S_LEN 2048
#define HID   2048
#define NH    16
#define HD    128

// ---------------- scratch (no allocations allowed) ----------------
__device__ float g_Q[S_LEN * HID];
__device__ float g_K[S_LEN * HID];
__device__ float g_V[S_LEN * HID];
__device__ float g_AO[S_LEN * HID];
__device__ float g_Xt[S_LEN * HID];
__device__ float g_Wq[HID * HID];
__device__ float g_Wk[HID * HID];
__device__ float g_Wv[HID * HID];
__device__ float g_Wo[HID * HID];

__device__ __forceinline__ float to_tf32(float x) {
    float r;
    asm("cvt.rna.tf32.f32 %0, %1;" : "=f"(r) : "f"(x));
    return r;
}

// fast exp2 for t <= 0: FMA/ALU pipes only. deg-6 Taylor, max rel err ~1.5e-5.
__device__ __forceinline__ float fexp2(float t) {
    t = fmaxf(t, -126.0f);
    float n = floorf(t);
    float f = t - n;
    float p = 1.5403530393381608e-4f;
    p = fmaf(p, f, 1.3333558146428443e-3f);
    p = fmaf(p, f, 9.6181291076284770e-3f);
    p = fmaf(p, f, 5.5504108664821580e-2f);
    p = fmaf(p, f, 2.4022650695910071e-1f);
    p = fmaf(p, f, 6.9314718055994531e-1f);
    p = fmaf(p, f, 1.0f);
    int e = (int)n;
    return p * __int_as_float((e + 127) << 23);
}

__device__ __forceinline__ void cp_async16(u32 dst, const void* src) {
    asm volatile("cp.async.cg.shared.global [%0], [%1], 16;" :: "r"(dst), "l"(src));
}
__device__ __forceinline__ void cp_commit() { asm volatile("cp.async.commit_group;"); }
__device__ __forceinline__ void cp_wait1()  { asm volatile("cp.async.wait_group 1;"); }
__device__ __forceinline__ void cp_wait0()  { asm volatile("cp.async.wait_group 0;"); }

__device__ __forceinline__ void mma_tf32(float* d, const u32* a, const u32* b) {
    asm volatile(
        "mma.sync.aligned.m16n8k8.row.col.f32.tf32.tf32.f32 "
        "{%0,%1,%2,%3}, {%4,%5,%6,%7}, {%8,%9}, {%0,%1,%2,%3};"
        : "+f"(d[0]), "+f"(d[1]), "+f"(d[2]), "+f"(d[3])
        : "r"(a[0]), "r"(a[1]), "r"(a[2]), "r"(a[3]), "r"(b[0]), "r"(b[1]));
}

// ---------------- tf32 pre-round: all 5 tensors in one launch ----------------
__global__ void cvt_tf32_all_kernel(const float* __restrict__ s0, float* __restrict__ d0,
                                    const float* __restrict__ s1, float* __restrict__ d1,
                                    const float* __restrict__ s2, float* __restrict__ d2,
                                    const float* __restrict__ s3, float* __restrict__ d3,
                                    const float* __restrict__ s4, float* __restrict__ d4) {
    const float* in;
    float* out;
    switch (blockIdx.y) {
        case 0: in = s0; out = d0; break;
        case 1: in = s1; out = d1; break;
        case 2: in = s2; out = d2; break;
        case 3: in = s3; out = d3; break;
        default: in = s4; out = d4; break;
    }
    int i = (blockIdx.x * blockDim.x + threadIdx.x) * 4;
    float4 v = *(const float4*)&in[i];
    v.x = to_tf32(v.x); v.y = to_tf32(v.y); v.z = to_tf32(v.z); v.w = to_tf32(v.w);
    *(float4*)&out[i] = v;
}

// ---------------- TF32 tensor-core GEMM: C[M,N] = A[M,K] @ B[K,N] ----------------
// Block tile 128x128x32, 3-stage cp.async pipeline (1 sync/iter), 8 warps (4M x 2N),
// register double-buffered fragments across the four K=8 sub-groups.
#define TBM 128
#define TBN 128
#define TBK 32
#define LDA 36     // (4g+tg) mod 32 distinct -> conflict-free A frags
#define LDB 136    // (8tg+g) mod 32 distinct -> conflict-free B frags
#define ASZ (TBM * LDA)          // 4608 floats
#define BSZ (TBK * LDB)          // 4352 floats
#define GEMM_SMEM_BYTES (3 * (ASZ + BSZ) * 4)   // 107520 B
#define NKIT (HID / TBK)         // 64

template <bool ROUND_OUT>
__global__ __launch_bounds__(256, 2) void tf32_gemm_kernel(const float* __restrict__ A,
                                                           const float* __restrict__ B,
                                                           float* __restrict__ C) {
    const int N = HID, K = HID;
    extern __shared__ float gsm[];
    float* As = gsm;                 // 3 x ASZ
    float* Bs = gsm + 3 * ASZ;       // 3 x BSZ

    const int tid  = threadIdx.x;
    const int lane = tid & 31;
    const int warp = tid >> 5;
    const int warpM = warp >> 1;
    const int warpN = warp & 1;
    const int g  = lane >> 2;
    const int tg = lane & 3;

    const int row0 = blockIdx.y * TBM;
    const int col0 = blockIdx.x * TBN;

    // global->smem mapping (per stage: A 128x32, B 32x128)
    const int arow = tid >> 3;           // 0..31 (+32/64/96)
    const int acol = (tid & 7) * 4;      // 0..28
    const int brow = tid >> 5;           // 0..7 (+8/16/24)
    const int bcol = (tid & 31) * 4;     // 0..124

    const float* gA = A + (size_t)(row0 + arow) * K + acol;
    const float* gB = B + (size_t)brow * N + col0 + bcol;

    float acc[2][8][4];
#pragma unroll
    for (int mt = 0; mt < 2; mt++)
#pragma unroll
        for (int nt = 0; nt < 8; nt++)
#pragma unroll
            for (int r = 0; r < 4; r++) acc[mt][nt][r] = 0.f;

    const u32 aBase = (u32)__cvta_generic_to_shared(&As[arow * LDA + acol]);
    const u32 bBase = (u32)__cvta_generic_to_shared(&Bs[brow * LDB + bcol]);

    // prologue: stages 0,1
#pragma unroll
    for (int p = 0; p < 2; p++) {
        int kk = p * TBK;
        u32 ad = aBase + (u32)(p * ASZ) * 4;
        u32 bd = bBase + (u32)(p * BSZ) * 4;
#pragma unroll
        for (int q = 0; q < 4; q++) {
            cp_async16(ad + (u32)(q * 32 * LDA) * 4, gA + (size_t)(q * 32) * K + kk);
            cp_async16(bd + (u32)(q * 8 * LDB) * 4, gB + (size_t)(kk + q * 8) * N);
        }
        cp_commit();
    }

    int st = 0, ld = 2;
    for (int kb = 0; kb < NKIT; kb++) {
        if (kb == NKIT - 1) cp_wait0(); else cp_wait1();
        __syncthreads();

        if (kb + 2 < NKIT) {
            int kk = (kb + 2) * TBK;
            u32 ad = aBase + (u32)(ld * ASZ) * 4;
            u32 bd = bBase + (u32)(ld * BSZ) * 4;
#pragma unroll
            for (int q = 0; q < 4; q++) {
                cp_async16(ad + (u32)(q * 32 * LDA) * 4, gA + (size_t)(q * 32) * K + kk);
                cp_async16(bd + (u32)(q * 8 * LDB) * 4, gB + (size_t)(kk + q * 8) * N);
            }
            cp_commit();
        }

        const float* as = As + st * ASZ;
        const float* bs = Bs + st * BSZ;

        u32 af[2][2][4];
        u32 bf[2][8][2];
        // preload group s=0
        {
            const int c = tg;
#pragma unroll
            for (int mt = 0; mt < 2; mt++) {
                int r = warpM * 32 + mt * 16 + g;
                af[0][mt][0] = __float_as_uint(as[r * LDA + c]);
                af[0][mt][1] = __float_as_uint(as[(r + 8) * LDA + c]);
                af[0][mt][2] = __float_as_uint(as[r * LDA + c + 4]);
                af[0][mt][3] = __float_as_uint(as[(r + 8) * LDA + c + 4]);
            }
#pragma unroll
            for (int nt = 0; nt < 8; nt++) {
                int n = warpN * 64 + nt * 8 + g;
                bf[0][nt][0] = __float_as_uint(bs[tg * LDB + n]);
                bf[0][nt][1] = __float_as_uint(bs[(tg + 4) * LDB + n]);
            }
        }
#pragma unroll
        for (int s = 0; s < 4; s++) {
            const int cur = s & 1, nxt = cur ^ 1;
            if (s < 3) {
                const int c = (s + 1) * 8 + tg;
#pragma unroll
                for (int mt = 0; mt < 2; mt++) {
                    int r = warpM * 32 + mt * 16 + g;
                    af[nxt][mt][0] = __float_as_uint(as[r * LDA + c]);
                    af[nxt][mt][1] = __float_as_uint(as[(r + 8) * LDA + c]);
                    af[nxt][mt][2] = __float_as_uint(as[r * LDA + c + 4]);
                    af[nxt][mt][3] = __float_as_uint(as[(r + 8) * LDA + c + 4]);
                }
#pragma unroll
                for (int nt = 0; nt < 8; nt++) {
                    int n = warpN * 64 + nt * 8 + g;
                    bf[nxt][nt][0] = __float_as_uint(bs[(c) * LDB + n]);
                    bf[nxt][nt][1] = __float_as_uint(bs[(c + 4) * LDB + n]);
                }
            }
#pragma unroll
            for (int mt = 0; mt < 2; mt++)
#pragma unroll
                for (int nt = 0; nt < 8; nt++)
                    mma_tf32(acc[mt][nt], af[cur][mt], bf[cur][nt]);
        }

        st = (st == 2) ? 0 : st + 1;
        ld = (ld == 2) ? 0 : ld + 1;
    }

#pragma unroll
    for (int mt = 0; mt < 2; mt++) {
        int r = row0 + warpM * 32 + mt * 16 + g;
#pragma unroll
        for (int nt = 0; nt < 8; nt++) {
            int c = col0 + warpN * 64 + nt * 8 + 2 * tg;
            float2 v0 = make_float2(acc[mt][nt][0], acc[mt][nt][1]);
            float2 v1 = make_float2(acc[mt][nt][2], acc[mt][nt][3]);
            if (ROUND_OUT) {
                v0.x = to_tf32(v0.x); v0.y = to_tf32(v0.y);
                v1.x = to_tf32(v1.x); v1.y = to_tf32(v1.y);
            }
            *(float2*)&C[(size_t)r * N + c]       = v0;
            *(float2*)&C[(size_t)(r + 8) * N + c] = v1;
        }
    }
}

// ---------------- RoPE (in-place; K output tf32-rounded) ----------------
__global__ void rope_kernel(float* __restrict__ Q, float* __restrict__ K) {
    int idx = blockIdx.x * blockDim.x + threadIdx.x;
    int j = idx & 63;
    int h = (idx >> 6) & (NH - 1);
    int t = idx >> 10;

    float expo   = (float)(2 * j) * (1.0f / 128.0f);
    float invfrq = expf(-expo * 9.210340371976184f);
    float ang    = (float)t * invfrq;
    float sv, cv;
    sincosf(ang, &sv, &cv);

    int base = t * HID + h * HD + j;
    float q1 = Q[base], q2 = Q[base + 64];
    Q[base]      = q1 * cv - q2 * sv;
    Q[base + 64] = q2 * cv + q1 * sv;
    float k1 = K[base], k2 = K[base + 64];
    K[base]      = to_tf32(k1 * cv - k2 * sv);
    K[base + 64] = to_tf32(k2 * cv + k1 * sv);
}

// ---------------- Flash attention on tensor cores (tf32 mma, causal) ----------------
#define FLD 132
#define VLD 136
#define SLD 68

#define FM_SMEM_FLOATS (64*FLD + 2*64*FLD + 2*64*VLD + 64*SLD + 128)
#define FM_SMEM_BYTES  (FM_SMEM_FLOATS * 4)

__global__ __launch_bounds__(256, 1) void flash_mma_kernel(const float* __restrict__ Q,
                                                           const float* __restrict__ K,
                                                           const float* __restrict__ V) {
    extern __shared__ float sm[];
    float* Qs = sm;                        // 64 x FLD
    float* Ks = Qs + 64 * FLD;             // 2 x 64 x FLD
    float* Vs = Ks + 2 * 64 * FLD;         // 2 x 64 x VLD
    float* Ss = Vs + 2 * 64 * VLD;         // 64 x SLD
    float* ra = Ss + 64 * SLD;             // 64
    float* rl = ra + 64;                   // 64

    const int qb = gridDim.x - 1 - blockIdx.x;   // heaviest CTAs first
    const int h  = blockIdx.y;
    const int tid  = threadIdx.x;
    const int lane = tid & 31, warp = tid >> 5;
    const int g = lane >> 2, tg = lane & 3;
    const int wm = warp >> 1, wn = warp & 1;
    const int m0 = wm * 16;
    const int qrow0 = qb * 64;
    const float scale = 0.08838834764831845f * 1.4426950408889634f;  // 1/sqrt(128)*log2e

    const int srow = tid >> 2, part = tid & 3;

    u32 ksm = (u32)__cvta_generic_to_shared(Ks);
    u32 vsm = (u32)__cvta_generic_to_shared(Vs);

    for (int i = tid; i < 64 * 32; i += 256) {
        int r = i >> 5, c = (i & 31) << 2;
        float4 v = *(const float4*)&Q[(size_t)(qrow0 + r) * HID + h * HD + c];
        v.x = to_tf32(v.x * scale); v.y = to_tf32(v.y * scale);
        v.z = to_tf32(v.z * scale); v.w = to_tf32(v.w * scale);
        *(float4*)&Qs[r * FLD + c] = v;
    }

#pragma unroll
    for (int t = 0; t < 8; t++) {
        int c = tid + t * 256;
        int r = c >> 5, s = (c & 31) << 2;
        cp_async16(ksm + (u32)(r * FLD + s) * 4, &K[(size_t)r * HID + h * HD + s]);
        cp_async16(vsm + (u32)(r * VLD + s) * 4, &V[(size_t)r * HID + h * HD + s]);
    }
    cp_commit();

    float oac[8][4];
#pragma unroll
    for (int nt = 0; nt < 8; nt++)
#pragma unroll
        for (int r = 0; r < 4; r++) oac[nt][r] = 0.f;
    float m_i = -1e30f, l_i = 0.f;

    for (int kb = 0; kb <= qb; kb++) {
        int st = kb & 1;
        cp_wait0();
        __syncthreads();   // stage st ready; all warps done with kb-1 (QK+PV on st^1)

        // prefetch next K/V into st^1 immediately: overlaps whole iteration
        if (kb < qb) {
            int krow0 = (kb + 1) * 64;
            u32 ko = ksm + (u32)((st ^ 1) * 64 * FLD) * 4;
            u32 vo = vsm + (u32)((st ^ 1) * 64 * VLD) * 4;
#pragma unroll
            for (int t = 0; t < 8; t++) {
                int c = tid + t * 256;
                int r = c >> 5, s = (c & 31) << 2;
                cp_async16(ko + (u32)(r * FLD + s) * 4, &K[(size_t)(krow0 + r) * HID + h * HD + s]);
                cp_async16(vo + (u32)(r * VLD + s) * 4, &V[(size_t)(krow0 + r) * HID + h * HD + s]);
            }
            cp_commit();
        }

        const float* ks = Ks + st * 64 * FLD;
        const float* vs = Vs + st * 64 * VLD;

        // ---- S = Q @ K^T : register double-buffered frags over 16 k8-groups ----
        float sac[4][4];
#pragma unroll
        for (int nt = 0; nt < 4; nt++)
#pragma unroll
            for (int r = 0; r < 4; r++) sac[nt][r] = 0.f;

        {
            u32 qa[2][4], kf[2][4][2];
            qa[0][0] = __float_as_uint(Qs[(m0 + g) * FLD + tg]);
            qa[0][1] = __float_as_uint(Qs[(m0 + g + 8) * FLD + tg]);
            qa[0][2] = __float_as_uint(Qs[(m0 + g) * FLD + tg + 4]);
            qa[0][3] = __float_as_uint(Qs[(m0 + g + 8) * FLD + tg + 4]);
#pragma unroll
            for (int nt = 0; nt < 4; nt++) {
                int n0 = wn * 32 + nt * 8;
                kf[0][nt][0] = __float_as_uint(ks[(n0 + g) * FLD + tg]);
                kf[0][nt][1] = __float_as_uint(ks[(n0 + g) * FLD + tg + 4]);
            }
#pragma unroll
            for (int kk = 0; kk < 16; kk++) {
                const int cur = kk & 1, nxt = cur ^ 1;
                if (kk < 15) {
                    const int k0 = (kk + 1) * 8;
                    qa[nxt][0] = __float_as_uint(Qs[(m0 + g) * FLD + k0 + tg]);
                    qa[nxt][1] = __float_as_uint(Qs[(m0 + g + 8) * FLD + k0 + tg]);
                    qa[nxt][2] = __float_as_uint(Qs[(m0 + g) * FLD + k0 + tg + 4]);
                    qa[nxt][3] = __float_as_uint(Qs[(m0 + g + 8) * FLD + k0 + tg + 4]);
#pragma unroll
                    for (int nt = 0; nt < 4; nt++) {
                        int n0 = wn * 32 + nt * 8;
                        kf[nxt][nt][0] = __float_as_uint(ks[(n0 + g) * FLD + k0 + tg]);
                        kf[nxt][nt][1] = __float_as_uint(ks[(n0 + g) * FLD + k0 + tg + 4]);
                    }
                }
#pragma unroll
                for (int nt = 0; nt < 4; nt++)
                    mma_tf32(sac[nt], qa[cur], kf[cur][nt]);
            }
        }

        // ---- causal mask + store S ----
        const bool diag = (kb == qb);
#pragma unroll
        for (int nt = 0; nt < 4; nt++) {
            int col = wn * 32 + nt * 8 + 2 * tg;
            int r0 = m0 + g, r1 = m0 + g + 8;
            float c0 = sac[nt][0], c1 = sac[nt][1], c2 = sac[nt][2], c3 = sac[nt][3];
            if (diag) {
                if (col     > r0) c0 = -1e30f;
                if (col + 1 > r0) c1 = -1e30f;
                if (col     > r1) c2 = -1e30f;
                if (col + 1 > r1) c3 = -1e30f;
            }
            Ss[r0 * SLD + col]     = c0;
            Ss[r0 * SLD + col + 1] = c1;
            Ss[r1 * SLD + col]     = c2;
            Ss[r1 * SLD + col + 1] = c3;
        }
        __syncthreads();

        // ---- online softmax (base-2) ----
        {
            float* srow_p = Ss + srow * SLD + part * 16;
            float4 p0 = *(float4*)(srow_p + 0);
            float4 p1 = *(float4*)(srow_p + 4);
            float4 p2 = *(float4*)(srow_p + 8);
            float4 p3 = *(float4*)(srow_p + 12);
            float mx = fmaxf(fmaxf(fmaxf(p0.x, p0.y), fmaxf(p0.z, p0.w)),
                             fmaxf(fmaxf(p1.x, p1.y), fmaxf(p1.z, p1.w)));
            mx = fmaxf(mx, fmaxf(fmaxf(fmaxf(p2.x, p2.y), fmaxf(p2.z, p2.w)),
                                 fmaxf(fmaxf(p3.x, p3.y), fmaxf(p3.z, p3.w))));
            mx = fmaxf(mx, __shfl_xor_sync(0xffffffffu, mx, 1));
            mx = fmaxf(mx, __shfl_xor_sync(0xffffffffu, mx, 2));
            float mnew = fmaxf(m_i, mx);
            float alpha = fexp2(m_i - mnew);
            p0.x = fexp2(p0.x - mnew); p0.y = fexp2(p0.y - mnew);
            p0.z = fexp2(p0.z - mnew); p0.w = fexp2(p0.w - mnew);
            p1.x = fexp2(p1.x - mnew); p1.y = fexp2(p1.y - mnew);
            p1.z = fexp2(p1.z - mnew); p1.w = fexp2(p1.w - mnew);
            p2.x = fexp2(p2.x - mnew); p2.y = fexp2(p2.y - mnew);
            p2.z = fexp2(p2.z - mnew); p2.w = fexp2(p2.w - mnew);
            p3.x = fexp2(p3.x - mnew); p3.y = fexp2(p3.y - mnew);
            p3.z = fexp2(p3.z - mnew); p3.w = fexp2(p3.w - mnew);
            float s = (((p0.x + p0.y) + (p0.z + p0.w)) + ((p1.x + p1.y) + (p1.z + p1.w)))
                    + (((p2.x + p2.y) + (p2.z + p2.w)) + ((p3.x + p3.y) + (p3.z + p3.w)));
            p0.x = to_tf32(p0.x); p0.y = to_tf32(p0.y); p0.z = to_tf32(p0.z); p0.w = to_tf32(p0.w);
            p1.x = to_tf32(p1.x); p1.y = to_tf32(p1.y); p1.z = to_tf32(p1.z); p1.w = to_tf32(p1.w);
            p2.x = to_tf32(p2.x); p2.y = to_tf32(p2.y); p2.z = to_tf32(p2.z); p2.w = to_tf32(p2.w);
            p3.x = to_tf32(p3.x); p3.y = to_tf32(p3.y); p3.z = to_tf32(p3.z); p3.w = to_tf32(p3.w);
            *(float4*)(srow_p + 0)  = p0;
            *(float4*)(srow_p + 4)  = p1;
            *(float4*)(srow_p + 8)  = p2;
            *(float4*)(srow_p + 12) = p3;
            s += __shfl_xor_sync(0xffffffffu, s, 1);
            s += __shfl_xor_sync(0xffffffffu, s, 2);
            l_i = l_i * alpha + s;
            m_i = mnew;
            if (part == 0) ra[srow] = alpha;
        }
        __syncthreads();

        // ---- O = O*alpha + P @ V : register double-buffered frags over 8 k8-groups ----
        float a0 = ra[m0 + g], a1 = ra[m0 + g + 8];
#pragma unroll
        for (int nt = 0; nt < 8; nt++) {
            oac[nt][0] *= a0; oac[nt][1] *= a0;
            oac[nt][2] *= a1; oac[nt][3] *= a1;
        }
        {
            u32 pa[2][4], vf[2][8][2];
            pa[0][0] = __float_as_uint(Ss[(m0 + g) * SLD + tg]);
            pa[0][1] = __float_as_uint(Ss[(m0 + g + 8) * SLD + tg]);
            pa[0][2] = __float_as_uint(Ss[(m0 + g) * SLD + tg + 4]);
            pa[0][3] = __float_as_uint(Ss[(m0 + g + 8) * SLD + tg + 4]);
#pragma unroll
            for (int nt = 0; nt < 8; nt++) {
                int n0 = wn * 64 + nt * 8;
                vf[0][nt][0] = __float_as_uint(vs[tg * VLD + n0 + g]);
                vf[0][nt][1] = __float_as_uint(vs[(tg + 4) * VLD + n0 + g]);
            }
#pragma unroll
            for (int kk = 0; kk < 8; kk++) {
                const int cur = kk & 1, nxt = cur ^ 1;
                if (kk < 7) {
                    const int k0 = (kk + 1) * 8;
                    pa[nxt][0] = __float_as_uint(Ss[(m0 + g) * SLD + k0 + tg]);
                    pa[nxt][1] = __float_as_uint(Ss[(m0 + g + 8) * SLD + k0 + tg]);
                    pa[nxt][2] = __float_as_uint(Ss[(m0 + g) * SLD + k0 + tg + 4]);
                    pa[nxt][3] = __float_as_uint(Ss[(m0 + g + 8) * SLD + k0 + tg + 4]);
#pragma unroll
                    for (int nt = 0; nt < 8; nt++) {
                        int n0 = wn * 64 + nt * 8;
                        vf[nxt][nt][0] = __float_as_uint(vs[(k0 + tg) * VLD + n0 + g]);
                        vf[nxt][nt][1] = __float_as_uint(vs[(k0 + tg + 4) * VLD + n0 + g]);
                    }
                }
#pragma unroll
                for (int nt = 0; nt < 8; nt++)
                    mma_tf32(oac[nt], pa[cur], vf[cur][nt]);
            }
        }
    }

    if (part == 0) rl[srow] = l_i;
    __syncthreads();

    float inv0 = 1.0f / rl[m0 + g];
    float inv1 = 1.0f / rl[m0 + g + 8];
#pragma unroll
    for (int nt = 0; nt < 8; nt++) {
        int col = wn * 64 + nt * 8 + 2 * tg;
        int r0 = qrow0 + m0 + g, r1 = r0 + 8;
        float2 w0 = make_float2(to_tf32(oac[nt][0] * inv0), to_tf32(oac[nt][1] * inv0));
        float2 w1 = make_float2(to_tf32(oac[nt][2] * inv1), to_tf32(oac[nt][3] * inv1));
        *(float2*)&g_AO[(size_t)r0 * HID + h * HD + col] = w0;
        *(float2*)&g_AO[(size_t)r1 * HID + h * HD + col] = w1;
    }
}

// ---------------- launch ----------------
extern "C" void kernel_launch(void* const* d_in, const int* in_sizes, int n_in,
                              void* d_out, int out_size) {
    const float* X  = (const float*)d_in[0];
    const float* wq = (const float*)d_in[1];
    const float* wk = (const float*)d_in[2];
    const float* wv = (const float*)d_in[3];
    const float* wo = (const float*)d_in[4];
    float* out = (float*)d_out;

    float *Q, *K, *V, *AO, *Xt, *Wq, *Wk, *Wv, *Wo;
    cudaGetSymbolAddress((void**)&Q,  g_Q);
    cudaGetSymbolAddress((void**)&K,  g_K);
    cudaGetSymbolAddress((void**)&V,  g_V);
    cudaGetSymbolAddress((void**)&AO, g_AO);
    cudaGetSymbolAddress((void**)&Xt, g_Xt);
    cudaGetSymbolAddress((void**)&Wq, g_Wq);
    cudaGetSymbolAddress((void**)&Wk, g_Wk);
    cudaGetSymbolAddress((void**)&Wv, g_Wv);
    cudaGetSymbolAddress((void**)&Wo, g_Wo);

    cudaFuncSetAttribute(tf32_gemm_kernel<false>, cudaFuncAttributeMaxDynamicSharedMemorySize,
                         GEMM_SMEM_BYTES);
    cudaFuncSetAttribute(tf32_gemm_kernel<true>, cudaFuncAttributeMaxDynamicSharedMemorySize,
                         GEMM_SMEM_BYTES);
    cudaFuncSetAttribute(flash_mma_kernel, cudaFuncAttributeMaxDynamicSharedMemorySize,
                         FM_SMEM_BYTES);

    cvt_tf32_all_kernel<<<dim3(HID * HID / (256 * 4), 5), 256>>>(
        X, Xt, wq, Wq, wk, Wk, wv, Wv, wo, Wo);

    dim3 gg(HID / TBN, S_LEN / TBM), gb(256);
    tf32_gemm_kernel<false><<<gg, gb, GEMM_SMEM_BYTES>>>(Xt, Wq, Q);
    tf32_gemm_kernel<false><<<gg, gb, GEMM_SMEM_BYTES>>>(Xt, Wk, K);
    tf32_gemm_kernel<true ><<<gg, gb, GEMM_SMEM_BYTES>>>(Xt, Wv, V);

    rope_kernel<<<(S_LEN * NH * 64) / 256, 256>>>(Q, K);

    flash_mma_kernel<<<dim3(S_LEN / 64, NH), 256, FM_SMEM_BYTES>>>(Q, K, V);

    tf32_gemm_kernel<false><<<gg, gb, GEMM_SMEM_BYTES>>>(AO, Wo, out);

    (void)in_sizes; (void)n_in; (void)out_size;
}

// round 9
// speedup vs baseline: 4.3315x; 1.1486x over previous
#include <cuda_runtime.h>
#include <cuda_bf16.h>
#include <cstdint>
#include <math.h>

typedef unsigned int u32;

// Problem constants: B=1, S=2048, HIDDEN=2048, NUM_HEADS=16, MLA_DIM=HEAD_DIM=128
#define S_LEN 2048
#define HID   2048
#define NH    16
#define HD    128

// ---------------- scratch ----------------
__device__ float g_Q[S_LEN * HID];
__device__ float g_K[S_LEN * HID];
__device__ float g_V[S_LEN * HID];
__device__ float g_AO[S_LEN * HID];
__device__ float g_Xt[S_LEN * HID];
__device__ float g_Wq[HID * HID];   // transposed [N][K], tf32-rounded
__device__ float g_Wk[HID * HID];
__device__ float g_Wv[HID * HID];
__device__ float g_Wo[HID * HID];

__device__ __forceinline__ float to_tf32(float x) {
    float r;
    asm("cvt.rna.tf32.f32 %0, %1;" : "=f"(r) : "f"(x));
    return r;
}

// fast exp2 for t <= 0: FMA/ALU pipes only. deg-6 Taylor, max rel err ~1.5e-5.
__device__ __forceinline__ float fexp2(float t) {
    t = fmaxf(t, -126.0f);
    float n = floorf(t);
    float f = t - n;
    float p = 1.5403530393381608e-4f;
    p = fmaf(p, f, 1.3333558146428443e-3f);
    p = fmaf(p, f, 9.6181291076284770e-3f);
    p = fmaf(p, f, 5.5504108664821580e-2f);
    p = fmaf(p, f, 2.4022650695910071e-1f);
    p = fmaf(p, f, 6.9314718055994531e-1f);
    p = fmaf(p, f, 1.0f);
    int e = (int)n;
    return p * __int_as_float((e + 127) << 23);
}

__device__ __forceinline__ void cp_async16(u32 dst, const void* src) {
    asm volatile("cp.async.cg.shared.global [%0], [%1], 16;" :: "r"(dst), "l"(src));
}
__device__ __forceinline__ void cp_commit() { asm volatile("cp.async.commit_group;"); }
__device__ __forceinline__ void cp_wait1()  { asm volatile("cp.async.wait_group 1;"); }
__device__ __forceinline__ void cp_wait0()  { asm volatile("cp.async.wait_group 0;"); }

__device__ __forceinline__ void mma_tf32(float* d, const u32* a, const u32* b) {
    asm volatile(
        "mma.sync.aligned.m16n8k8.row.col.f32.tf32.tf32.f32 "
        "{%0,%1,%2,%3}, {%4,%5,%6,%7}, {%8,%9}, {%0,%1,%2,%3};"
        : "+f"(d[0]), "+f"(d[1]), "+f"(d[2]), "+f"(d[3])
        : "r"(a[0]), "r"(a[1]), "r"(a[2]), "r"(a[3]), "r"(b[0]), "r"(b[1]));
}

__device__ __forceinline__ void ldsm4(u32& r0, u32& r1, u32& r2, u32& r3, u32 addr) {
    asm volatile("ldmatrix.sync.aligned.m8n8.x4.shared.b16 {%0,%1,%2,%3}, [%4];"
                 : "=r"(r0), "=r"(r1), "=r"(r2), "=r"(r3) : "r"(addr));
}

// ---------------- prepass: round X ----------------
__global__ void cvt_x_kernel(const float* __restrict__ in, float* __restrict__ out) {
    int i = (blockIdx.x * blockDim.x + threadIdx.x) * 4;
    float4 v = *(const float4*)&in[i];
    v.x = to_tf32(v.x); v.y = to_tf32(v.y); v.z = to_tf32(v.z); v.w = to_tf32(v.w);
    *(float4*)&out[i] = v;
}

// ---------------- prepass: transpose + round the 4 weight matrices ----------------
__global__ void cvt_trans_kernel(const float* __restrict__ s0, float* __restrict__ d0,
                                 const float* __restrict__ s1, float* __restrict__ d1,
                                 const float* __restrict__ s2, float* __restrict__ d2,
                                 const float* __restrict__ s3, float* __restrict__ d3) {
    const float* in;
    float* out;
    switch (blockIdx.z) {
        case 0: in = s0; out = d0; break;
        case 1: in = s1; out = d1; break;
        case 2: in = s2; out = d2; break;
        default: in = s3; out = d3; break;
    }
    __shared__ float ts[32][33];
    int x  = blockIdx.x * 32 + threadIdx.x;
    int y0 = blockIdx.y * 32 + threadIdx.y;
#pragma unroll
    for (int i = 0; i < 4; i++)
        ts[threadIdx.y + i * 8][threadIdx.x] = in[(size_t)(y0 + i * 8) * HID + x];
    __syncthreads();
    int x2 = blockIdx.y * 32 + threadIdx.x;
    int y2 = blockIdx.x * 32 + threadIdx.y;
#pragma unroll
    for (int i = 0; i < 4; i++)
        out[(size_t)(y2 + i * 8) * HID + x2] = to_tf32(ts[threadIdx.x][threadIdx.y + i * 8]);
}

// ---------------- TF32 GEMM with ldmatrix + swizzled smem ----------------
// C[M,N] = A[M,K] @ Bt[N,K]^T. Block 128x128x32, 3-stage cp.async, 8 warps 4Mx2N.
// smem tile layout: [row(128)][chunk'(8)][16B], chunk' = chunk ^ (row & 7)  (SW128).
#define TBM 128
#define TBN 128
#define TBK 32
#define TSZ 4096                                    // floats per tile-stage (128*32)
#define GEMM_SMEM_BYTES (3 * 2 * TSZ * 4)           // 98304
#define NKIT (HID / TBK)                            // 64

template <bool ROUND_Z2>
__global__ __launch_bounds__(256, 2) void tf32_gemm_ldsm(
    const float* __restrict__ A,
    const float* __restrict__ B0, const float* __restrict__ B1, const float* __restrict__ B2,
    float* __restrict__ C0, float* __restrict__ C1, float* __restrict__ C2) {
    const float* B = (blockIdx.z == 0) ? B0 : ((blockIdx.z == 1) ? B1 : B2);
    float* C       = (blockIdx.z == 0) ? C0 : ((blockIdx.z == 1) ? C1 : C2);
    const bool round_out = ROUND_Z2 && (blockIdx.z == 2);

    const int K = HID, N = HID;
    extern __shared__ float gsm[];
    float* As = gsm;               // 3 x TSZ
    float* Bs = gsm + 3 * TSZ;     // 3 x TSZ

    const int tid  = threadIdx.x;
    const int lane = tid & 31;
    const int warp = tid >> 5;
    const int warpM = warp >> 1;
    const int warpN = warp & 1;
    const int g  = lane >> 2;
    const int tg = lane & 3;

    const int row0 = blockIdx.y * TBM;
    const int col0 = blockIdx.x * TBN;

    // ---- cp.async mapping: r_ld = tid>>3 (+32q), c_ld = tid&7 ----
    const int r_ld = tid >> 3, c_ld = tid & 7;
    const float* gA = A + (size_t)(row0 + r_ld) * K + c_ld * 4;
    const float* gB = B + (size_t)(col0 + r_ld) * K + c_ld * 4;
    const u32 smA = (u32)__cvta_generic_to_shared(As);
    const u32 smB = (u32)__cvta_generic_to_shared(Bs);
    const u32 dOff = (u32)((r_ld * 8 + (c_ld ^ (r_ld & 7))) << 4);   // bytes within stage

    // ---- ldmatrix lane bases ----
    const int l8 = lane & 7;
    const int a_m  = warpM * 32 + l8 + (((lane >> 3) & 1) << 3);
    const int a_cs = (lane >> 4) & 1;
    const int b_n  = warpN * 64 + l8 + (((lane >> 4) & 1) << 3);
    const int b_cs = (lane >> 3) & 1;

    float acc[2][8][4];
#pragma unroll
    for (int mt = 0; mt < 2; mt++)
#pragma unroll
        for (int nt = 0; nt < 8; nt++)
#pragma unroll
            for (int r = 0; r < 4; r++) acc[mt][nt][r] = 0.f;

    // prologue: stages 0,1
#pragma unroll
    for (int p = 0; p < 2; p++) {
        int kk = p * TBK;
        u32 ad = smA + (u32)(p * TSZ * 4) + dOff;
        u32 bd = smB + (u32)(p * TSZ * 4) + dOff;
#pragma unroll
        for (int q = 0; q < 4; q++) {
            cp_async16(ad + (u32)(q * 4096), gA + kk + (size_t)(q * 32) * K);
            cp_async16(bd + (u32)(q * 4096), gB + kk + (size_t)(q * 32) * K);
        }
        cp_commit();
    }

    int st = 0, ld = 2;
    for (int kb = 0; kb < NKIT; kb++) {
        if (kb == NKIT - 1) cp_wait0(); else cp_wait1();
        __syncthreads();

        if (kb + 2 < NKIT) {
            int kk = (kb + 2) * TBK;
            u32 ad = smA + (u32)(ld * TSZ * 4) + dOff;
            u32 bd = smB + (u32)(ld * TSZ * 4) + dOff;
#pragma unroll
            for (int q = 0; q < 4; q++) {
                cp_async16(ad + (u32)(q * 4096), gA + kk + (size_t)(q * 32) * K);
                cp_async16(bd + (u32)(q * 4096), gB + kk + (size_t)(q * 32) * K);
            }
            cp_commit();
        }

        // lane address bases for this stage (bytes)
        const u32 aStage = smA + (u32)(st * TSZ * 4);
        const u32 bStage = smB + (u32)(st * TSZ * 4);

        u32 af[2][2][4];   // [buf][mt][4]
        u32 bf[2][8][2];   // [buf][nt][2]

        // preload kg = 0
#pragma unroll
        for (int mt = 0; mt < 2; mt++)
            ldsm4(af[0][mt][0], af[0][mt][1], af[0][mt][2], af[0][mt][3],
                  aStage + (u32)((a_m + mt * 16) * 128 + ((a_cs ^ l8) << 4)));
#pragma unroll
        for (int p = 0; p < 4; p++)
            ldsm4(bf[0][2 * p][0], bf[0][2 * p][1], bf[0][2 * p + 1][0], bf[0][2 * p + 1][1],
                  bStage + (u32)((b_n + p * 16) * 128 + ((b_cs ^ l8) << 4)));

#pragma unroll
        for (int kg = 0; kg < 4; kg++) {
            const int cur = kg & 1, nxt = cur ^ 1;
            if (kg < 3) {
                const int c = 2 * (kg + 1);
#pragma unroll
                for (int mt = 0; mt < 2; mt++)
                    ldsm4(af[nxt][mt][0], af[nxt][mt][1], af[nxt][mt][2], af[nxt][mt][3],
                          aStage + (u32)((a_m + mt * 16) * 128 + (((c + a_cs) ^ l8) << 4)));
#pragma unroll
                for (int p = 0; p < 4; p++)
                    ldsm4(bf[nxt][2 * p][0], bf[nxt][2 * p][1], bf[nxt][2 * p + 1][0], bf[nxt][2 * p + 1][1],
                          bStage + (u32)((b_n + p * 16) * 128 + (((c + b_cs) ^ l8) << 4)));
            }
#pragma unroll
            for (int mt = 0; mt < 2; mt++)
#pragma unroll
                for (int nt = 0; nt < 8; nt++)
                    mma_tf32(acc[mt][nt], af[cur][mt], bf[cur][nt]);
        }

        st = (st == 2) ? 0 : st + 1;
        ld = (ld == 2) ? 0 : ld + 1;
    }

#pragma unroll
    for (int mt = 0; mt < 2; mt++) {
        int r = row0 + warpM * 32 + mt * 16 + g;
#pragma unroll
        for (int nt = 0; nt < 8; nt++) {
            int c = col0 + warpN * 64 + nt * 8 + 2 * tg;
            float2 v0 = make_float2(acc[mt][nt][0], acc[mt][nt][1]);
            float2 v1 = make_float2(acc[mt][nt][2], acc[mt][nt][3]);
            if (round_out) {
                v0.x = to_tf32(v0.x); v0.y = to_tf32(v0.y);
                v1.x = to_tf32(v1.x); v1.y = to_tf32(v1.y);
            }
            *(float2*)&C[(size_t)r * N + c]       = v0;
            *(float2*)&C[(size_t)(r + 8) * N + c] = v1;
        }
    }
}

// ---------------- RoPE (in-place; K output tf32-rounded) ----------------
__global__ void rope_kernel(float* __restrict__ Q, float* __restrict__ K) {
    int idx = blockIdx.x * blockDim.x + threadIdx.x;
    int j = idx & 63;
    int h = (idx >> 6) & (NH - 1);
    int t = idx >> 10;

    float expo   = (float)(2 * j) * (1.0f / 128.0f);
    float invfrq = expf(-expo * 9.210340371976184f);
    float ang    = (float)t * invfrq;
    float sv, cv;
    sincosf(ang, &sv, &cv);

    int base = t * HID + h * HD + j;
    float q1 = Q[base], q2 = Q[base + 64];
    Q[base]      = q1 * cv - q2 * sv;
    Q[base + 64] = q2 * cv + q1 * sv;
    float k1 = K[base], k2 = K[base + 64];
    K[base]      = to_tf32(k1 * cv - k2 * sv);
    K[base + 64] = to_tf32(k2 * cv + k1 * sv);
}

// ---------------- Flash attention on tensor cores (unchanged from R8) ----------------
#define FLD 132
#define VLD 136
#define SLD 68

#define FM_SMEM_FLOATS (64*FLD + 2*64*FLD + 2*64*VLD + 64*SLD + 128)
#define FM_SMEM_BYTES  (FM_SMEM_FLOATS * 4)

__global__ __launch_bounds__(256, 1) void flash_mma_kernel(const float* __restrict__ Q,
                                                           const float* __restrict__ K,
                                                           const float* __restrict__ V) {
    extern __shared__ float sm[];
    float* Qs = sm;
    float* Ks = Qs + 64 * FLD;
    float* Vs = Ks + 2 * 64 * FLD;
    float* Ss = Vs + 2 * 64 * VLD;
    float* ra = Ss + 64 * SLD;
    float* rl = ra + 64;

    const int qb = gridDim.x - 1 - blockIdx.x;
    const int h  = blockIdx.y;
    const int tid  = threadIdx.x;
    const int lane = tid & 31, warp = tid >> 5;
    const int g = lane >> 2, tg = lane & 3;
    const int wm = warp >> 1, wn = warp & 1;
    const int m0 = wm * 16;
    const int qrow0 = qb * 64;
    const float scale = 0.08838834764831845f * 1.4426950408889634f;

    const int srow = tid >> 2, part = tid & 3;

    u32 ksm = (u32)__cvta_generic_to_shared(Ks);
    u32 vsm = (u32)__cvta_generic_to_shared(Vs);

    for (int i = tid; i < 64 * 32; i += 256) {
        int r = i >> 5, c = (i & 31) << 2;
        float4 v = *(const float4*)&Q[(size_t)(qrow0 + r) * HID + h * HD + c];
        v.x = to_tf32(v.x * scale); v.y = to_tf32(v.y * scale);
        v.z = to_tf32(v.z * scale); v.w = to_tf32(v.w * scale);
        *(float4*)&Qs[r * FLD + c] = v;
    }

#pragma unroll
    for (int t = 0; t < 8; t++) {
        int c = tid + t * 256;
        int r = c >> 5, s = (c & 31) << 2;
        cp_async16(ksm + (u32)(r * FLD + s) * 4, &K[(size_t)r * HID + h * HD + s]);
        cp_async16(vsm + (u32)(r * VLD + s) * 4, &V[(size_t)r * HID + h * HD + s]);
    }
    cp_commit();

    float oac[8][4];
#pragma unroll
    for (int nt = 0; nt < 8; nt++)
#pragma unroll
        for (int r = 0; r < 4; r++) oac[nt][r] = 0.f;
    float m_i = -1e30f, l_i = 0.f;

    for (int kb = 0; kb <= qb; kb++) {
        int st = kb & 1;
        cp_wait0();
        __syncthreads();

        if (kb < qb) {
            int krow0 = (kb + 1) * 64;
            u32 ko = ksm + (u32)((st ^ 1) * 64 * FLD) * 4;
            u32 vo = vsm + (u32)((st ^ 1) * 64 * VLD) * 4;
#pragma unroll
            for (int t = 0; t < 8; t++) {
                int c = tid + t * 256;
                int r = c >> 5, s = (c & 31) << 2;
                cp_async16(ko + (u32)(r * FLD + s) * 4, &K[(size_t)(krow0 + r) * HID + h * HD + s]);
                cp_async16(vo + (u32)(r * VLD + s) * 4, &V[(size_t)(krow0 + r) * HID + h * HD + s]);
            }
            cp_commit();
        }

        const float* ks = Ks + st * 64 * FLD;
        const float* vs = Vs + st * 64 * VLD;

        float sac[4][4];
#pragma unroll
        for (int nt = 0; nt < 4; nt++)
#pragma unroll
            for (int r = 0; r < 4; r++) sac[nt][r] = 0.f;

        {
            u32 qa[2][4], kf[2][4][2];
            qa[0][0] = __float_as_uint(Qs[(m0 + g) * FLD + tg]);
            qa[0][1] = __float_as_uint(Qs[(m0 + g + 8) * FLD + tg]);
            qa[0][2] = __float_as_uint(Qs[(m0 + g) * FLD + tg + 4]);
            qa[0][3] = __float_as_uint(Qs[(m0 + g + 8) * FLD + tg + 4]);
#pragma unroll
            for (int nt = 0; nt < 4; nt++) {
                int n0 = wn * 32 + nt * 8;
                kf[0][nt][0] = __float_as_uint(ks[(n0 + g) * FLD + tg]);
                kf[0][nt][1] = __float_as_uint(ks[(n0 + g) * FLD + tg + 4]);
            }
#pragma unroll
            for (int kk = 0; kk < 16; kk++) {
                const int cur = kk & 1, nxt = cur ^ 1;
                if (kk < 15) {
                    const int k0 = (kk + 1) * 8;
                    qa[nxt][0] = __float_as_uint(Qs[(m0 + g) * FLD + k0 + tg]);
                    qa[nxt][1] = __float_as_uint(Qs[(m0 + g + 8) * FLD + k0 + tg]);
                    qa[nxt][2] = __float_as_uint(Qs[(m0 + g) * FLD + k0 + tg + 4]);
                    qa[nxt][3] = __float_as_uint(Qs[(m0 + g + 8) * FLD + k0 + tg + 4]);
#pragma unroll
                    for (int nt = 0; nt < 4; nt++) {
                        int n0 = wn * 32 + nt * 8;
                        kf[nxt][nt][0] = __float_as_uint(ks[(n0 + g) * FLD + k0 + tg]);
                        kf[nxt][nt][1] = __float_as_uint(ks[(n0 + g) * FLD + k0 + tg + 4]);
                    }
                }
#pragma unroll
                for (int nt = 0; nt < 4; nt++)
                    mma_tf32(sac[nt], qa[cur], kf[cur][nt]);
            }
        }

        const bool diag = (kb == qb);
#pragma unroll
        for (int nt = 0; nt < 4; nt++) {
            int col = wn * 32 + nt * 8 + 2 * tg;
            int r0 = m0 + g, r1 = m0 + g + 8;
            float c0 = sac[nt][0], c1 = sac[nt][1], c2 = sac[nt][2], c3 = sac[nt][3];
            if (diag) {
                if (col     > r0) c0 = -1e30f;
                if (col + 1 > r0) c1 = -1e30f;
                if (col     > r1) c2 = -1e30f;
                if (col + 1 > r1) c3 = -1e30f;
            }
            Ss[r0 * SLD + col]     = c0;
            Ss[r0 * SLD + col + 1] = c1;
            Ss[r1 * SLD + col]     = c2;
            Ss[r1 * SLD + col + 1] = c3;
        }
        __syncthreads();

        {
            float* srow_p = Ss + srow * SLD + part * 16;
            float4 p0 = *(float4*)(srow_p + 0);
            float4 p1 = *(float4*)(srow_p + 4);
            float4 p2 = *(float4*)(srow_p + 8);
            float4 p3 = *(float4*)(srow_p + 12);
            float mx = fmaxf(fmaxf(fmaxf(p0.x, p0.y), fmaxf(p0.z, p0.w)),
                             fmaxf(fmaxf(p1.x, p1.y), fmaxf(p1.z, p1.w)));
            mx = fmaxf(mx, fmaxf(fmaxf(fmaxf(p2.x, p2.y), fmaxf(p2.z, p2.w)),
                                 fmaxf(fmaxf(p3.x, p3.y), fmaxf(p3.z, p3.w))));
            mx = fmaxf(mx, __shfl_xor_sync(0xffffffffu, mx, 1));
            mx = fmaxf(mx, __shfl_xor_sync(0xffffffffu, mx, 2));
            float mnew = fmaxf(m_i, mx);
            float alpha = fexp2(m_i - mnew);
            p0.x = fexp2(p0.x - mnew); p0.y = fexp2(p0.y - mnew);
            p0.z = fexp2(p0.z - mnew); p0.w = fexp2(p0.w - mnew);
            p1.x = fexp2(p1.x - mnew); p1.y = fexp2(p1.y - mnew);
            p1.z = fexp2(p1.z - mnew); p1.w = fexp2(p1.w - mnew);
            p2.x = fexp2(p2.x - mnew); p2.y = fexp2(p2.y - mnew);
            p2.z = fexp2(p2.z - mnew); p2.w = fexp2(p2.w - mnew);
            p3.x = fexp2(p3.x - mnew); p3.y = fexp2(p3.y - mnew);
            p3.z = fexp2(p3.z - mnew); p3.w = fexp2(p3.w - mnew);
            float s = (((p0.x + p0.y) + (p0.z + p0.w)) + ((p1.x + p1.y) + (p1.z + p1.w)))
                    + (((p2.x + p2.y) + (p2.z + p2.w)) + ((p3.x + p3.y) + (p3.z + p3.w)));
            p0.x = to_tf32(p0.x); p0.y = to_tf32(p0.y); p0.z = to_tf32(p0.z); p0.w = to_tf32(p0.w);
            p1.x = to_tf32(p1.x); p1.y = to_tf32(p1.y); p1.z = to_tf32(p1.z); p1.w = to_tf32(p1.w);
            p2.x = to_tf32(p2.x); p2.y = to_tf32(p2.y); p2.z = to_tf32(p2.z); p2.w = to_tf32(p2.w);
            p3.x = to_tf32(p3.x); p3.y = to_tf32(p3.y); p3.z = to_tf32(p3.z); p3.w = to_tf32(p3.w);
            *(float4*)(srow_p + 0)  = p0;
            *(float4*)(srow_p + 4)  = p1;
            *(float4*)(srow_p + 8)  = p2;
            *(float4*)(srow_p + 12) = p3;
            s += __shfl_xor_sync(0xffffffffu, s, 1);
            s += __shfl_xor_sync(0xffffffffu, s, 2);
            l_i = l_i * alpha + s;
            m_i = mnew;
            if (part == 0) ra[srow] = alpha;
        }
        __syncthreads();

        float a0 = ra[m0 + g], a1 = ra[m0 + g + 8];
#pragma unroll
        for (int nt = 0; nt < 8; nt++) {
            oac[nt][0] *= a0; oac[nt][1] *= a0;
            oac[nt][2] *= a1; oac[nt][3] *= a1;
        }
        {
            u32 pa[2][4], vf[2][8][2];
            pa[0][0] = __float_as_uint(Ss[(m0 + g) * SLD + tg]);
            pa[0][1] = __float_as_uint(Ss[(m0 + g + 8) * SLD + tg]);
            pa[0][2] = __float_as_uint(Ss[(m0 + g) * SLD + tg + 4]);
            pa[0][3] = __float_as_uint(Ss[(m0 + g + 8) * SLD + tg + 4]);
#pragma unroll
            for (int nt = 0; nt < 8; nt++) {
                int n0 = wn * 64 + nt * 8;
                vf[0][nt][0] = __float_as_uint(vs[tg * VLD + n0 + g]);
                vf[0][nt][1] = __float_as_uint(vs[(tg + 4) * VLD + n0 + g]);
            }
#pragma unroll
            for (int kk = 0; kk < 8; kk++) {
                const int cur = kk & 1, nxt = cur ^ 1;
                if (kk < 7) {
                    const int k0 = (kk + 1) * 8;
                    pa[nxt][0] = __float_as_uint(Ss[(m0 + g) * SLD + k0 + tg]);
                    pa[nxt][1] = __float_as_uint(Ss[(m0 + g + 8) * SLD + k0 + tg]);
                    pa[nxt][2] = __float_as_uint(Ss[(m0 + g) * SLD + k0 + tg + 4]);
                    pa[nxt][3] = __float_as_uint(Ss[(m0 + g + 8) * SLD + k0 + tg + 4]);
#pragma unroll
                    for (int nt = 0; nt < 8; nt++) {
                        int n0 = wn * 64 + nt * 8;
                        vf[nxt][nt][0] = __float_as_uint(vs[(k0 + tg) * VLD + n0 + g]);
                        vf[nxt][nt][1] = __float_as_uint(vs[(k0 + tg + 4) * VLD + n0 + g]);
                    }
                }
#pragma unroll
                for (int nt = 0; nt < 8; nt++)
                    mma_tf32(oac[nt], pa[cur], vf[cur][nt]);
            }
        }
    }

    if (part == 0) rl[srow] = l_i;
    __syncthreads();

    float inv0 = 1.0f / rl[m0 + g];
    float inv1 = 1.0f / rl[m0 + g + 8];
#pragma unroll
    for (int nt = 0; nt < 8; nt++) {
        int col = wn * 64 + nt * 8 + 2 * tg;
        int r0 = qrow0 + m0 + g, r1 = r0 + 8;
        float2 w0 = make_float2(to_tf32(oac[nt][0] * inv0), to_tf32(oac[nt][1] * inv0));
        float2 w1 = make_float2(to_tf32(oac[nt][2] * inv1), to_tf32(oac[nt][3] * inv1));
        *(float2*)&g_AO[(size_t)r0 * HID + h * HD + col] = w0;
        *(float2*)&g_AO[(size_t)r1 * HID + h * HD + col] = w1;
    }
}

// ---------------- launch ----------------
extern "C" void kernel_launch(void* const* d_in, const int* in_sizes, int n_in,
                              void* d_out, int out_size) {
    const float* X  = (const float*)d_in[0];
    const float* wq = (const float*)d_in[1];
    const float* wk = (const float*)d_in[2];
    const float* wv = (const float*)d_in[3];
    const float* wo = (const float*)d_in[4];
    float* out = (float*)d_out;

    float *Q, *K, *V, *AO, *Xt, *Wq, *Wk, *Wv, *Wo;
    cudaGetSymbolAddress((void**)&Q,  g_Q);
    cudaGetSymbolAddress((void**)&K,  g_K);
    cudaGetSymbolAddress((void**)&V,  g_V);
    cudaGetSymbolAddress((void**)&AO, g_AO);
    cudaGetSymbolAddress((void**)&Xt, g_Xt);
    cudaGetSymbolAddress((void**)&Wq, g_Wq);
    cudaGetSymbolAddress((void**)&Wk, g_Wk);
    cudaGetSymbolAddress((void**)&Wv, g_Wv);
    cudaGetSymbolAddress((void**)&Wo, g_Wo);

    cudaFuncSetAttribute(tf32_gemm_ldsm<true>, cudaFuncAttributeMaxDynamicSharedMemorySize,
                         GEMM_SMEM_BYTES);
    cudaFuncSetAttribute(tf32_gemm_ldsm<false>, cudaFuncAttributeMaxDynamicSharedMemorySize,
                         GEMM_SMEM_BYTES);
    cudaFuncSetAttribute(flash_mma_kernel, cudaFuncAttributeMaxDynamicSharedMemorySize,
                         FM_SMEM_BYTES);

    cvt_x_kernel<<<HID * HID / (256 * 4), 256>>>(X, Xt);
    cvt_trans_kernel<<<dim3(64, 64, 4), dim3(32, 8)>>>(wq, Wq, wk, Wk, wv, Wv, wo, Wo);

    // fused Q/K/V projections (z selects weight/output); V rounded in epilogue
    tf32_gemm_ldsm<true><<<dim3(16, 16, 3), 256, GEMM_SMEM_BYTES>>>(
        Xt, Wq, Wk, Wv, Q, K, V);

    rope_kernel<<<(S_LEN * NH * 64) / 256, 256>>>(Q, K);

    flash_mma_kernel<<<dim3(S_LEN / 64, NH), 256, FM_SMEM_BYTES>>>(Q, K, V);

    tf32_gemm_ldsm<false><<<dim3(16, 16, 1), 256, GEMM_SMEM_BYTES>>>(
        AO, Wo, Wo, Wo, out, out, out);

    (void)in_sizes; (void)n_in; (void)out_size;
}

// round 11
// speedup vs baseline: 4.4564x; 1.0289x over previous
#include <cuda_runtime.h>
#include <cuda_bf16.h>
#include <cstdint>
#include <math.h>

typedef unsigned int u32;

// Problem constants: B=1, S=2048, HIDDEN=2048, NUM_HEADS=16, MLA_DIM=HEAD_DIM=128
#define S_LEN 2048
#define HID   2048
#define NH    16
#define HD    128

// ---------------- scratch ----------------
__device__ float g_Q[S_LEN * HID];
__device__ float g_K[S_LEN * HID];
__device__ float g_V[S_LEN * HID];
__device__ float g_AO[S_LEN * HID];
__device__ float g_Xt[S_LEN * HID];
__device__ float g_Wq[HID * HID];   // transposed [N][K], tf32-rounded
__device__ float g_Wk[HID * HID];
__device__ float g_Wv[HID * HID];
__device__ float g_Wo[HID * HID];

__device__ __forceinline__ float to_tf32(float x) {
    float r;
    asm("cvt.rna.tf32.f32 %0, %1;" : "=f"(r) : "f"(x));
    return r;
}

// fast exp2 for t <= 0: FMA/ALU pipes only. deg-6 Taylor, max rel err ~1.5e-5.
__device__ __forceinline__ float fexp2(float t) {
    t = fmaxf(t, -126.0f);
    float n = floorf(t);
    float f = t - n;
    float p = 1.5403530393381608e-4f;
    p = fmaf(p, f, 1.3333558146428443e-3f);
    p = fmaf(p, f, 9.6181291076284770e-3f);
    p = fmaf(p, f, 5.5504108664821580e-2f);
    p = fmaf(p, f, 2.4022650695910071e-1f);
    p = fmaf(p, f, 6.9314718055994531e-1f);
    p = fmaf(p, f, 1.0f);
    int e = (int)n;
    return p * __int_as_float((e + 127) << 23);
}

__device__ __forceinline__ void cp_async16(u32 dst, const void* src) {
    asm volatile("cp.async.cg.shared.global [%0], [%1], 16;" :: "r"(dst), "l"(src));
}
__device__ __forceinline__ void cp_commit() { asm volatile("cp.async.commit_group;"); }
__device__ __forceinline__ void cp_wait1()  { asm volatile("cp.async.wait_group 1;"); }
__device__ __forceinline__ void cp_wait0()  { asm volatile("cp.async.wait_group 0;"); }

__device__ __forceinline__ void mma_tf32(float* d, const u32* a, const u32* b) {
    asm volatile(
        "mma.sync.aligned.m16n8k8.row.col.f32.tf32.tf32.f32 "
        "{%0,%1,%2,%3}, {%4,%5,%6,%7}, {%8,%9}, {%0,%1,%2,%3};"
        : "+f"(d[0]), "+f"(d[1]), "+f"(d[2]), "+f"(d[3])
        : "r"(a[0]), "r"(a[1]), "r"(a[2]), "r"(a[3]), "r"(b[0]), "r"(b[1]));
}

__device__ __forceinline__ void ldsm4(u32& r0, u32& r1, u32& r2, u32& r3, u32 addr) {
    asm volatile("ldmatrix.sync.aligned.m8n8.x4.shared.b16 {%0,%1,%2,%3}, [%4];"
                 : "=r"(r0), "=r"(r1), "=r"(r2), "=r"(r3) : "r"(addr));
}

// ---------------- prepass: round X ----------------
__global__ void cvt_x_kernel(const float* __restrict__ in, float* __restrict__ out) {
    int i = (blockIdx.x * blockDim.x + threadIdx.x) * 4;
    float4 v = *(const float4*)&in[i];
    v.x = to_tf32(v.x); v.y = to_tf32(v.y); v.z = to_tf32(v.z); v.w = to_tf32(v.w);
    *(float4*)&out[i] = v;
}

// ---------------- prepass: transpose + round the 4 weight matrices ----------------
__global__ void cvt_trans_kernel(const float* __restrict__ s0, float* __restrict__ d0,
                                 const float* __restrict__ s1, float* __restrict__ d1,
                                 const float* __restrict__ s2, float* __restrict__ d2,
                                 const float* __restrict__ s3, float* __restrict__ d3) {
    const float* in;
    float* out;
    switch (blockIdx.z) {
        case 0: in = s0; out = d0; break;
        case 1: in = s1; out = d1; break;
        case 2: in = s2; out = d2; break;
        default: in = s3; out = d3; break;
    }
    __shared__ float ts[32][33];
    int x  = blockIdx.x * 32 + threadIdx.x;
    int y0 = blockIdx.y * 32 + threadIdx.y;
#pragma unroll
    for (int i = 0; i < 4; i++)
        ts[threadIdx.y + i * 8][threadIdx.x] = in[(size_t)(y0 + i * 8) * HID + x];
    __syncthreads();
    int x2 = blockIdx.y * 32 + threadIdx.x;
    int y2 = blockIdx.x * 32 + threadIdx.y;
#pragma unroll
    for (int i = 0; i < 4; i++)
        out[(size_t)(y2 + i * 8) * HID + x2] = to_tf32(ts[threadIdx.x][threadIdx.y + i * 8]);
}

// ---------------- TF32 GEMM with ldmatrix + swizzled smem (unchanged from R9) ----------------
#define TBM 128
#define TBN 128
#define TBK 32
#define TSZ 4096
#define GEMM_SMEM_BYTES (3 * 2 * TSZ * 4)
#define NKIT (HID / TBK)

template <bool ROUND_Z2>
__global__ __launch_bounds__(256, 2) void tf32_gemm_ldsm(
    const float* __restrict__ A,
    const float* __restrict__ B0, const float* __restrict__ B1, const float* __restrict__ B2,
    float* __restrict__ C0, float* __restrict__ C1, float* __restrict__ C2) {
    const float* B = (blockIdx.z == 0) ? B0 : ((blockIdx.z == 1) ? B1 : B2);
    float* C       = (blockIdx.z == 0) ? C0 : ((blockIdx.z == 1) ? C1 : C2);
    const bool round_out = ROUND_Z2 && (blockIdx.z == 2);

    const int K = HID, N = HID;
    extern __shared__ float gsm[];
    float* As = gsm;
    float* Bs = gsm + 3 * TSZ;

    const int tid  = threadIdx.x;
    const int lane = tid & 31;
    const int warp = tid >> 5;
    const int warpM = warp >> 1;
    const int warpN = warp & 1;
    const int g  = lane >> 2;
    const int tg = lane & 3;

    const int row0 = blockIdx.y * TBM;
    const int col0 = blockIdx.x * TBN;

    const int r_ld = tid >> 3, c_ld = tid & 7;
    const float* gA = A + (size_t)(row0 + r_ld) * K + c_ld * 4;
    const float* gB = B + (size_t)(col0 + r_ld) * K + c_ld * 4;
    const u32 smA = (u32)__cvta_generic_to_shared(As);
    const u32 smB = (u32)__cvta_generic_to_shared(Bs);
    const u32 dOff = (u32)((r_ld * 8 + (c_ld ^ (r_ld & 7))) << 4);

    const int l8 = lane & 7;
    const int a_m  = warpM * 32 + l8 + (((lane >> 3) & 1) << 3);
    const int a_cs = (lane >> 4) & 1;
    const int b_n  = warpN * 64 + l8 + (((lane >> 4) & 1) << 3);
    const int b_cs = (lane >> 3) & 1;

    float acc[2][8][4];
#pragma unroll
    for (int mt = 0; mt < 2; mt++)
#pragma unroll
        for (int nt = 0; nt < 8; nt++)
#pragma unroll
            for (int r = 0; r < 4; r++) acc[mt][nt][r] = 0.f;

#pragma unroll
    for (int p = 0; p < 2; p++) {
        int kk = p * TBK;
        u32 ad = smA + (u32)(p * TSZ * 4) + dOff;
        u32 bd = smB + (u32)(p * TSZ * 4) + dOff;
#pragma unroll
        for (int q = 0; q < 4; q++) {
            cp_async16(ad + (u32)(q * 4096), gA + kk + (size_t)(q * 32) * K);
            cp_async16(bd + (u32)(q * 4096), gB + kk + (size_t)(q * 32) * K);
        }
        cp_commit();
    }

    int st = 0, ld = 2;
    for (int kb = 0; kb < NKIT; kb++) {
        if (kb == NKIT - 1) cp_wait0(); else cp_wait1();
        __syncthreads();

        if (kb + 2 < NKIT) {
            int kk = (kb + 2) * TBK;
            u32 ad = smA + (u32)(ld * TSZ * 4) + dOff;
            u32 bd = smB + (u32)(ld * TSZ * 4) + dOff;
#pragma unroll
            for (int q = 0; q < 4; q++) {
                cp_async16(ad + (u32)(q * 4096), gA + kk + (size_t)(q * 32) * K);
                cp_async16(bd + (u32)(q * 4096), gB + kk + (size_t)(q * 32) * K);
            }
            cp_commit();
        }

        const u32 aStage = smA + (u32)(st * TSZ * 4);
        const u32 bStage = smB + (u32)(st * TSZ * 4);

        u32 af[2][2][4];
        u32 bf[2][8][2];

#pragma unroll
        for (int mt = 0; mt < 2; mt++)
            ldsm4(af[0][mt][0], af[0][mt][1], af[0][mt][2], af[0][mt][3],
                  aStage + (u32)((a_m + mt * 16) * 128 + ((a_cs ^ l8) << 4)));
#pragma unroll
        for (int p = 0; p < 4; p++)
            ldsm4(bf[0][2 * p][0], bf[0][2 * p][1], bf[0][2 * p + 1][0], bf[0][2 * p + 1][1],
                  bStage + (u32)((b_n + p * 16) * 128 + ((b_cs ^ l8) << 4)));

#pragma unroll
        for (int kg = 0; kg < 4; kg++) {
            const int cur = kg & 1, nxt = cur ^ 1;
            if (kg < 3) {
                const int c = 2 * (kg + 1);
#pragma unroll
                for (int mt = 0; mt < 2; mt++)
                    ldsm4(af[nxt][mt][0], af[nxt][mt][1], af[nxt][mt][2], af[nxt][mt][3],
                          aStage + (u32)((a_m + mt * 16) * 128 + (((c + a_cs) ^ l8) << 4)));
#pragma unroll
                for (int p = 0; p < 4; p++)
                    ldsm4(bf[nxt][2 * p][0], bf[nxt][2 * p][1], bf[nxt][2 * p + 1][0], bf[nxt][2 * p + 1][1],
                          bStage + (u32)((b_n + p * 16) * 128 + (((c + b_cs) ^ l8) << 4)));
            }
#pragma unroll
            for (int mt = 0; mt < 2; mt++)
#pragma unroll
                for (int nt = 0; nt < 8; nt++)
                    mma_tf32(acc[mt][nt], af[cur][mt], bf[cur][nt]);
        }

        st = (st == 2) ? 0 : st + 1;
        ld = (ld == 2) ? 0 : ld + 1;
    }

#pragma unroll
    for (int mt = 0; mt < 2; mt++) {
        int r = row0 + warpM * 32 + mt * 16 + g;
#pragma unroll
        for (int nt = 0; nt < 8; nt++) {
            int c = col0 + warpN * 64 + nt * 8 + 2 * tg;
            float2 v0 = make_float2(acc[mt][nt][0], acc[mt][nt][1]);
            float2 v1 = make_float2(acc[mt][nt][2], acc[mt][nt][3]);
            if (round_out) {
                v0.x = to_tf32(v0.x); v0.y = to_tf32(v0.y);
                v1.x = to_tf32(v1.x); v1.y = to_tf32(v1.y);
            }
            *(float2*)&C[(size_t)r * N + c]       = v0;
            *(float2*)&C[(size_t)(r + 8) * N + c] = v1;
        }
    }
}

// ---------------- RoPE (in-place; K output tf32-rounded) ----------------
__global__ void rope_kernel(float* __restrict__ Q, float* __restrict__ K) {
    int idx = blockIdx.x * blockDim.x + threadIdx.x;
    int j = idx & 63;
    int h = (idx >> 6) & (NH - 1);
    int t = idx >> 10;

    float expo   = (float)(2 * j) * (1.0f / 128.0f);
    float invfrq = expf(-expo * 9.210340371976184f);
    float ang    = (float)t * invfrq;
    float sv, cv;
    sincosf(ang, &sv, &cv);

    int base = t * HID + h * HD + j;
    float q1 = Q[base], q2 = Q[base + 64];
    Q[base]      = q1 * cv - q2 * sv;
    Q[base + 64] = q2 * cv + q1 * sv;
    float k1 = K[base], k2 = K[base + 64];
    K[base]      = to_tf32(k1 * cv - k2 * sv);
    K[base + 64] = to_tf32(k2 * cv + k1 * sv);
}

// ---------------- Flash attention: ldmatrix Q/K/P + swizzled Q/K tiles ----------------
// Q/K tiles: 64 rows x 128 floats (512 B/row), SW128 swizzle chunk' = chunk ^ (row&7).
#define QKROWB 512                 // bytes per Q/K smem row
#define QK_TILE_FLOATS (64 * 128)  // 8192
#define VLD 136
#define SLD 68

#define FM_SMEM_FLOATS (QK_TILE_FLOATS + 2*QK_TILE_FLOATS + 2*64*VLD + 64*SLD + 128)
#define FM_SMEM_BYTES  (FM_SMEM_FLOATS * 4)

__global__ __launch_bounds__(256, 1) void flash_mma_kernel(const float* __restrict__ Q,
                                                           const float* __restrict__ K,
                                                           const float* __restrict__ V) {
    extern __shared__ float sm[];
    float* Qs = sm;                          // 64 x 128 swizzled
    float* Ks = Qs + QK_TILE_FLOATS;         // 2 stages x 64 x 128 swizzled
    float* Vs = Ks + 2 * QK_TILE_FLOATS;     // 2 stages x 64 x VLD (linear)
    float* Ss = Vs + 2 * 64 * VLD;           // 64 x SLD
    float* ra = Ss + 64 * SLD;
    float* rl = ra + 64;

    const int qb = gridDim.x - 1 - blockIdx.x;
    const int h  = blockIdx.y;
    const int tid  = threadIdx.x;
    const int lane = tid & 31, warp = tid >> 5;
    const int g = lane >> 2, tg = lane & 3;
    const int wm = warp >> 1, wn = warp & 1;
    const int m0 = wm * 16;
    const int qrow0 = qb * 64;
    const float scale = 0.08838834764831845f * 1.4426950408889634f;

    const int srow = tid >> 2, part = tid & 3;

    // ldmatrix lane bases (same derivation as the verified GEMM)
    const int l8 = lane & 7;
    const int a_m  = m0 + l8 + (((lane >> 3) & 1) << 3);
    const int a_cs = (lane >> 4) & 1;
    const int b_n  = wn * 32 + l8 + (((lane >> 4) & 1) << 3);
    const int b_cs = (lane >> 3) & 1;

    const u32 qsmB = (u32)__cvta_generic_to_shared(Qs);
    const u32 ksmB = (u32)__cvta_generic_to_shared(Ks);
    const u32 vsmB = (u32)__cvta_generic_to_shared(Vs);
    const u32 ssmB = (u32)__cvta_generic_to_shared(Ss);

    // Q tile: scale + tf32-round, store swizzled
    for (int i = tid; i < 64 * 32; i += 256) {
        int r = i >> 5, cc = i & 31;                      // cc = 16B chunk
        float4 v = *(const float4*)&Q[(size_t)(qrow0 + r) * HID + h * HD + cc * 4];
        v.x = to_tf32(v.x * scale); v.y = to_tf32(v.y * scale);
        v.z = to_tf32(v.z * scale); v.w = to_tf32(v.w * scale);
        *(float4*)((char*)Qs + r * QKROWB + ((cc ^ (r & 7)) << 4)) = v;
    }

    // prefetch kb=0 into stage 0 (K swizzled, V linear)
#pragma unroll
    for (int t = 0; t < 8; t++) {
        int i = tid + t * 256;
        int r = i >> 5, cc = i & 31;
        cp_async16(ksmB + (u32)(r * QKROWB + ((cc ^ (r & 7)) << 4)),
                   &K[(size_t)r * HID + h * HD + cc * 4]);
        cp_async16(vsmB + (u32)((r * VLD + cc * 4) << 2),
                   &V[(size_t)r * HID + h * HD + cc * 4]);
    }
    cp_commit();

    float oac[8][4];
#pragma unroll
    for (int nt = 0; nt < 8; nt++)
#pragma unroll
        for (int r = 0; r < 4; r++) oac[nt][r] = 0.f;
    float m_i = -1e30f, l_i = 0.f;

    for (int kb = 0; kb <= qb; kb++) {
        int st = kb & 1;
        cp_wait0();
        __syncthreads();

        if (kb < qb) {
            int krow0 = (kb + 1) * 64;
            u32 ko = ksmB + (u32)((st ^ 1) * QK_TILE_FLOATS * 4);
            u32 vo = vsmB + (u32)((st ^ 1) * 64 * VLD * 4);
#pragma unroll
            for (int t = 0; t < 8; t++) {
                int i = tid + t * 256;
                int r = i >> 5, cc = i & 31;
                cp_async16(ko + (u32)(r * QKROWB + ((cc ^ (r & 7)) << 4)),
                           &K[(size_t)(krow0 + r) * HID + h * HD + cc * 4]);
                cp_async16(vo + (u32)((r * VLD + cc * 4) << 2),
                           &V[(size_t)(krow0 + r) * HID + h * HD + cc * 4]);
            }
            cp_commit();
        }

        const u32 kStage = ksmB + (u32)(st * QK_TILE_FLOATS * 4);
        const float* vs = Vs + st * 64 * VLD;

        // ---- S = Q @ K^T : ldmatrix frags, double-buffered over 16 k8-groups ----
        float sac[4][4];
#pragma unroll
        for (int nt = 0; nt < 4; nt++)
#pragma unroll
            for (int r = 0; r < 4; r++) sac[nt][r] = 0.f;

        {
            u32 qa[2][4], kf[2][4][2];
            ldsm4(qa[0][0], qa[0][1], qa[0][2], qa[0][3],
                  qsmB + (u32)(a_m * QKROWB + ((a_cs ^ l8) << 4)));
#pragma unroll
            for (int p = 0; p < 2; p++)
                ldsm4(kf[0][2 * p][0], kf[0][2 * p][1], kf[0][2 * p + 1][0], kf[0][2 * p + 1][1],
                      kStage + (u32)((b_n + p * 16) * QKROWB + ((b_cs ^ l8) << 4)));
#pragma unroll
            for (int kk = 0; kk < 16; kk++) {
                const int cur = kk & 1, nxt = cur ^ 1;
                if (kk < 15) {
                    const int c = 2 * (kk + 1);
                    ldsm4(qa[nxt][0], qa[nxt][1], qa[nxt][2], qa[nxt][3],
                          qsmB + (u32)(a_m * QKROWB + (((c + a_cs) ^ l8) << 4)));
#pragma unroll
                    for (int p = 0; p < 2; p++)
                        ldsm4(kf[nxt][2 * p][0], kf[nxt][2 * p][1], kf[nxt][2 * p + 1][0], kf[nxt][2 * p + 1][1],
                              kStage + (u32)((b_n + p * 16) * QKROWB + (((c + b_cs) ^ l8) << 4)));
                }
#pragma unroll
                for (int nt = 0; nt < 4; nt++)
                    mma_tf32(sac[nt], qa[cur], kf[cur][nt]);
            }
        }

        // ---- causal mask + store S ----
        const bool diag = (kb == qb);
#pragma unroll
        for (int nt = 0; nt < 4; nt++) {
            int col = wn * 32 + nt * 8 + 2 * tg;
            int r0 = m0 + g, r1 = m0 + g + 8;
            float c0 = sac[nt][0], c1 = sac[nt][1], c2 = sac[nt][2], c3 = sac[nt][3];
            if (diag) {
                if (col     > r0) c0 = -1e30f;
                if (col + 1 > r0) c1 = -1e30f;
                if (col     > r1) c2 = -1e30f;
                if (col + 1 > r1) c3 = -1e30f;
            }
            Ss[r0 * SLD + col]     = c0;
            Ss[r0 * SLD + col + 1] = c1;
            Ss[r1 * SLD + col]     = c2;
            Ss[r1 * SLD + col + 1] = c3;
        }
        __syncthreads();

        // ---- online softmax (base-2) ----
        {
            float* srow_p = Ss + srow * SLD + part * 16;
            float4 p0 = *(float4*)(srow_p + 0);
            float4 p1 = *(float4*)(srow_p + 4);
            float4 p2 = *(float4*)(srow_p + 8);
            float4 p3 = *(float4*)(srow_p + 12);
            float mx = fmaxf(fmaxf(fmaxf(p0.x, p0.y), fmaxf(p0.z, p0.w)),
                             fmaxf(fmaxf(p1.x, p1.y), fmaxf(p1.z, p1.w)));
            mx = fmaxf(mx, fmaxf(fmaxf(fmaxf(p2.x, p2.y), fmaxf(p2.z, p2.w)),
                                 fmaxf(fmaxf(p3.x, p3.y), fmaxf(p3.z, p3.w))));
            mx = fmaxf(mx, __shfl_xor_sync(0xffffffffu, mx, 1));
            mx = fmaxf(mx, __shfl_xor_sync(0xffffffffu, mx, 2));
            float mnew = fmaxf(m_i, mx);
            float alpha = fexp2(m_i - mnew);
            p0.x = fexp2(p0.x - mnew); p0.y = fexp2(p0.y - mnew);
            p0.z = fexp2(p0.z - mnew); p0.w = fexp2(p0.w - mnew);
            p1.x = fexp2(p1.x - mnew); p1.y = fexp2(p1.y - mnew);
            p1.z = fexp2(p1.z - mnew); p1.w = fexp2(p1.w - mnew);
            p2.x = fexp2(p2.x - mnew); p2.y = fexp2(p2.y - mnew);
            p2.z = fexp2(p2.z - mnew); p2.w = fexp2(p2.w - mnew);
            p3.x = fexp2(p3.x - mnew); p3.y = fexp2(p3.y - mnew);
            p3.z = fexp2(p3.z - mnew); p3.w = fexp2(p3.w - mnew);
            float s = (((p0.x + p0.y) + (p0.z + p0.w)) + ((p1.x + p1.y) + (p1.z + p1.w)))
                    + (((p2.x + p2.y) + (p2.z + p2.w)) + ((p3.x + p3.y) + (p3.z + p3.w)));
            p0.x = to_tf32(p0.x); p0.y = to_tf32(p0.y); p0.z = to_tf32(p0.z); p0.w = to_tf32(p0.w);
            p1.x = to_tf32(p1.x); p1.y = to_tf32(p1.y); p1.z = to_tf32(p1.z); p1.w = to_tf32(p1.w);
            p2.x = to_tf32(p2.x); p2.y = to_tf32(p2.y); p2.z = to_tf32(p2.z); p2.w = to_tf32(p2.w);
            p3.x = to_tf32(p3.x); p3.y = to_tf32(p3.y); p3.z = to_tf32(p3.z); p3.w = to_tf32(p3.w);
            *(float4*)(srow_p + 0)  = p0;
            *(float4*)(srow_p + 4)  = p1;
            *(float4*)(srow_p + 8)  = p2;
            *(float4*)(srow_p + 12) = p3;
            s += __shfl_xor_sync(0xffffffffu, s, 1);
            s += __shfl_xor_sync(0xffffffffu, s, 2);
            l_i = l_i * alpha + s;
            m_i = mnew;
            if (part == 0) ra[srow] = alpha;
        }
        __syncthreads();

        // ---- O = O*alpha + P @ V : P via ldmatrix from Ss, V scalar ----
        float a0 = ra[m0 + g], a1 = ra[m0 + g + 8];
#pragma unroll
        for (int nt = 0; nt < 8; nt++) {
            oac[nt][0] *= a0; oac[nt][1] *= a0;
            oac[nt][2] *= a1; oac[nt][3] *= a1;
        }
        {
            u32 pa[2][4], vf[2][8][2];
            // Ss stride 68 floats: banks 4*(row%8)+4*chunk distinct per 8-row matrix
            ldsm4(pa[0][0], pa[0][1], pa[0][2], pa[0][3],
                  ssmB + (u32)((a_m * SLD + a_cs * 4) << 2));
#pragma unroll
            for (int nt = 0; nt < 8; nt++) {
                int n0 = wn * 64 + nt * 8;
                vf[0][nt][0] = __float_as_uint(vs[tg * VLD + n0 + g]);
                vf[0][nt][1] = __float_as_uint(vs[(tg + 4) * VLD + n0 + g]);
            }
#pragma unroll
            for (int kk = 0; kk < 8; kk++) {
                const int cur = kk & 1, nxt = cur ^ 1;
                if (kk < 7) {
                    const int k0 = (kk + 1) * 8;   // float-column offset into Ss
                    ldsm4(pa[nxt][0], pa[nxt][1], pa[nxt][2], pa[nxt][3],
                          ssmB + (u32)((a_m * SLD + k0 + a_cs * 4) << 2));
#pragma unroll
                    for (int nt = 0; nt < 8; nt++) {
                        int n0 = wn * 64 + nt * 8;
                        vf[nxt][nt][0] = __float_as_uint(vs[(k0 + tg) * VLD + n0 + g]);
                        vf[nxt][nt][1] = __float_as_uint(vs[(k0 + tg + 4) * VLD + n0 + g]);
                    }
                }
#pragma unroll
                for (int nt = 0; nt < 8; nt++)
                    mma_tf32(oac[nt], pa[cur], vf[cur][nt]);
            }
        }
    }

    if (part == 0) rl[srow] = l_i;
    __syncthreads();

    float inv0 = 1.0f / rl[m0 + g];
    float inv1 = 1.0f / rl[m0 + g + 8];
#pragma unroll
    for (int nt = 0; nt < 8; nt++) {
        int col = wn * 64 + nt * 8 + 2 * tg;
        int r0 = qrow0 + m0 + g, r1 = r0 + 8;
        float2 w0 = make_float2(to_tf32(oac[nt][0] * inv0), to_tf32(oac[nt][1] * inv0));
        float2 w1 = make_float2(to_tf32(oac[nt][2] * inv1), to_tf32(oac[nt][3] * inv1));
        *(float2*)&g_AO[(size_t)r0 * HID + h * HD + col] = w0;
        *(float2*)&g_AO[(size_t)r1 * HID + h * HD + col] = w1;
    }
}

// ---------------- launch ----------------
extern "C" void kernel_launch(void* const* d_in, const int* in_sizes, int n_in,
                              void* d_out, int out_size) {
    const float* X  = (const float*)d_in[0];
    const float* wq = (const float*)d_in[1];
    const float* wk = (const float*)d_in[2];
    const float* wv = (const float*)d_in[3];
    const float* wo = (const float*)d_in[4];
    float* out = (float*)d_out;

    float *Q, *K, *V, *AO, *Xt, *Wq, *Wk, *Wv, *Wo;
    cudaGetSymbolAddress((void**)&Q,  g_Q);
    cudaGetSymbolAddress((void**)&K,  g_K);
    cudaGetSymbolAddress((void**)&V,  g_V);
    cudaGetSymbolAddress((void**)&AO, g_AO);
    cudaGetSymbolAddress((void**)&Xt, g_Xt);
    cudaGetSymbolAddress((void**)&Wq, g_Wq);
    cudaGetSymbolAddress((void**)&Wk, g_Wk);
    cudaGetSymbolAddress((void**)&Wv, g_Wv);
    cudaGetSymbolAddress((void**)&Wo, g_Wo);

    cudaFuncSetAttribute(tf32_gemm_ldsm<true>, cudaFuncAttributeMaxDynamicSharedMemorySize,
                         GEMM_SMEM_BYTES);
    cudaFuncSetAttribute(tf32_gemm_ldsm<false>, cudaFuncAttributeMaxDynamicSharedMemorySize,
                         GEMM_SMEM_BYTES);
    cudaFuncSetAttribute(flash_mma_kernel, cudaFuncAttributeMaxDynamicSharedMemorySize,
                         FM_SMEM_BYTES);

    cvt_x_kernel<<<HID * HID / (256 * 4), 256>>>(X, Xt);
    cvt_trans_kernel<<<dim3(64, 64, 4), dim3(32, 8)>>>(wq, Wq, wk, Wk, wv, Wv, wo, Wo);

    tf32_gemm_ldsm<true><<<dim3(16, 16, 3), 256, GEMM_SMEM_BYTES>>>(
        Xt, Wq, Wk, Wv, Q, K, V);

    rope_kernel<<<(S_LEN * NH * 64) / 256, 256>>>(Q, K);

    flash_mma_kernel<<<dim3(S_LEN / 64, NH), 256, FM_SMEM_BYTES>>>(Q, K, V);

    tf32_gemm_ldsm<false><<<dim3(16, 16, 1), 256, GEMM_SMEM_BYTES>>>(
        AO, Wo, Wo, Wo, out, out, out);

    (void)in_sizes; (void)n_in; (void)out_size;
}

// round 13
// speedup vs baseline: 4.6304x; 1.0390x over previous
#include <cuda_runtime.h>
#include <cuda_bf16.h>
#include <cstdint>
#include <math.h>

typedef unsigned int u32;

// Problem constants: B=1, S=2048, HIDDEN=2048, NUM_HEADS=16, MLA_DIM=HEAD_DIM=128
#define S_LEN 2048
#define HID   2048
#define NH    16
#define HD    128

// ---------------- scratch ----------------
__device__ float g_Q[S_LEN * HID];
__device__ float g_K[S_LEN * HID];
__device__ float g_V[S_LEN * HID];
__device__ float g_AO[S_LEN * HID];
__device__ float g_Xt[S_LEN * HID];
__device__ float g_Wq[HID * HID];   // transposed [N][K], tf32-rounded
__device__ float g_Wk[HID * HID];
__device__ float g_Wv[HID * HID];
__device__ float g_Wo[HID * HID];

__device__ __forceinline__ float to_tf32(float x) {
    float r;
    asm("cvt.rna.tf32.f32 %0, %1;" : "=f"(r) : "f"(x));
    return r;
}

// fast exp2 for t <= 0: FMA/ALU pipes only. deg-6 Taylor, max rel err ~1.5e-5.
__device__ __forceinline__ float fexp2(float t) {
    t = fmaxf(t, -126.0f);
    float n = floorf(t);
    float f = t - n;
    float p = 1.5403530393381608e-4f;
    p = fmaf(p, f, 1.3333558146428443e-3f);
    p = fmaf(p, f, 9.6181291076284770e-3f);
    p = fmaf(p, f, 5.5504108664821580e-2f);
    p = fmaf(p, f, 2.4022650695910071e-1f);
    p = fmaf(p, f, 6.9314718055994531e-1f);
    p = fmaf(p, f, 1.0f);
    int e = (int)n;
    return p * __int_as_float((e + 127) << 23);
}

__device__ __forceinline__ void cp_async16(u32 dst, const void* src) {
    asm volatile("cp.async.cg.shared.global [%0], [%1], 16;" :: "r"(dst), "l"(src));
}
__device__ __forceinline__ void cp_commit() { asm volatile("cp.async.commit_group;"); }
__device__ __forceinline__ void cp_wait1()  { asm volatile("cp.async.wait_group 1;"); }
__device__ __forceinline__ void cp_wait0()  { asm volatile("cp.async.wait_group 0;"); }

__device__ __forceinline__ void bar_pair(int id) {
    asm volatile("bar.sync %0, 64;" :: "r"(id) : "memory");
}

__device__ __forceinline__ void mma_tf32(float* d, const u32* a, const u32* b) {
    asm volatile(
        "mma.sync.aligned.m16n8k8.row.col.f32.tf32.tf32.f32 "
        "{%0,%1,%2,%3}, {%4,%5,%6,%7}, {%8,%9}, {%0,%1,%2,%3};"
        : "+f"(d[0]), "+f"(d[1]), "+f"(d[2]), "+f"(d[3])
        : "r"(a[0]), "r"(a[1]), "r"(a[2]), "r"(a[3]), "r"(b[0]), "r"(b[1]));
}

__device__ __forceinline__ void ldsm4(u32& r0, u32& r1, u32& r2, u32& r3, u32 addr) {
    asm volatile("ldmatrix.sync.aligned.m8n8.x4.shared.b16 {%0,%1,%2,%3}, [%4];"
                 : "=r"(r0), "=r"(r1), "=r"(r2), "=r"(r3) : "r"(addr));
}

// ---------------- merged prepass: z=0 rounds X; z=1..4 transpose+round weights ----------------
__global__ void prepass_kernel(const float* __restrict__ x, float* __restrict__ xo,
                               const float* __restrict__ s0, float* __restrict__ d0,
                               const float* __restrict__ s1, float* __restrict__ d1,
                               const float* __restrict__ s2, float* __restrict__ d2,
                               const float* __restrict__ s3, float* __restrict__ d3) {
    if (blockIdx.z == 0) {
        // plain round: 32x32 tile, 32x8 threads, 4 rows each
        int xcol = blockIdx.x * 32 + threadIdx.x;
        int yrow = blockIdx.y * 32 + threadIdx.y;
#pragma unroll
        for (int i = 0; i < 4; i++) {
            size_t idx = (size_t)(yrow + i * 8) * HID + xcol;
            xo[idx] = to_tf32(x[idx]);
        }
        return;
    }
    const float* in;
    float* out;
    switch (blockIdx.z) {
        case 1: in = s0; out = d0; break;
        case 2: in = s1; out = d1; break;
        case 3: in = s2; out = d2; break;
        default: in = s3; out = d3; break;
    }
    __shared__ float ts[32][33];
    int x0 = blockIdx.x * 32 + threadIdx.x;
    int y0 = blockIdx.y * 32 + threadIdx.y;
#pragma unroll
    for (int i = 0; i < 4; i++)
        ts[threadIdx.y + i * 8][threadIdx.x] = in[(size_t)(y0 + i * 8) * HID + x0];
    __syncthreads();
    int x2 = blockIdx.y * 32 + threadIdx.x;
    int y2 = blockIdx.x * 32 + threadIdx.y;
#pragma unroll
    for (int i = 0; i < 4; i++)
        out[(size_t)(y2 + i * 8) * HID + x2] = to_tf32(ts[threadIdx.x][threadIdx.y + i * 8]);
}

// ---------------- TF32 GEMM with ldmatrix + swizzled smem (R11, proven) ----------------
#define TBM 128
#define TBN 128
#define TBK 32
#define TSZ 4096
#define GEMM_SMEM_BYTES (3 * 2 * TSZ * 4)
#define NKIT (HID / TBK)

template <bool ROUND_Z2>
__global__ __launch_bounds__(256, 2) void tf32_gemm_ldsm(
    const float* __restrict__ A,
    const float* __restrict__ B0, const float* __restrict__ B1, const float* __restrict__ B2,
    float* __restrict__ C0, float* __restrict__ C1, float* __restrict__ C2) {
    const float* B = (blockIdx.z == 0) ? B0 : ((blockIdx.z == 1) ? B1 : B2);
    float* C       = (blockIdx.z == 0) ? C0 : ((blockIdx.z == 1) ? C1 : C2);
    const bool round_out = ROUND_Z2 && (blockIdx.z == 2);

    const int K = HID, N = HID;
    extern __shared__ float gsm[];
    float* As = gsm;
    float* Bs = gsm + 3 * TSZ;

    const int tid  = threadIdx.x;
    const int lane = tid & 31;
    const int warp = tid >> 5;
    const int warpM = warp >> 1;
    const int warpN = warp & 1;
    const int g  = lane >> 2;
    const int tg = lane & 3;

    const int row0 = blockIdx.y * TBM;
    const int col0 = blockIdx.x * TBN;

    const int r_ld = tid >> 3, c_ld = tid & 7;
    const float* gA = A + (size_t)(row0 + r_ld) * K + c_ld * 4;
    const float* gB = B + (size_t)(col0 + r_ld) * K + c_ld * 4;
    const u32 smA = (u32)__cvta_generic_to_shared(As);
    const u32 smB = (u32)__cvta_generic_to_shared(Bs);
    const u32 dOff = (u32)((r_ld * 8 + (c_ld ^ (r_ld & 7))) << 4);

    const int l8 = lane & 7;
    const int a_m  = warpM * 32 + l8 + (((lane >> 3) & 1) << 3);
    const int a_cs = (lane >> 4) & 1;
    const int b_n  = warpN * 64 + l8 + (((lane >> 4) & 1) << 3);
    const int b_cs = (lane >> 3) & 1;

    float acc[2][8][4];
#pragma unroll
    for (int mt = 0; mt < 2; mt++)
#pragma unroll
        for (int nt = 0; nt < 8; nt++)
#pragma unroll
            for (int r = 0; r < 4; r++) acc[mt][nt][r] = 0.f;

#pragma unroll
    for (int p = 0; p < 2; p++) {
        int kk = p * TBK;
        u32 ad = smA + (u32)(p * TSZ * 4) + dOff;
        u32 bd = smB + (u32)(p * TSZ * 4) + dOff;
#pragma unroll
        for (int q = 0; q < 4; q++) {
            cp_async16(ad + (u32)(q * 4096), gA + kk + (size_t)(q * 32) * K);
            cp_async16(bd + (u32)(q * 4096), gB + kk + (size_t)(q * 32) * K);
        }
        cp_commit();
    }

    int st = 0, ld = 2;
    for (int kb = 0; kb < NKIT; kb++) {
        if (kb == NKIT - 1) cp_wait0(); else cp_wait1();
        __syncthreads();

        if (kb + 2 < NKIT) {
            int kk = (kb + 2) * TBK;
            u32 ad = smA + (u32)(ld * TSZ * 4) + dOff;
            u32 bd = smB + (u32)(ld * TSZ * 4) + dOff;
#pragma unroll
            for (int q = 0; q < 4; q++) {
                cp_async16(ad + (u32)(q * 4096), gA + kk + (size_t)(q * 32) * K);
                cp_async16(bd + (u32)(q * 4096), gB + kk + (size_t)(q * 32) * K);
            }
            cp_commit();
        }

        const u32 aStage = smA + (u32)(st * TSZ * 4);
        const u32 bStage = smB + (u32)(st * TSZ * 4);

        u32 af[2][2][4];
        u32 bf[2][8][2];

#pragma unroll
        for (int mt = 0; mt < 2; mt++)
            ldsm4(af[0][mt][0], af[0][mt][1], af[0][mt][2], af[0][mt][3],
                  aStage + (u32)((a_m + mt * 16) * 128 + ((a_cs ^ l8) << 4)));
#pragma unroll
        for (int p = 0; p < 4; p++)
            ldsm4(bf[0][2 * p][0], bf[0][2 * p][1], bf[0][2 * p + 1][0], bf[0][2 * p + 1][1],
                  bStage + (u32)((b_n + p * 16) * 128 + ((b_cs ^ l8) << 4)));

#pragma unroll
        for (int kg = 0; kg < 4; kg++) {
            const int cur = kg & 1, nxt = cur ^ 1;
            if (kg < 3) {
                const int c = 2 * (kg + 1);
#pragma unroll
                for (int mt = 0; mt < 2; mt++)
                    ldsm4(af[nxt][mt][0], af[nxt][mt][1], af[nxt][mt][2], af[nxt][mt][3],
                          aStage + (u32)((a_m + mt * 16) * 128 + (((c + a_cs) ^ l8) << 4)));
#pragma unroll
                for (int p = 0; p < 4; p++)
                    ldsm4(bf[nxt][2 * p][0], bf[nxt][2 * p][1], bf[nxt][2 * p + 1][0], bf[nxt][2 * p + 1][1],
                          bStage + (u32)((b_n + p * 16) * 128 + (((c + b_cs) ^ l8) << 4)));
            }
#pragma unroll
            for (int mt = 0; mt < 2; mt++)
#pragma unroll
                for (int nt = 0; nt < 8; nt++)
                    mma_tf32(acc[mt][nt], af[cur][mt], bf[cur][nt]);
        }

        st = (st == 2) ? 0 : st + 1;
        ld = (ld == 2) ? 0 : ld + 1;
    }

#pragma unroll
    for (int mt = 0; mt < 2; mt++) {
        int r = row0 + warpM * 32 + mt * 16 + g;
#pragma unroll
        for (int nt = 0; nt < 8; nt++) {
            int c = col0 + warpN * 64 + nt * 8 + 2 * tg;
            float2 v0 = make_float2(acc[mt][nt][0], acc[mt][nt][1]);
            float2 v1 = make_float2(acc[mt][nt][2], acc[mt][nt][3]);
            if (round_out) {
                v0.x = to_tf32(v0.x); v0.y = to_tf32(v0.y);
                v1.x = to_tf32(v1.x); v1.y = to_tf32(v1.y);
            }
            *(float2*)&C[(size_t)r * N + c]       = v0;
            *(float2*)&C[(size_t)(r + 8) * N + c] = v1;
        }
    }
}

// ---------------- RoPE (in-place; K output tf32-rounded) ----------------
__global__ void rope_kernel(float* __restrict__ Q, float* __restrict__ K) {
    int idx = blockIdx.x * blockDim.x + threadIdx.x;
    int j = idx & 63;
    int h = (idx >> 6) & (NH - 1);
    int t = idx >> 10;

    float expo   = (float)(2 * j) * (1.0f / 128.0f);
    float invfrq = expf(-expo * 9.210340371976184f);
    float ang    = (float)t * invfrq;
    float sv, cv;
    sincosf(ang, &sv, &cv);

    int base = t * HID + h * HD + j;
    float q1 = Q[base], q2 = Q[base + 64];
    Q[base]      = q1 * cv - q2 * sv;
    Q[base + 64] = q2 * cv + q1 * sv;
    float k1 = K[base], k2 = K[base + 64];
    K[base]      = to_tf32(k1 * cv - k2 * sv);
    K[base + 64] = to_tf32(k2 * cv + k1 * sv);
}

// ---------------- Flash attention: register softmax + pair barriers ----------------
#define QKROWB 512                 // bytes per Q/K smem row
#define QK_TILE_FLOATS (64 * 128)  // 8192
#define VLD 136
#define SLD 68

#define FM_SMEM_FLOATS (QK_TILE_FLOATS + 2*QK_TILE_FLOATS + 2*64*VLD + 64*SLD + 256)
#define FM_SMEM_BYTES  (FM_SMEM_FLOATS * 4)

__global__ __launch_bounds__(256, 1) void flash_mma_kernel(const float* __restrict__ Q,
                                                           const float* __restrict__ K,
                                                           const float* __restrict__ V) {
    extern __shared__ float sm[];
    float* Qs   = sm;                          // 64 x 128 swizzled
    float* Ks   = Qs + QK_TILE_FLOATS;         // 2 stages x 64 x 128 swizzled
    float* Vs   = Ks + 2 * QK_TILE_FLOATS;     // 2 stages x 64 x VLD (linear)
    float* Ss   = Vs + 2 * 64 * VLD;           // 64 x SLD (holds P)
    float* rmax = Ss + 64 * SLD;               // [2][64]
    float* rsum = rmax + 128;                  // [2][64]

    const int qb = gridDim.x - 1 - blockIdx.x;
    const int h  = blockIdx.y;
    const int tid  = threadIdx.x;
    const int lane = tid & 31, warp = tid >> 5;
    const int g = lane >> 2, tg = lane & 3;
    const int wm = warp >> 1, wn = warp & 1;
    const int m0 = wm * 16;
    const int qrow0 = qb * 64;
    const float scale = 0.08838834764831845f * 1.4426950408889634f;
    const int barid = 1 + wm;                   // pair barrier id per wm group
    const int r0 = m0 + g, r1 = m0 + g + 8;     // this thread's accumulator rows

    const int l8 = lane & 7;
    const int a_m  = m0 + l8 + (((lane >> 3) & 1) << 3);
    const int a_cs = (lane >> 4) & 1;
    const int b_n  = wn * 32 + l8 + (((lane >> 4) & 1) << 3);
    const int b_cs = (lane >> 3) & 1;

    const u32 qsmB = (u32)__cvta_generic_to_shared(Qs);
    const u32 ksmB = (u32)__cvta_generic_to_shared(Ks);
    const u32 vsmB = (u32)__cvta_generic_to_shared(Vs);
    const u32 ssmB = (u32)__cvta_generic_to_shared(Ss);

    for (int i = tid; i < 64 * 32; i += 256) {
        int r = i >> 5, cc = i & 31;
        float4 v = *(const float4*)&Q[(size_t)(qrow0 + r) * HID + h * HD + cc * 4];
        v.x = to_tf32(v.x * scale); v.y = to_tf32(v.y * scale);
        v.z = to_tf32(v.z * scale); v.w = to_tf32(v.w * scale);
        *(float4*)((char*)Qs + r * QKROWB + ((cc ^ (r & 7)) << 4)) = v;
    }

#pragma unroll
    for (int t = 0; t < 8; t++) {
        int i = tid + t * 256;
        int r = i >> 5, cc = i & 31;
        cp_async16(ksmB + (u32)(r * QKROWB + ((cc ^ (r & 7)) << 4)),
                   &K[(size_t)r * HID + h * HD + cc * 4]);
        cp_async16(vsmB + (u32)((r * VLD + cc * 4) << 2),
                   &V[(size_t)r * HID + h * HD + cc * 4]);
    }
    cp_commit();

    float oac[8][4];
#pragma unroll
    for (int nt = 0; nt < 8; nt++)
#pragma unroll
        for (int r = 0; r < 4; r++) oac[nt][r] = 0.f;
    float m_i0 = -1e30f, m_i1 = -1e30f, l_i0 = 0.f, l_i1 = 0.f;

    for (int kb = 0; kb <= qb; kb++) {
        int st = kb & 1;
        cp_wait0();
        __syncthreads();   // stage st ready; all warps done with prior PV (P smem reuse)

        if (kb < qb) {
            int krow0 = (kb + 1) * 64;
            u32 ko = ksmB + (u32)((st ^ 1) * QK_TILE_FLOATS * 4);
            u32 vo = vsmB + (u32)((st ^ 1) * 64 * VLD * 4);
#pragma unroll
            for (int t = 0; t < 8; t++) {
                int i = tid + t * 256;
                int r = i >> 5, cc = i & 31;
                cp_async16(ko + (u32)(r * QKROWB + ((cc ^ (r & 7)) << 4)),
                           &K[(size_t)(krow0 + r) * HID + h * HD + cc * 4]);
                cp_async16(vo + (u32)((r * VLD + cc * 4) << 2),
                           &V[(size_t)(krow0 + r) * HID + h * HD + cc * 4]);
            }
            cp_commit();
        }

        const u32 kStage = ksmB + (u32)(st * QK_TILE_FLOATS * 4);
        const float* vs = Vs + st * 64 * VLD;

        // ---- S = Q @ K^T (regs) ----
        float sac[4][4];
#pragma unroll
        for (int nt = 0; nt < 4; nt++)
#pragma unroll
            for (int r = 0; r < 4; r++) sac[nt][r] = 0.f;

        {
            u32 qa[2][4], kf[2][4][2];
            ldsm4(qa[0][0], qa[0][1], qa[0][2], qa[0][3],
                  qsmB + (u32)(a_m * QKROWB + ((a_cs ^ l8) << 4)));
#pragma unroll
            for (int p = 0; p < 2; p++)
                ldsm4(kf[0][2 * p][0], kf[0][2 * p][1], kf[0][2 * p + 1][0], kf[0][2 * p + 1][1],
                      kStage + (u32)((b_n + p * 16) * QKROWB + ((b_cs ^ l8) << 4)));
#pragma unroll
            for (int kk = 0; kk < 16; kk++) {
                const int cur = kk & 1, nxt = cur ^ 1;
                if (kk < 15) {
                    const int c = 2 * (kk + 1);
                    ldsm4(qa[nxt][0], qa[nxt][1], qa[nxt][2], qa[nxt][3],
                          qsmB + (u32)(a_m * QKROWB + (((c + a_cs) ^ l8) << 4)));
#pragma unroll
                    for (int p = 0; p < 2; p++)
                        ldsm4(kf[nxt][2 * p][0], kf[nxt][2 * p][1], kf[nxt][2 * p + 1][0], kf[nxt][2 * p + 1][1],
                              kStage + (u32)((b_n + p * 16) * QKROWB + (((c + b_cs) ^ l8) << 4)));
                }
#pragma unroll
                for (int nt = 0; nt < 4; nt++)
                    mma_tf32(sac[nt], qa[cur], kf[cur][nt]);
            }
        }

        // ---- causal mask (regs) ----
        if (kb == qb) {
#pragma unroll
            for (int nt = 0; nt < 4; nt++) {
                int col = wn * 32 + nt * 8 + 2 * tg;
                if (col     > r0) sac[nt][0] = -1e30f;
                if (col + 1 > r0) sac[nt][1] = -1e30f;
                if (col     > r1) sac[nt][2] = -1e30f;
                if (col + 1 > r1) sac[nt][3] = -1e30f;
            }
        }

        // ---- softmax step 1: warp-half row max -> pair exchange ----
        float mx0 = -1e30f, mx1 = -1e30f;
#pragma unroll
        for (int nt = 0; nt < 4; nt++) {
            mx0 = fmaxf(mx0, fmaxf(sac[nt][0], sac[nt][1]));
            mx1 = fmaxf(mx1, fmaxf(sac[nt][2], sac[nt][3]));
        }
        mx0 = fmaxf(mx0, __shfl_xor_sync(0xffffffffu, mx0, 1));
        mx0 = fmaxf(mx0, __shfl_xor_sync(0xffffffffu, mx0, 2));
        mx1 = fmaxf(mx1, __shfl_xor_sync(0xffffffffu, mx1, 1));
        mx1 = fmaxf(mx1, __shfl_xor_sync(0xffffffffu, mx1, 2));
        if (tg == 0) {
            rmax[wn * 64 + r0] = mx0;
            rmax[wn * 64 + r1] = mx1;
        }
        bar_pair(barid);
        float fm0 = fmaxf(rmax[r0], rmax[64 + r0]);
        float fm1 = fmaxf(rmax[r1], rmax[64 + r1]);
        float mnew0 = fmaxf(m_i0, fm0), mnew1 = fmaxf(m_i1, fm1);
        float alpha0 = fexp2(m_i0 - mnew0), alpha1 = fexp2(m_i1 - mnew1);

        // ---- softmax step 2: exp (regs), write P + partial sums ----
        float s0 = 0.f, s1 = 0.f;
#pragma unroll
        for (int nt = 0; nt < 4; nt++) {
            int col = wn * 32 + nt * 8 + 2 * tg;
            float p00 = fexp2(sac[nt][0] - mnew0);
            float p01 = fexp2(sac[nt][1] - mnew0);
            float p10 = fexp2(sac[nt][2] - mnew1);
            float p11 = fexp2(sac[nt][3] - mnew1);
            s0 += p00 + p01;
            s1 += p10 + p11;
            Ss[r0 * SLD + col]     = to_tf32(p00);
            Ss[r0 * SLD + col + 1] = to_tf32(p01);
            Ss[r1 * SLD + col]     = to_tf32(p10);
            Ss[r1 * SLD + col + 1] = to_tf32(p11);
        }
        s0 += __shfl_xor_sync(0xffffffffu, s0, 1);
        s0 += __shfl_xor_sync(0xffffffffu, s0, 2);
        s1 += __shfl_xor_sync(0xffffffffu, s1, 1);
        s1 += __shfl_xor_sync(0xffffffffu, s1, 2);
        if (tg == 0) {
            rsum[wn * 64 + r0] = s0;
            rsum[wn * 64 + r1] = s1;
        }
        bar_pair(barid);
        l_i0 = l_i0 * alpha0 + (rsum[r0] + rsum[64 + r0]);
        l_i1 = l_i1 * alpha1 + (rsum[r1] + rsum[64 + r1]);
        m_i0 = mnew0; m_i1 = mnew1;

        // ---- O = O*alpha + P @ V ----
#pragma unroll
        for (int nt = 0; nt < 8; nt++) {
            oac[nt][0] *= alpha0; oac[nt][1] *= alpha0;
            oac[nt][2] *= alpha1; oac[nt][3] *= alpha1;
        }
        {
            u32 pa[2][4], vf[2][8][2];
            ldsm4(pa[0][0], pa[0][1], pa[0][2], pa[0][3],
                  ssmB + (u32)((a_m * SLD + a_cs * 4) << 2));
#pragma unroll
            for (int nt = 0; nt < 8; nt++) {
                int n0 = wn * 64 + nt * 8;
                vf[0][nt][0] = __float_as_uint(vs[tg * VLD + n0 + g]);
                vf[0][nt][1] = __float_as_uint(vs[(tg + 4) * VLD + n0 + g]);
            }
#pragma unroll
            for (int kk = 0; kk < 8; kk++) {
                const int cur = kk & 1, nxt = cur ^ 1;
                if (kk < 7) {
                    const int k0 = (kk + 1) * 8;
                    ldsm4(pa[nxt][0], pa[nxt][1], pa[nxt][2], pa[nxt][3],
                          ssmB + (u32)((a_m * SLD + k0 + a_cs * 4) << 2));
#pragma unroll
                    for (int nt = 0; nt < 8; nt++) {
                        int n0 = wn * 64 + nt * 8;
                        vf[nxt][nt][0] = __float_as_uint(vs[(k0 + tg) * VLD + n0 + g]);
                        vf[nxt][nt][1] = __float_as_uint(vs[(k0 + tg + 4) * VLD + n0 + g]);
                    }
                }
#pragma unroll
                for (int nt = 0; nt < 8; nt++)
                    mma_tf32(oac[nt], pa[cur], vf[cur][nt]);
            }
        }
    }

    float inv0 = 1.0f / l_i0;
    float inv1 = 1.0f / l_i1;
#pragma unroll
    for (int nt = 0; nt < 8; nt++) {
        int col = wn * 64 + nt * 8 + 2 * tg;
        int gr0 = qrow0 + r0, gr1 = qrow0 + r1;
        float2 w0 = make_float2(to_tf32(oac[nt][0] * inv0), to_tf32(oac[nt][1] * inv0));
        float2 w1 = make_float2(to_tf32(oac[nt][2] * inv1), to_tf32(oac[nt][3] * inv1));
        *(float2*)&g_AO[(size_t)gr0 * HID + h * HD + col] = w0;
        *(float2*)&g_AO[(size_t)gr1 * HID + h * HD + col] = w1;
    }
}

// ---------------- launch ----------------
extern "C" void kernel_launch(void* const* d_in, const int* in_sizes, int n_in,
                              void* d_out, int out_size) {
    const float* X  = (const float*)d_in[0];
    const float* wq = (const float*)d_in[1];
    const float* wk = (const float*)d_in[2];
    const float* wv = (const float*)d_in[3];
    const float* wo = (const float*)d_in[4];
    float* out = (float*)d_out;

    float *Q, *K, *V, *AO, *Xt, *Wq, *Wk, *Wv, *Wo;
    cudaGetSymbolAddress((void**)&Q,  g_Q);
    cudaGetSymbolAddress((void**)&K,  g_K);
    cudaGetSymbolAddress((void**)&V,  g_V);
    cudaGetSymbolAddress((void**)&AO, g_AO);
    cudaGetSymbolAddress((void**)&Xt, g_Xt);
    cudaGetSymbolAddress((void**)&Wq, g_Wq);
    cudaGetSymbolAddress((void**)&Wk, g_Wk);
    cudaGetSymbolAddress((void**)&Wv, g_Wv);
    cudaGetSymbolAddress((void**)&Wo, g_Wo);

    cudaFuncSetAttribute(tf32_gemm_ldsm<true>, cudaFuncAttributeMaxDynamicSharedMemorySize,
                         GEMM_SMEM_BYTES);
    cudaFuncSetAttribute(tf32_gemm_ldsm<false>, cudaFuncAttributeMaxDynamicSharedMemorySize,
                         GEMM_SMEM_BYTES);
    cudaFuncSetAttribute(flash_mma_kernel, cudaFuncAttributeMaxDynamicSharedMemorySize,
                         FM_SMEM_BYTES);

    prepass_kernel<<<dim3(64, 64, 5), dim3(32, 8)>>>(
        X, Xt, wq, Wq, wk, Wk, wv, Wv, wo, Wo);

    tf32_gemm_ldsm<true><<<dim3(16, 16, 3), 256, GEMM_SMEM_BYTES>>>(
        Xt, Wq, Wk, Wv, Q, K, V);

    rope_kernel<<<(S_LEN * NH * 64) / 256, 256>>>(Q, K);

    flash_mma_kernel<<<dim3(S_LEN / 64, NH), 256, FM_SMEM_BYTES>>>(Q, K, V);

    tf32_gemm_ldsm<false><<<dim3(16, 16, 1), 256, GEMM_SMEM_BYTES>>>(
        AO, Wo, Wo, Wo, out, out, out);

    (void)in_sizes; (void)n_in; (void)out_size;
}

// round 14
// speedup vs baseline: 4.7237x; 1.0202x over previous
#include <cuda_runtime.h>
#include <cuda_bf16.h>
#include <cstdint>
#include <math.h>

typedef unsigned int u32;

// Problem constants: B=1, S=2048, HIDDEN=2048, NUM_HEADS=16, MLA_DIM=HEAD_DIM=128
#define S_LEN 2048
#define HID   2048
#define NH    16
#define HD    128

// ---------------- scratch ----------------
__device__ float g_Q[S_LEN * HID];
__device__ float g_K[S_LEN * HID];
__device__ float g_Vt[HID * S_LEN];   // V transposed: [n = h*HD+d][s]
__device__ float g_AO[S_LEN * HID];
__device__ float g_Xt[S_LEN * HID];
__device__ float g_Wq[HID * HID];     // transposed [N][K], tf32-rounded
__device__ float g_Wk[HID * HID];
__device__ float g_Wv[HID * HID];
__device__ float g_Wo[HID * HID];

__device__ __forceinline__ float to_tf32(float x) {
    float r;
    asm("cvt.rna.tf32.f32 %0, %1;" : "=f"(r) : "f"(x));
    return r;
}

// fast exp2 for t <= 0: FMA/ALU pipes only. deg-6 Taylor, max rel err ~1.5e-5.
__device__ __forceinline__ float fexp2(float t) {
    t = fmaxf(t, -126.0f);
    float n = floorf(t);
    float f = t - n;
    float p = 1.5403530393381608e-4f;
    p = fmaf(p, f, 1.3333558146428443e-3f);
    p = fmaf(p, f, 9.6181291076284770e-3f);
    p = fmaf(p, f, 5.5504108664821580e-2f);
    p = fmaf(p, f, 2.4022650695910071e-1f);
    p = fmaf(p, f, 6.9314718055994531e-1f);
    p = fmaf(p, f, 1.0f);
    int e = (int)n;
    return p * __int_as_float((e + 127) << 23);
}

__device__ __forceinline__ void cp_async16(u32 dst, const void* src) {
    asm volatile("cp.async.cg.shared.global [%0], [%1], 16;" :: "r"(dst), "l"(src));
}
__device__ __forceinline__ void cp_commit() { asm volatile("cp.async.commit_group;"); }
__device__ __forceinline__ void cp_wait1()  { asm volatile("cp.async.wait_group 1;"); }
__device__ __forceinline__ void cp_wait0()  { asm volatile("cp.async.wait_group 0;"); }

__device__ __forceinline__ void bar_pair(int id) {
    asm volatile("bar.sync %0, 64;" :: "r"(id) : "memory");
}

__device__ __forceinline__ void mma_tf32(float* d, const u32* a, const u32* b) {
    asm volatile(
        "mma.sync.aligned.m16n8k8.row.col.f32.tf32.tf32.f32 "
        "{%0,%1,%2,%3}, {%4,%5,%6,%7}, {%8,%9}, {%0,%1,%2,%3};"
        : "+f"(d[0]), "+f"(d[1]), "+f"(d[2]), "+f"(d[3])
        : "r"(a[0]), "r"(a[1]), "r"(a[2]), "r"(a[3]), "r"(b[0]), "r"(b[1]));
}

__device__ __forceinline__ void ldsm4(u32& r0, u32& r1, u32& r2, u32& r3, u32 addr) {
    asm volatile("ldmatrix.sync.aligned.m8n8.x4.shared.b16 {%0,%1,%2,%3}, [%4];"
                 : "=r"(r0), "=r"(r1), "=r"(r2), "=r"(r3) : "r"(addr));
}

// ---------------- merged prepass: z=0 rounds X; z=1..4 transpose+round weights ----------------
__global__ void prepass_kernel(const float* __restrict__ x, float* __restrict__ xo,
                               const float* __restrict__ s0, float* __restrict__ d0,
                               const float* __restrict__ s1, float* __restrict__ d1,
                               const float* __restrict__ s2, float* __restrict__ d2,
                               const float* __restrict__ s3, float* __restrict__ d3) {
    if (blockIdx.z == 0) {
        int xcol = blockIdx.x * 32 + threadIdx.x;
        int yrow = blockIdx.y * 32 + threadIdx.y;
#pragma unroll
        for (int i = 0; i < 4; i++) {
            size_t idx = (size_t)(yrow + i * 8) * HID + xcol;
            xo[idx] = to_tf32(x[idx]);
        }
        return;
    }
    const float* in;
    float* out;
    switch (blockIdx.z) {
        case 1: in = s0; out = d0; break;
        case 2: in = s1; out = d1; break;
        case 3: in = s2; out = d2; break;
        default: in = s3; out = d3; break;
    }
    __shared__ float ts[32][33];
    int x0 = blockIdx.x * 32 + threadIdx.x;
    int y0 = blockIdx.y * 32 + threadIdx.y;
#pragma unroll
    for (int i = 0; i < 4; i++)
        ts[threadIdx.y + i * 8][threadIdx.x] = in[(size_t)(y0 + i * 8) * HID + x0];
    __syncthreads();
    int x2 = blockIdx.y * 32 + threadIdx.x;
    int y2 = blockIdx.x * 32 + threadIdx.y;
#pragma unroll
    for (int i = 0; i < 4; i++)
        out[(size_t)(y2 + i * 8) * HID + x2] = to_tf32(ts[threadIdx.x][threadIdx.y + i * 8]);
}

// ---------------- TF32 GEMM with ldmatrix + swizzled smem ----------------
// TRANS_Z2: blockIdx.z==2 writes C transposed (tf32-rounded) into a [N][M] buffer.
#define TBM 128
#define TBN 128
#define TBK 32
#define TSZ 4096
#define GEMM_SMEM_BYTES (3 * 2 * TSZ * 4)
#define NKIT (HID / TBK)

template <bool TRANS_Z2>
__global__ __launch_bounds__(256, 2) void tf32_gemm_ldsm(
    const float* __restrict__ A,
    const float* __restrict__ B0, const float* __restrict__ B1, const float* __restrict__ B2,
    float* __restrict__ C0, float* __restrict__ C1, float* __restrict__ C2) {
    const float* B = (blockIdx.z == 0) ? B0 : ((blockIdx.z == 1) ? B1 : B2);
    float* C       = (blockIdx.z == 0) ? C0 : ((blockIdx.z == 1) ? C1 : C2);
    const bool trans_out = TRANS_Z2 && (blockIdx.z == 2);

    const int K = HID, N = HID;
    extern __shared__ float gsm[];
    float* As = gsm;
    float* Bs = gsm + 3 * TSZ;

    const int tid  = threadIdx.x;
    const int lane = tid & 31;
    const int warp = tid >> 5;
    const int warpM = warp >> 1;
    const int warpN = warp & 1;
    const int g  = lane >> 2;
    const int tg = lane & 3;

    const int row0 = blockIdx.y * TBM;
    const int col0 = blockIdx.x * TBN;

    const int r_ld = tid >> 3, c_ld = tid & 7;
    const float* gA = A + (size_t)(row0 + r_ld) * K + c_ld * 4;
    const float* gB = B + (size_t)(col0 + r_ld) * K + c_ld * 4;
    const u32 smA = (u32)__cvta_generic_to_shared(As);
    const u32 smB = (u32)__cvta_generic_to_shared(Bs);
    const u32 dOff = (u32)((r_ld * 8 + (c_ld ^ (r_ld & 7))) << 4);

    const int l8 = lane & 7;
    const int a_m  = warpM * 32 + l8 + (((lane >> 3) & 1) << 3);
    const int a_cs = (lane >> 4) & 1;
    const int b_n  = warpN * 64 + l8 + (((lane >> 4) & 1) << 3);
    const int b_cs = (lane >> 3) & 1;

    float acc[2][8][4];
#pragma unroll
    for (int mt = 0; mt < 2; mt++)
#pragma unroll
        for (int nt = 0; nt < 8; nt++)
#pragma unroll
            for (int r = 0; r < 4; r++) acc[mt][nt][r] = 0.f;

#pragma unroll
    for (int p = 0; p < 2; p++) {
        int kk = p * TBK;
        u32 ad = smA + (u32)(p * TSZ * 4) + dOff;
        u32 bd = smB + (u32)(p * TSZ * 4) + dOff;
#pragma unroll
        for (int q = 0; q < 4; q++) {
            cp_async16(ad + (u32)(q * 4096), gA + kk + (size_t)(q * 32) * K);
            cp_async16(bd + (u32)(q * 4096), gB + kk + (size_t)(q * 32) * K);
        }
        cp_commit();
    }

    int st = 0, ld = 2;
    for (int kb = 0; kb < NKIT; kb++) {
        if (kb == NKIT - 1) cp_wait0(); else cp_wait1();
        __syncthreads();

        if (kb + 2 < NKIT) {
            int kk = (kb + 2) * TBK;
            u32 ad = smA + (u32)(ld * TSZ * 4) + dOff;
            u32 bd = smB + (u32)(ld * TSZ * 4) + dOff;
#pragma unroll
            for (int q = 0; q < 4; q++) {
                cp_async16(ad + (u32)(q * 4096), gA + kk + (size_t)(q * 32) * K);
                cp_async16(bd + (u32)(q * 4096), gB + kk + (size_t)(q * 32) * K);
            }
            cp_commit();
        }

        const u32 aStage = smA + (u32)(st * TSZ * 4);
        const u32 bStage = smB + (u32)(st * TSZ * 4);

        u32 af[2][2][4];
        u32 bf[2][8][2];

#pragma unroll
        for (int mt = 0; mt < 2; mt++)
            ldsm4(af[0][mt][0], af[0][mt][1], af[0][mt][2], af[0][mt][3],
                  aStage + (u32)((a_m + mt * 16) * 128 + ((a_cs ^ l8) << 4)));
#pragma unroll
        for (int p = 0; p < 4; p++)
            ldsm4(bf[0][2 * p][0], bf[0][2 * p][1], bf[0][2 * p + 1][0], bf[0][2 * p + 1][1],
                  bStage + (u32)((b_n + p * 16) * 128 + ((b_cs ^ l8) << 4)));

#pragma unroll
        for (int kg = 0; kg < 4; kg++) {
            const int cur = kg & 1, nxt = cur ^ 1;
            if (kg < 3) {
                const int c = 2 * (kg + 1);
#pragma unroll
                for (int mt = 0; mt < 2; mt++)
                    ldsm4(af[nxt][mt][0], af[nxt][mt][1], af[nxt][mt][2], af[nxt][mt][3],
                          aStage + (u32)((a_m + mt * 16) * 128 + (((c + a_cs) ^ l8) << 4)));
#pragma unroll
                for (int p = 0; p < 4; p++)
                    ldsm4(bf[nxt][2 * p][0], bf[nxt][2 * p][1], bf[nxt][2 * p + 1][0], bf[nxt][2 * p + 1][1],
                          bStage + (u32)((b_n + p * 16) * 128 + (((c + b_cs) ^ l8) << 4)));
            }
#pragma unroll
            for (int mt = 0; mt < 2; mt++)
#pragma unroll
                for (int nt = 0; nt < 8; nt++)
                    mma_tf32(acc[mt][nt], af[cur][mt], bf[cur][nt]);
        }

        st = (st == 2) ? 0 : st + 1;
        ld = (ld == 2) ? 0 : ld + 1;
    }

    if (trans_out) {
        // transposed + tf32-rounded store: C[n][m]
#pragma unroll
        for (int mt = 0; mt < 2; mt++) {
            int r = row0 + warpM * 32 + mt * 16 + g;
#pragma unroll
            for (int nt = 0; nt < 8; nt++) {
                int c = col0 + warpN * 64 + nt * 8 + 2 * tg;
                C[(size_t)c * N + r]           = to_tf32(acc[mt][nt][0]);
                C[(size_t)(c + 1) * N + r]     = to_tf32(acc[mt][nt][1]);
                C[(size_t)c * N + r + 8]       = to_tf32(acc[mt][nt][2]);
                C[(size_t)(c + 1) * N + r + 8] = to_tf32(acc[mt][nt][3]);
            }
        }
    } else {
#pragma unroll
        for (int mt = 0; mt < 2; mt++) {
            int r = row0 + warpM * 32 + mt * 16 + g;
#pragma unroll
            for (int nt = 0; nt < 8; nt++) {
                int c = col0 + warpN * 64 + nt * 8 + 2 * tg;
                *(float2*)&C[(size_t)r * N + c]       = make_float2(acc[mt][nt][0], acc[mt][nt][1]);
                *(float2*)&C[(size_t)(r + 8) * N + c] = make_float2(acc[mt][nt][2], acc[mt][nt][3]);
            }
        }
    }
}

// ---------------- RoPE (in-place; K output tf32-rounded) ----------------
__global__ void rope_kernel(float* __restrict__ Q, float* __restrict__ K) {
    int idx = blockIdx.x * blockDim.x + threadIdx.x;
    int j = idx & 63;
    int h = (idx >> 6) & (NH - 1);
    int t = idx >> 10;

    float expo   = (float)(2 * j) * (1.0f / 128.0f);
    float invfrq = expf(-expo * 9.210340371976184f);
    float ang    = (float)t * invfrq;
    float sv, cv;
    sincosf(ang, &sv, &cv);

    int base = t * HID + h * HD + j;
    float q1 = Q[base], q2 = Q[base + 64];
    Q[base]      = q1 * cv - q2 * sv;
    Q[base + 64] = q2 * cv + q1 * sv;
    float k1 = K[base], k2 = K[base + 64];
    K[base]      = to_tf32(k1 * cv - k2 * sv);
    K[base + 64] = to_tf32(k2 * cv + k1 * sv);
}

// ---------------- Flash attention: all-ldmatrix operands, Vt tiles ----------------
// Q/K tiles: 64 rows x 128 floats (512 B/row), swizzle chunk' = chunk ^ (row&7).
// Vt tiles: 128 d-rows x 64 floats (256 B/row), swizzle chunk' = chunk ^ (row&7), chunk 0..15.
#define QKROWB 512
#define QK_TILE_FLOATS (64 * 128)    // 8192
#define VT_TILE_FLOATS (128 * 64)    // 8192
#define SLD 68

#define FM_SMEM_FLOATS (QK_TILE_FLOATS + 2*QK_TILE_FLOATS + 2*VT_TILE_FLOATS + 64*SLD + 256 + 128)
#define FM_SMEM_BYTES  (FM_SMEM_FLOATS * 4)

__global__ __launch_bounds__(256, 1) void flash_mma_kernel(const float* __restrict__ Q,
                                                           const float* __restrict__ K,
                                                           const float* __restrict__ Vt) {
    extern __shared__ float sm[];
    float* Qs   = sm;                          // 64 x 128 swizzled
    float* Ks   = Qs + QK_TILE_FLOATS;         // 2 stages
    float* Vts  = Ks + 2 * QK_TILE_FLOATS;     // 2 stages, 128 x 64 swizzled
    float* Ss   = Vts + 2 * VT_TILE_FLOATS;    // 64 x SLD (holds P)
    float* rmax = Ss + 64 * SLD;               // [2 bufs][2 halves][64]
    float* rsum = rmax + 256;                  // [2 halves][64] (epilogue only)

    const int qb = gridDim.x - 1 - blockIdx.x;
    const int h  = blockIdx.y;
    const int tid  = threadIdx.x;
    const int lane = tid & 31, warp = tid >> 5;
    const int g = lane >> 2, tg = lane & 3;
    const int wm = warp >> 1, wn = warp & 1;
    const int m0 = wm * 16;
    const int qrow0 = qb * 64;
    const float scale = 0.08838834764831845f * 1.4426950408889634f;
    const int barid = 1 + wm;
    const int r0 = m0 + g, r1 = m0 + g + 8;

    const int l8 = lane & 7;
    const int a_m  = m0 + l8 + (((lane >> 3) & 1) << 3);
    const int a_cs = (lane >> 4) & 1;
    const int b_n  = wn * 32 + l8 + (((lane >> 4) & 1) << 3);   // K frag rows (64-range)
    const int v_n  = wn * 64 + l8 + (((lane >> 4) & 1) << 3);   // Vt frag rows (128-range)
    const int b_cs = (lane >> 3) & 1;

    const u32 qsmB = (u32)__cvta_generic_to_shared(Qs);
    const u32 ksmB = (u32)__cvta_generic_to_shared(Ks);
    const u32 vsmB = (u32)__cvta_generic_to_shared(Vts);
    const u32 ssmB = (u32)__cvta_generic_to_shared(Ss);

    // Q tile: scale + tf32-round, store swizzled
    for (int i = tid; i < 64 * 32; i += 256) {
        int r = i >> 5, cc = i & 31;
        float4 v = *(const float4*)&Q[(size_t)(qrow0 + r) * HID + h * HD + cc * 4];
        v.x = to_tf32(v.x * scale); v.y = to_tf32(v.y * scale);
        v.z = to_tf32(v.z * scale); v.w = to_tf32(v.w * scale);
        *(float4*)((char*)Qs + r * QKROWB + ((cc ^ (r & 7)) << 4)) = v;
    }

    // prefetch kb=0 into stage 0: K (64x128 swizzled), Vt (128x64 swizzled 256B rows)
#pragma unroll
    for (int t = 0; t < 8; t++) {
        int i = tid + t * 256;
        {
            int r = i >> 5, cc = i & 31;
            cp_async16(ksmB + (u32)(r * QKROWB + ((cc ^ (r & 7)) << 4)),
                       &K[(size_t)r * HID + h * HD + cc * 4]);
        }
        {
            int r = i >> 4, cc = i & 15;
            cp_async16(vsmB + (u32)(r * 256 + ((cc ^ (r & 7)) << 4)),
                       &Vt[(size_t)(h * HD + r) * S_LEN + cc * 4]);
        }
    }
    cp_commit();

    float oac[8][4];
#pragma unroll
    for (int nt = 0; nt < 8; nt++)
#pragma unroll
        for (int r = 0; r < 4; r++) oac[nt][r] = 0.f;
    float m_i0 = -1e30f, m_i1 = -1e30f, l_i0 = 0.f, l_i1 = 0.f;

    for (int kb = 0; kb <= qb; kb++) {
        int st = kb & 1;
        cp_wait0();
        __syncthreads();

        if (kb < qb) {
            int krow0 = (kb + 1) * 64;
            u32 ko = ksmB + (u32)((st ^ 1) * QK_TILE_FLOATS * 4);
            u32 vo = vsmB + (u32)((st ^ 1) * VT_TILE_FLOATS * 4);
#pragma unroll
            for (int t = 0; t < 8; t++) {
                int i = tid + t * 256;
                {
                    int r = i >> 5, cc = i & 31;
                    cp_async16(ko + (u32)(r * QKROWB + ((cc ^ (r & 7)) << 4)),
                               &K[(size_t)(krow0 + r) * HID + h * HD + cc * 4]);
                }
                {
                    int r = i >> 4, cc = i & 15;
                    cp_async16(vo + (u32)(r * 256 + ((cc ^ (r & 7)) << 4)),
                               &Vt[(size_t)(h * HD + r) * S_LEN + krow0 + cc * 4]);
                }
            }
            cp_commit();
        }

        const u32 kStage = ksmB + (u32)(st * QK_TILE_FLOATS * 4);
        const u32 vStage = vsmB + (u32)(st * VT_TILE_FLOATS * 4);

        // ---- S = Q @ K^T (regs) ----
        float sac[4][4];
#pragma unroll
        for (int nt = 0; nt < 4; nt++)
#pragma unroll
            for (int r = 0; r < 4; r++) sac[nt][r] = 0.f;

        {
            u32 qa[2][4], kf[2][4][2];
            ldsm4(qa[0][0], qa[0][1], qa[0][2], qa[0][3],
                  qsmB + (u32)(a_m * QKROWB + ((a_cs ^ l8) << 4)));
#pragma unroll
            for (int p = 0; p < 2; p++)
                ldsm4(kf[0][2 * p][0], kf[0][2 * p][1], kf[0][2 * p + 1][0], kf[0][2 * p + 1][1],
                      kStage + (u32)((b_n + p * 16) * QKROWB + ((b_cs ^ l8) << 4)));
#pragma unroll
            for (int kk = 0; kk < 16; kk++) {
                const int cur = kk & 1, nxt = cur ^ 1;
                if (kk < 15) {
                    const int c = 2 * (kk + 1);
                    ldsm4(qa[nxt][0], qa[nxt][1], qa[nxt][2], qa[nxt][3],
                          qsmB + (u32)(a_m * QKROWB + (((c + a_cs) ^ l8) << 4)));
#pragma unroll
                    for (int p = 0; p < 2; p++)
                        ldsm4(kf[nxt][2 * p][0], kf[nxt][2 * p][1], kf[nxt][2 * p + 1][0], kf[nxt][2 * p + 1][1],
                              kStage + (u32)((b_n + p * 16) * QKROWB + (((c + b_cs) ^ l8) << 4)));
                }
#pragma unroll
                for (int nt = 0; nt < 4; nt++)
                    mma_tf32(sac[nt], qa[cur], kf[cur][nt]);
            }
        }

        // ---- causal mask (regs) ----
        if (kb == qb) {
#pragma unroll
            for (int nt = 0; nt < 4; nt++) {
                int col = wn * 32 + nt * 8 + 2 * tg;
                if (col     > r0) sac[nt][0] = -1e30f;
                if (col + 1 > r0) sac[nt][1] = -1e30f;
                if (col     > r1) sac[nt][2] = -1e30f;
                if (col + 1 > r1) sac[nt][3] = -1e30f;
            }
        }

        // ---- softmax: row max (pair exchange, double-buffered), sum kept as local halves ----
        float mx0 = -1e30f, mx1 = -1e30f;
#pragma unroll
        for (int nt = 0; nt < 4; nt++) {
            mx0 = fmaxf(mx0, fmaxf(sac[nt][0], sac[nt][1]));
            mx1 = fmaxf(mx1, fmaxf(sac[nt][2], sac[nt][3]));
        }
        mx0 = fmaxf(mx0, __shfl_xor_sync(0xffffffffu, mx0, 1));
        mx0 = fmaxf(mx0, __shfl_xor_sync(0xffffffffu, mx0, 2));
        mx1 = fmaxf(mx1, __shfl_xor_sync(0xffffffffu, mx1, 1));
        mx1 = fmaxf(mx1, __shfl_xor_sync(0xffffffffu, mx1, 2));
        float* rb = rmax + (kb & 1) * 128;
        if (tg == 0) {
            rb[wn * 64 + r0] = mx0;
            rb[wn * 64 + r1] = mx1;
        }
        bar_pair(barid);
        float mnew0 = fmaxf(m_i0, fmaxf(rb[r0], rb[64 + r0]));
        float mnew1 = fmaxf(m_i1, fmaxf(rb[r1], rb[64 + r1]));
        float alpha0 = fexp2(m_i0 - mnew0), alpha1 = fexp2(m_i1 - mnew1);

        float s0 = 0.f, s1 = 0.f;
#pragma unroll
        for (int nt = 0; nt < 4; nt++) {
            int col = wn * 32 + nt * 8 + 2 * tg;
            float p00 = fexp2(sac[nt][0] - mnew0);
            float p01 = fexp2(sac[nt][1] - mnew0);
            float p10 = fexp2(sac[nt][2] - mnew1);
            float p11 = fexp2(sac[nt][3] - mnew1);
            s0 += p00 + p01;
            s1 += p10 + p11;
            Ss[r0 * SLD + col]     = to_tf32(p00);
            Ss[r0 * SLD + col + 1] = to_tf32(p01);
            Ss[r1 * SLD + col]     = to_tf32(p10);
            Ss[r1 * SLD + col + 1] = to_tf32(p11);
        }
        s0 += __shfl_xor_sync(0xffffffffu, s0, 1);
        s0 += __shfl_xor_sync(0xffffffffu, s0, 2);
        s1 += __shfl_xor_sync(0xffffffffu, s1, 1);
        s1 += __shfl_xor_sync(0xffffffffu, s1, 2);
        l_i0 = l_i0 * alpha0 + s0;    // this wn-half's partial row sum
        l_i1 = l_i1 * alpha1 + s1;
        m_i0 = mnew0; m_i1 = mnew1;
        bar_pair(barid);   // P (Ss) visible to pair before ldmatrix reads

        // ---- O = O*alpha + P @ Vt^T : all ldmatrix ----
#pragma unroll
        for (int nt = 0; nt < 8; nt++) {
            oac[nt][0] *= alpha0; oac[nt][1] *= alpha0;
            oac[nt][2] *= alpha1; oac[nt][3] *= alpha1;
        }
        {
            u32 pa[2][4], vf[2][8][2];
            ldsm4(pa[0][0], pa[0][1], pa[0][2], pa[0][3],
                  ssmB + (u32)((a_m * SLD + a_cs * 4) << 2));
#pragma unroll
            for (int p = 0; p < 4; p++)
                ldsm4(vf[0][2 * p][0], vf[0][2 * p][1], vf[0][2 * p + 1][0], vf[0][2 * p + 1][1],
                      vStage + (u32)((v_n + p * 16) * 256 + ((b_cs ^ l8) << 4)));
#pragma unroll
            for (int kk = 0; kk < 8; kk++) {
                const int cur = kk & 1, nxt = cur ^ 1;
                if (kk < 7) {
                    const int k0 = (kk + 1) * 8;
                    const int c = 2 * (kk + 1);
                    ldsm4(pa[nxt][0], pa[nxt][1], pa[nxt][2], pa[nxt][3],
                          ssmB + (u32)((a_m * SLD + k0 + a_cs * 4) << 2));
#pragma unroll
                    for (int p = 0; p < 4; p++)
                        ldsm4(vf[nxt][2 * p][0], vf[nxt][2 * p][1], vf[nxt][2 * p + 1][0], vf[nxt][2 * p + 1][1],
                              vStage + (u32)((v_n + p * 16) * 256 + (((c + b_cs) ^ l8) << 4)));
                }
#pragma unroll
                for (int nt = 0; nt < 8; nt++)
                    mma_tf32(oac[nt], pa[cur], vf[cur][nt]);
            }
        }
    }

    // combine l halves once
    if (tg == 0) {
        rsum[wn * 64 + r0] = l_i0;
        rsum[wn * 64 + r1] = l_i1;
    }
    bar_pair(barid);
    float inv0 = 1.0f / (rsum[r0] + rsum[64 + r0]);
    float inv1 = 1.0f / (rsum[r1] + rsum[64 + r1]);
#pragma unroll
    for (int nt = 0; nt < 8; nt++) {
        int col = wn * 64 + nt * 8 + 2 * tg;
        int gr0 = qrow0 + r0, gr1 = qrow0 + r1;
        float2 w0 = make_float2(to_tf32(oac[nt][0] * inv0), to_tf32(oac[nt][1] * inv0));
        float2 w1 = make_float2(to_tf32(oac[nt][2] * inv1), to_tf32(oac[nt][3] * inv1));
        *(float2*)&g_AO[(size_t)gr0 * HID + h * HD + col] = w0;
        *(float2*)&g_AO[(size_t)gr1 * HID + h * HD + col] = w1;
    }
}

// ---------------- launch ----------------
extern "C" void kernel_launch(void* const* d_in, const int* in_sizes, int n_in,
                              void* d_out, int out_size) {
    const float* X  = (const float*)d_in[0];
    const float* wq = (const float*)d_in[1];
    const float* wk = (const float*)d_in[2];
    const float* wv = (const float*)d_in[3];
    const float* wo = (const float*)d_in[4];
    float* out = (float*)d_out;

    float *Q, *K, *Vt, *AO, *Xt, *Wq, *Wk, *Wv, *Wo;
    cudaGetSymbolAddress((void**)&Q,  g_Q);
    cudaGetSymbolAddress((void**)&K,  g_K);
    cudaGetSymbolAddress((void**)&Vt, g_Vt);
    cudaGetSymbolAddress((void**)&AO, g_AO);
    cudaGetSymbolAddress((void**)&Xt, g_Xt);
    cudaGetSymbolAddress((void**)&Wq, g_Wq);
    cudaGetSymbolAddress((void**)&Wk, g_Wk);
    cudaGetSymbolAddress((void**)&Wv, g_Wv);
    cudaGetSymbolAddress((void**)&Wo, g_Wo);

    cudaFuncSetAttribute(tf32_gemm_ldsm<true>, cudaFuncAttributeMaxDynamicSharedMemorySize,
                         GEMM_SMEM_BYTES);
    cudaFuncSetAttribute(tf32_gemm_ldsm<false>, cudaFuncAttributeMaxDynamicSharedMemorySize,
                         GEMM_SMEM_BYTES);
    cudaFuncSetAttribute(flash_mma_kernel, cudaFuncAttributeMaxDynamicSharedMemorySize,
                         FM_SMEM_BYTES);

    prepass_kernel<<<dim3(64, 64, 5), dim3(32, 8)>>>(
        X, Xt, wq, Wq, wk, Wk, wv, Wv, wo, Wo);

    // fused Q/K/V projections; z=2 (V) writes transposed + rounded into Vt
    tf32_gemm_ldsm<true><<<dim3(16, 16, 3), 256, GEMM_SMEM_BYTES>>>(
        Xt, Wq, Wk, Wv, Q, K, Vt);

    rope_kernel<<<(S_LEN * NH * 64) / 256, 256>>>(Q, K);

    flash_mma_kernel<<<dim3(S_LEN / 64, NH), 256, FM_SMEM_BYTES>>>(Q, K, Vt);

    tf32_gemm_ldsm<false><<<dim3(16, 16, 1), 256, GEMM_SMEM_BYTES>>>(
        AO, Wo, Wo, Wo, out, out, out);

    (void)in_sizes; (void)n_in; (void)out_size;
}